// round 9
// baseline (speedup 1.0000x reference)
#include <cuda_runtime.h>
#include <cstdint>

#define NB   16
#define NN   1024
#define NF   256
#define NH   8
#define NK   512
#define NDOUT 256
#define EPSF 1e-8f
#define OUT_ELEMS (NB*NK*NDOUT)
#define SP   513   // padded row stride (conflict-free sequential row walks)
#define NROWS 16   // n rows per scores block
#define NCHUNK 32  // 8-float key chunks per head

typedef unsigned long long u64;

// packed fp32x2 FMA: acc = a*b + acc (elementwise on 2 packed floats)
#define FMA2(acc, a, b) \
    asm("fma.rn.f32x2 %0, %1, %2, %0;" : "+l"(acc) : "l"(a), "l"(b))

__device__ __forceinline__ float u64_pair_sum(u64 v) {
    unsigned lo, hi;
    asm("mov.b64 {%0, %1}, %2;" : "=r"(lo), "=r"(hi) : "l"(v));
    return __fadd_rn(__uint_as_float(lo), __uint_as_float(hi));
}

// ---- scratch (static device allocations; no cudaMalloc allowed) ----
__device__ float  g_C[(size_t)NB*NN*NK];    // 32 MB
__device__ float  g_V[(size_t)NB*NK*NF];    // 8 MB
__device__ float  g_cnf[NB*NK];
__device__ float  g_k2[NH*NK];
__device__ double g_kl;

// ------------------------------------------------------------------
// exp(x) for x in [-0.125, 0], float-float, ~1e-11 accurate.
__device__ __forceinline__ float exp_small(float x) {
    if (x < -0.125f) return (float)exp((double)x);   // rare fallback
    float x2h = __fmul_rn(x, x);
    float x2l = fmaf(x, x, -x2h);
    float U = fmaf(x, fmaf(x, fmaf(x, fmaf(x, 1.f/5040.f, 1.f/720.f),
                                   1.f/120.f), 1.f/24.f), 1.f/6.f);
    float tail = fmaf(__fmul_rn(x2h, x), U, 0.5f*x2l);
    float sh = __fadd_rn(1.f, x);
    float sl = __fadd_rn(__fsub_rn(1.f, sh), x);
    float b  = 0.5f*x2h;
    float th = __fadd_rn(sh, b);
    float tl = __fadd_rn(__fsub_rn(sh, th), b);
    return __fadd_rn(th, __fadd_rn(__fadd_rn(tl, sl), tail));
}

// log(y) for y ~ 1/512*(1 +- 0.06), float-float, ~1e-11 accurate.
__device__ __forceinline__ float log_near(float y) {
    const double LN512 = 6.2383246250395078;
    const float LH = (float)LN512;
    const float LL = (float)(LN512 - (double)LH);
    float u = __fmul_rn(y, 512.f);
    float w = __fsub_rn(u, 1.f);
    if (fabsf(w) > 0.0625f) return (float)log((double)y);  // rare fallback
    float w2h = __fmul_rn(w, w);
    float w2l = fmaf(w, w, -w2h);
    float V = fmaf(w, fmaf(w, fmaf(w, fmaf(w, fmaf(w, -1.f/8.f, 1.f/7.f),
                                   -1.f/6.f), 1.f/5.f), -1.f/4.f), 1.f/3.f);
    float tail = fmaf(__fmul_rn(w2h, w), V, -0.5f*w2l);
    float b  = -0.5f*w2h;
    float sh = __fadd_rn(w, b);
    float sl = __fadd_rn(__fsub_rn(w, sh), b);
    float th = __fadd_rn(sh, -LH);
    float tl = __fadd_rn(__fsub_rn(-LH, th), sh);
    return __fadd_rn(th, __fsub_rn(__fadd_rn(__fadd_rn(tl, sl), tail), LL));
}

// ------------------------------------------------------------------
__global__ void init_kernel() {
    if (blockIdx.x == 0 && threadIdx.x == 0) g_kl = 0.0;
}

// one dummy: shifts scores_kernel to global ncu slot 5 (-s 5 -c 1)
__global__ void dummy_kernel() {}

// ||keys[h][k]||^2 : warp per row
__global__ void k2_kernel(const float* __restrict__ keys) {
    int warp = threadIdx.x >> 5, lane = threadIdx.x & 31;
    int row = blockIdx.x * 8 + warp;           // < NH*NK = 4096
    const float4* kr = (const float4*)(keys + (size_t)row * NF);
    float s = 0.f;
    #pragma unroll
    for (int j = lane; j < 64; j += 32) {
        float4 v = kr[j];
        s += v.x*v.x + v.y*v.y + v.z*v.z + v.w*v.w;
    }
    #pragma unroll
    for (int o = 16; o; o >>= 1) s += __shfl_xor_sync(0xffffffffu, s, o);
    if (!lane) g_k2[row] = s;
}

// ------------------------------------------------------------------
// issue one 8-float key chunk (all 512 rows, 16KB) into stage chunk%3.
// 256 threads: thread t copies granule t&1 of rows (t>>1)+128i.
// smem layout: granule g = stage*1024 + seg*512 + row (float4 units).
__device__ __forceinline__ void issue_chunk8(
    const float* __restrict__ khead, float* kbuf, int chunk, int tid)
{
    const int s   = chunk % 3;
    const int seg = tid & 1;
    const int r0  = tid >> 1;
    const float* src = khead + (size_t)r0*NF + chunk*8 + seg*4;
    float* dstb = kbuf + ((size_t)s*1024 + seg*512 + r0) * 4;
    #pragma unroll
    for (int i = 0; i < 4; i++) {
        unsigned dst = (unsigned)__cvta_generic_to_shared(dstb + i*128*4);
        asm volatile("cp.async.ca.shared.global [%0], [%1], 16;"
                     :: "r"(dst), "l"(src + (size_t)i*128*NF));
    }
    asm volatile("cp.async.commit_group;");
}

// ------------------------------------------------------------------
// Fused scores kernel: 256 threads, 16 n rows, 2 blocks/SM.
// 3-stage cp.async (8-float chunks), ONE barrier per chunk, 4k x 8n
// register tiling. Accumulation order per (n,k) bitwise identical to
// all passing rounds (granule-ascending, .x then .y).
__global__ void __launch_bounds__(256, 2) scores_kernel(
    const float* __restrict__ Q, const float* __restrict__ keys,
    const float* __restrict__ conv_w, const int* __restrict__ mask)
{
    extern __shared__ float sm[];
    float* Qs   = sm;                       // 16*256 floats = 16 KB
    float* Sacc = Qs + NROWS*256;           // 16*SP = 32.8 KB
    float* kbuf = Sacc + NROWS*SP;          // 3*1024 float4 = 48 KB
    float* Ctmp = kbuf;                     // aliased (disjoint phases)
    float* rowv = kbuf + 3*1024*4;          // 16
    float* q2s  = rowv + NROWS;             // 16
    float* mxs  = q2s + NROWS;              // 16
    float* msk  = mxs + NROWS;              // 16

    const int tid  = threadIdx.x;
    const int lane = tid & 31, warp = tid >> 5;
    const int b  = blockIdx.y;
    const int n0 = blockIdx.x * NROWS;

    // GEMM tiling: 4 k rows x 8 n per thread
    const int k0 = tid & 127;
    const int nbase = (tid >> 7) * 8;       // 0 or 8

    // load Q tile + mask, zero Sacc
    const float4* Qg = (const float4*)(Q + ((size_t)b*NN + n0)*NF);
    float4* Qs4 = (float4*)Qs;
    #pragma unroll
    for (int i = tid; i < NROWS*64; i += 256) Qs4[i] = Qg[i];
    if (tid < NROWS) msk[tid] = (float)mask[b*NN + n0 + tid];
    #pragma unroll
    for (int n = 0; n < NROWS; n++) {
        Sacc[n*SP + tid] = 0.f;
        Sacc[n*SP + tid + 256] = 0.f;
    }
    __syncthreads();

    // q2 per row (warp per 2 rows; 8 warps x 2 = 16 rows)
    #pragma unroll
    for (int r = 0; r < 2; r++) {
        int n = warp*2 + r;
        float s = 0.f;
        #pragma unroll
        for (int j = 0; j < 8; j++) {
            float v = Qs[n*256 + lane + 32*j];
            s = __fadd_rn(s, __fmul_rn(v, v));
        }
        #pragma unroll
        for (int o = 16; o; o >>= 1)
            s = __fadd_rn(s, __shfl_xor_sync(0xffffffffu, s, o));
        if (!lane) q2s[n] = s;
    }
    __syncthreads();

    const ulonglong2* Qsv = (const ulonglong2*)Qs;   // [n*64 + granule]
    const ulonglong2* kb  = (const ulonglong2*)kbuf;

    for (int h = 0; h < NH; h++) {
        // previous head's Ctmp reads done before kbuf overwrite
        __syncthreads();

        u64 acc[4][8];
        #pragma unroll
        for (int kk = 0; kk < 4; kk++)
            #pragma unroll
            for (int n = 0; n < 8; n++) acc[kk][n] = 0ull;

        const float* khead = keys + (size_t)h*NK*NF;

        issue_chunk8(khead, kbuf, 0, tid);
        issue_chunk8(khead, kbuf, 1, tid);

        #pragma unroll 1
        for (int chunk = 0; chunk < NCHUNK; chunk++) {
            if (chunk + 2 < NCHUNK) {
                asm volatile("cp.async.wait_group 1;");
            } else if (chunk + 1 < NCHUNK) {
                asm volatile("cp.async.wait_group 1;");
            } else {
                asm volatile("cp.async.wait_group 0;");
            }
            __syncthreads();   // chunk's stage visible; prev compute done
            if (chunk + 2 < NCHUNK)
                issue_chunk8(khead, kbuf, chunk + 2, tid);

            const int sbase = (chunk % 3) * 1024;
            const ulonglong2* qbase = &Qsv[nbase*64 + chunk*2];

            // granule-ascending accumulation (bitwise-frozen order)
            #pragma unroll
            for (int g = 0; g < 2; g++) {
                ulonglong2 kv0 = kb[sbase + g*512 + k0];
                ulonglong2 kv1 = kb[sbase + g*512 + k0 + 128];
                ulonglong2 kv2 = kb[sbase + g*512 + k0 + 256];
                ulonglong2 kv3 = kb[sbase + g*512 + k0 + 384];
                #pragma unroll
                for (int n = 0; n < 8; n++) {
                    ulonglong2 q = qbase[n*64 + g];
                    FMA2(acc[0][n], kv0.x, q.x);
                    FMA2(acc[0][n], kv0.y, q.y);
                    FMA2(acc[1][n], kv1.x, q.x);
                    FMA2(acc[1][n], kv1.y, q.y);
                    FMA2(acc[2][n], kv2.x, q.x);
                    FMA2(acc[2][n], kv2.y, q.y);
                    FMA2(acc[3][n], kv3.x, q.x);
                    FMA2(acc[3][n], kv3.y, q.y);
                }
            }
        }
        __syncthreads();   // GEMM reads done before Ctmp (alias) writes

        // d2 = (q2+k2) - 2*qk; c = 1/(1 + sqrt(max(d2,0))^2)
        #pragma unroll
        for (int kk = 0; kk < 4; kk++) {
            int kx = k0 + kk*128;
            float k2v = g_k2[h*NK + kx];
            #pragma unroll
            for (int n = 0; n < 8; n++) {
                int nn = nbase + n;
                float qk = u64_pair_sum(acc[kk][n]);
                float d2 = __fsub_rn(__fadd_rn(q2s[nn], k2v),
                                     __fmul_rn(2.0f, qk));
                float t  = sqrtf(fmaxf(d2, 0.0f));
                Ctmp[nn*SP + kx] =
                    __fdiv_rn(1.0f, __fadd_rn(1.0f, __fmul_rn(t, t)));
            }
        }
        __syncthreads();

        // rowsum over k: strict sequential ascending fp32 (frozen order)
        if (tid < NROWS) {
            const float* row = &Ctmp[tid*SP];
            float s = 0.f;
            #pragma unroll 8
            for (int j = 0; j < NK; j++)
                s = __fadd_rn(s, row[j]);
            rowv[tid] = s;
        }
        __syncthreads();

        // logits += cw * ((c / rowsum) * msk), ascending h
        const float cw = conv_w[h];
        #pragma unroll
        for (int kk = 0; kk < 4; kk++) {
            int kx = k0 + kk*128;
            #pragma unroll
            for (int n = 0; n < 8; n++) {
                int nn = nbase + n;
                float cdiv = __fdiv_rn(Ctmp[nn*SP + kx], rowv[nn]);
                float term = __fmul_rn(cw, __fmul_rn(cdiv, msk[nn]));
                Sacc[nn*SP + kx] = __fadd_rn(Sacc[nn*SP + kx], term);
            }
        }
    }
    __syncthreads();

    // softmax: row max (warp per 2 rows)
    #pragma unroll
    for (int r = 0; r < 2; r++) {
        int n = warp*2 + r;
        float mx = -3.402823466e38f;
        #pragma unroll
        for (int j = 0; j < 16; j++)
            mx = fmaxf(mx, Sacc[n*SP + lane + 32*j]);
        #pragma unroll
        for (int o = 16; o; o >>= 1)
            mx = fmaxf(mx, __shfl_xor_sync(0xffffffffu, mx, o));
        if (!lane) mxs[n] = mx;
    }
    __syncthreads();
    // e = exp(x - mx), correctly-rounded-grade
    #pragma unroll
    for (int n = 0; n < NROWS; n++) {
        float x0 = __fsub_rn(Sacc[n*SP + tid], mxs[n]);
        float x1 = __fsub_rn(Sacc[n*SP + tid + 256], mxs[n]);
        Sacc[n*SP + tid]       = exp_small(x0);
        Sacc[n*SP + tid + 256] = exp_small(x1);
    }
    __syncthreads();
    // denominator: strict sequential ascending fp32 (frozen order)
    if (tid < NROWS) {
        const float* row = &Sacc[tid*SP];
        float s = 0.f;
        #pragma unroll 8
        for (int j = 0; j < NK; j++)
            s = __fadd_rn(s, row[j]);
        rowv[tid] = s;
    }
    __syncthreads();

    // C = (e / s) * msk
    float* Cout = g_C + ((size_t)b*NN + n0)*NK;
    #pragma unroll
    for (int n = 0; n < NROWS; n++) {
        Cout[(size_t)n*NK + tid] =
            __fmul_rn(__fdiv_rn(Sacc[n*SP + tid], rowv[n]), msk[n]);
        Cout[(size_t)n*NK + tid + 256] =
            __fmul_rn(__fdiv_rn(Sacc[n*SP + tid + 256], rowv[n]), msk[n]);
    }
}

// ------------------------------------------------------------------
// cn[b][k] = strict sequential ascending fp32 sum over n of C[b][n][k]
__global__ void __launch_bounds__(256) cn_kernel()
{
    int id = blockIdx.x * blockDim.x + threadIdx.x;   // < NB*NK
    int b = id >> 9, kk = id & 511;
    const float* base = g_C + ((size_t)b*NN)*NK + kk;
    float s = 0.f;
    #pragma unroll 8
    for (int n = 0; n < NN; n++)
        s = __fadd_rn(s, base[(size_t)n*NK]);
    g_cnf[id] = s;
}

// ------------------------------------------------------------------
// KL: warp per (b,n) row. Sequential fp32 pn; float-float logs.
__global__ void __launch_bounds__(256) kl_kernel()
{
    __shared__ float cbuf[8][SP];
    __shared__ float pbuf[8][SP];
    const int warp = threadIdx.x >> 5, lane = threadIdx.x & 31;
    const int row = blockIdx.x * 8 + warp;   // < NB*NN
    const int b = row >> 10;
    const float* crow = g_C + (size_t)row * NK;
    const float* cnb = g_cnf + b*NK;

    #pragma unroll
    for (int j = 0; j < 16; j++) {
        int kk = lane + 32*j;
        float c = crow[kk];
        float cnf = __fadd_rn(cnb[kk], EPSF);
        float p = __fdiv_rn(__fmul_rn(c, c), cnf);
        cbuf[warp][kk] = c;
        pbuf[warp][kk] = p;
    }
    __syncwarp();
    if (!lane) {
        float pn = 0.f;
        const float* prow = pbuf[warp];
        #pragma unroll 8
        for (int j = 0; j < NK; j++)
            pn = __fadd_rn(pn, prow[j]);
        pbuf[warp][512] = __fadd_rn(pn, EPSF);
    }
    __syncwarp();
    const float pnf = pbuf[warp][512];

    double t = 0.0;
    #pragma unroll
    for (int j = 0; j < 16; j++) {
        int kk = lane + 32*j;
        float pv = pbuf[warp][kk];
        if (pv != 0.f) {
            float P  = __fdiv_rn(pv, pnf);
            float la = log_near(__fadd_rn(P, EPSF));
            float lb = log_near(__fadd_rn(cbuf[warp][kk], EPSF));
            t += (double)__fmul_rn(P, __fsub_rn(la, lb));
        }
    }
    #pragma unroll
    for (int o = 16; o; o >>= 1) t += __shfl_xor_sync(0xffffffffu, t, o);
    if (!lane) atomicAdd(&g_kl, t);
}

// ------------------------------------------------------------------
// V[b][k][f] = sum_n C[b][n][k] * Q[b][n][f] ; 64x64 tile, packed f32x2
__global__ void __launch_bounds__(256) v_kernel(const float* __restrict__ Q)
{
    const int b = blockIdx.z;
    const int k0 = blockIdx.x * 64, f0 = blockIdx.y * 64;
    __shared__ __align__(16) float As[32][64];
    __shared__ __align__(16) float Bs[32][64];
    const int tid = threadIdx.x;
    const int tx = tid & 15, ty = tid >> 4;
    const int lr = tid >> 6, lc = tid & 63;

    u64 acc2[4][2];
    #pragma unroll
    for (int i = 0; i < 4; i++) { acc2[i][0] = 0ull; acc2[i][1] = 0ull; }

    for (int n0 = 0; n0 < NN; n0 += 32) {
        #pragma unroll
        for (int r = 0; r < 8; r++) {
            int nn = lr + r*4;
            As[nn][lc] = g_C[((size_t)b*NN + n0 + nn)*NK + k0 + lc];
            Bs[nn][lc] = Q[((size_t)b*NN + n0 + nn)*NF + f0 + lc];
        }
        __syncthreads();
        #pragma unroll
        for (int nn = 0; nn < 32; nn++) {
            const u64* Brow = (const u64*)&Bs[nn][ty*4];
            u64 b0 = Brow[0], b1 = Brow[1];
            #pragma unroll
            for (int i = 0; i < 4; i++) {
                unsigned ab = __float_as_uint(As[nn][tx*4 + i]);
                u64 ap;
                asm("mov.b64 %0, {%1, %1};" : "=l"(ap) : "r"(ab));
                FMA2(acc2[i][0], ap, b0);
                FMA2(acc2[i][1], ap, b1);
            }
        }
        __syncthreads();
    }
    #pragma unroll
    for (int i = 0; i < 4; i++)
        #pragma unroll
        for (int jp = 0; jp < 2; jp++) {
            unsigned lo, hi;
            asm("mov.b64 {%0, %1}, %2;" : "=r"(lo), "=r"(hi) : "l"(acc2[i][jp]));
            size_t base = ((size_t)b*NK + k0 + tx*4 + i)*NF + f0 + ty*4 + jp*2;
            g_V[base]     = __uint_as_float(lo);
            g_V[base + 1] = __uint_as_float(hi);
        }
}

// ------------------------------------------------------------------
// out[m][o] = lrelu( sum_f V[m][f]*W[o][f] + bias[o] )
__global__ void __launch_bounds__(256) out_kernel(
    const float* __restrict__ W, const float* __restrict__ bias,
    float* __restrict__ out)
{
    const int m0 = blockIdx.x * 64, o0 = blockIdx.y * 64;
    __shared__ float As[64][33];
    __shared__ float Ws[64][33];
    const int tid = threadIdx.x;
    const int tx = tid & 15, ty = tid >> 4;
    const int lr = tid >> 5, lc = tid & 31;

    float acc[4][4];
    #pragma unroll
    for (int i = 0; i < 4; i++)
        #pragma unroll
        for (int j = 0; j < 4; j++) acc[i][j] = 0.f;

    for (int fc = 0; fc < NF; fc += 32) {
        #pragma unroll
        for (int r = 0; r < 8; r++) {
            int mm = lr + r*8;
            As[mm][lc] = g_V[(size_t)(m0 + mm)*NF + fc + lc];
            Ws[mm][lc] = W[(size_t)(o0 + mm)*NF + fc + lc];
        }
        __syncthreads();
        #pragma unroll
        for (int ff = 0; ff < 32; ff++) {
            float a[4], w[4];
            #pragma unroll
            for (int i = 0; i < 4; i++) a[i] = As[tx*4 + i][ff];
            #pragma unroll
            for (int j = 0; j < 4; j++) w[j] = Ws[ty*4 + j][ff];
            #pragma unroll
            for (int i = 0; i < 4; i++)
                #pragma unroll
                for (int j = 0; j < 4; j++)
                    acc[i][j] = fmaf(a[i], w[j], acc[i][j]);
        }
        __syncthreads();
    }
    #pragma unroll
    for (int j = 0; j < 4; j++) {
        float bj = bias[o0 + ty*4 + j];
        #pragma unroll
        for (int i = 0; i < 4; i++) {
            float v = acc[i][j] + bj;
            v = (v >= 0.f) ? v : 0.01f * v;
            out[(size_t)(m0 + tx*4 + i)*NDOUT + o0 + ty*4 + j] = v;
        }
    }
}

// write kl scalar(s) after the out tensor
__global__ void finalize_kernel(float* __restrict__ out, int out_size)
{
    int i = OUT_ELEMS + blockIdx.x * blockDim.x + threadIdx.x;
    if (i < out_size) out[i] = __fmul_rn(100.0f, (float)g_kl);
}

// ------------------------------------------------------------------
extern "C" void kernel_launch(void* const* d_in, const int* in_sizes, int n_in,
                              void* d_out, int out_size)
{
    const float* Q      = (const float*)d_in[0];
    const float* keys   = (const float*)d_in[1];
    const float* conv_w = (const float*)d_in[2];
    const float* lin_w  = (const float*)d_in[3];
    const float* lin_b  = (const float*)d_in[4];
    const int*   mask   = (const int*)d_in[5];
    float* out = (float*)d_out;

    // smem: Qs 16384 + Sacc 32832 + kbuf 49152 + 64 floats misc = 98,624 B
    const int smem = (NROWS*256 + NROWS*SP + 3*1024*4 + 4*NROWS)
                     * (int)sizeof(float);
    cudaFuncSetAttribute(scores_kernel, cudaFuncAttributeMaxDynamicSharedMemorySize, smem);

    init_kernel<<<1, 32>>>();                      // my #0
    k2_kernel<<<(NH*NK)/8, 256>>>(keys);           // my #1
    dummy_kernel<<<1, 32>>>();                     // my #2
    scores_kernel<<<dim3(NN/NROWS, NB), 256, smem>>>(Q, keys, conv_w, mask); // my #3 = ncu slot 5
    cn_kernel<<<(NB*NK)/256, 256>>>();
    kl_kernel<<<(NB*NN)/8, 256>>>();
    v_kernel<<<dim3(NK/64, NF/64, NB), 256>>>(Q);
    out_kernel<<<dim3((NB*NK)/64, NDOUT/64), 256>>>(lin_w, lin_b, out);

    int extra = out_size - OUT_ELEMS;
    if (extra > 0)
        finalize_kernel<<<(extra + 255)/256, 256>>>(out, out_size);
}

// round 10
// speedup vs baseline: 1.1317x; 1.1317x over previous
#include <cuda_runtime.h>
#include <cstdint>

#define NB   16
#define NN   1024
#define NF   256
#define NH   8
#define NK   512
#define NDOUT 256
#define EPSF 1e-8f
#define OUT_ELEMS (NB*NK*NDOUT)
#define SP   513   // padded row stride

typedef unsigned long long u64;

// packed fp32x2 FMA: acc = a*b + acc
#define FMA2(acc, a, b) \
    asm("fma.rn.f32x2 %0, %1, %2, %0;" : "+l"(acc) : "l"(a), "l"(b))

__device__ __forceinline__ float u64_pair_sum(u64 v) {
    unsigned lo, hi;
    asm("mov.b64 {%0, %1}, %2;" : "=r"(lo), "=r"(hi) : "l"(v));
    return __fadd_rn(__uint_as_float(lo), __uint_as_float(hi));
}

// ---- scratch ----
__device__ float  g_C[(size_t)NB*NN*NK];    // 32 MB
__device__ float  g_V[(size_t)NB*NK*NF];    // 8 MB
__device__ float  g_cnf[NB*NK];
__device__ float  g_k2[NH*NK];
__device__ double g_kl;

// ------------------------------------------------------------------
// exp(x) for x in [-0.125, 0], float-float, ~1e-11 accurate.
__device__ __forceinline__ float exp_small(float x) {
    if (x < -0.125f) return (float)exp((double)x);   // rare fallback
    float x2h = __fmul_rn(x, x);
    float x2l = fmaf(x, x, -x2h);
    float U = fmaf(x, fmaf(x, fmaf(x, fmaf(x, 1.f/5040.f, 1.f/720.f),
                                   1.f/120.f), 1.f/24.f), 1.f/6.f);
    float tail = fmaf(__fmul_rn(x2h, x), U, 0.5f*x2l);
    float sh = __fadd_rn(1.f, x);
    float sl = __fadd_rn(__fsub_rn(1.f, sh), x);
    float b  = 0.5f*x2h;
    float th = __fadd_rn(sh, b);
    float tl = __fadd_rn(__fsub_rn(sh, th), b);
    return __fadd_rn(th, __fadd_rn(__fadd_rn(tl, sl), tail));
}

// log(y) for y ~ 1/512*(1 +- 0.06), float-float, ~1e-11 accurate.
__device__ __forceinline__ float log_near(float y) {
    const double LN512 = 6.2383246250395078;
    const float LH = (float)LN512;
    const float LL = (float)(LN512 - (double)LH);
    float u = __fmul_rn(y, 512.f);
    float w = __fsub_rn(u, 1.f);
    if (fabsf(w) > 0.0625f) return (float)log((double)y);  // rare fallback
    float w2h = __fmul_rn(w, w);
    float w2l = fmaf(w, w, -w2h);
    float V = fmaf(w, fmaf(w, fmaf(w, fmaf(w, fmaf(w, -1.f/8.f, 1.f/7.f),
                                   -1.f/6.f), 1.f/5.f), -1.f/4.f), 1.f/3.f);
    float tail = fmaf(__fmul_rn(w2h, w), V, -0.5f*w2l);
    float b  = -0.5f*w2h;
    float sh = __fadd_rn(w, b);
    float sl = __fadd_rn(__fsub_rn(w, sh), b);
    float th = __fadd_rn(sh, -LH);
    float tl = __fadd_rn(__fsub_rn(-LH, th), sh);
    return __fadd_rn(th, __fsub_rn(__fadd_rn(__fadd_rn(tl, sl), tail), LL));
}

// ------------------------------------------------------------------
__global__ void init_kernel() {
    if (blockIdx.x == 0 && threadIdx.x == 0) g_kl = 0.0;
}

// one dummy: shifts scores_kernel to global ncu slot 5 (-s 5 -c 1)
__global__ void dummy_kernel() {}

// ||keys[h][k]||^2 : warp per row
__global__ void k2_kernel(const float* __restrict__ keys) {
    int warp = threadIdx.x >> 5, lane = threadIdx.x & 31;
    int row = blockIdx.x * 8 + warp;           // < NH*NK = 4096
    const float4* kr = (const float4*)(keys + (size_t)row * NF);
    float s = 0.f;
    #pragma unroll
    for (int j = lane; j < 64; j += 32) {
        float4 v = kr[j];
        s += v.x*v.x + v.y*v.y + v.z*v.z + v.w*v.w;
    }
    #pragma unroll
    for (int o = 16; o; o >>= 1) s += __shfl_xor_sync(0xffffffffu, s, o);
    if (!lane) g_k2[row] = s;
}

// ------------------------------------------------------------------
// issue one key chunk (16 floats/row for all 512 rows) into stage chunk%3.
// Thread t copies seg (t&3) of rows (t>>2)+128i.
// smem layout: granule g = stage*2048 + seg*512 + row (float4 units).
__device__ __forceinline__ void issue_chunk(
    const float* __restrict__ khead, float* kbuf, int chunk, int tid)
{
    const int s   = chunk % 3;
    const int seg = tid & 3;
    const int r0  = tid >> 2;
    const float* src = khead + (size_t)r0*NF + chunk*16 + seg*4;
    float* dstb = kbuf + ((size_t)s*2048 + seg*512 + r0) * 4;
    #pragma unroll
    for (int i = 0; i < 4; i++) {
        unsigned dst = (unsigned)__cvta_generic_to_shared(dstb + i*128*4);
        asm volatile("cp.async.ca.shared.global [%0], [%1], 16;"
                     :: "r"(dst), "l"(src + (size_t)i*128*NF));
    }
    asm volatile("cp.async.commit_group;");
}

// ------------------------------------------------------------------
// Fused scores kernel (R8 shape): 512 threads, 32 rows, 3-stage cp.async,
// 2k x 16n register tiling, ONE barrier per chunk, PARALLEL per-head
// rowsum (order-insensitive: enters logits as per-row scale, annihilated
// by softmax to O(1e-11)). Softmax denominator / exp stay frozen.
__global__ void __launch_bounds__(512, 1) scores_kernel(
    const float* __restrict__ Q, const float* __restrict__ keys,
    const float* __restrict__ conv_w, const int* __restrict__ mask)
{
    extern __shared__ float sm[];
    float* Qs   = sm;                       // 32*256 floats
    float* Sacc = Qs + 32*256;              // 32*SP
    float* kbuf = Sacc + 32*SP;             // 3*2048 float4 = 24576 floats
    float* Ctmp = kbuf;                     // aliased (disjoint phases)
    float* rowv = kbuf + 3*2048*4;          // 32
    float* q2s  = rowv + 32;                // 32
    float* mxs  = q2s + 32;                 // 32
    float* msk  = mxs + 32;                 // 32

    const int tid  = threadIdx.x;
    const int lane = tid & 31, warp = tid >> 5;
    const int b  = blockIdx.y;
    const int n0 = blockIdx.x * 32;
    const int k  = tid;             // 0..511 (softmax/C phases)

    // GEMM tiling: 2 k rows x 16 n per thread
    const int k0 = tid & 255;
    const int k1 = k0 + 256;
    const int nbase = (tid >> 8) * 16;      // 0 or 16

    // load Q tile + mask, zero Sacc
    const float4* Qg = (const float4*)(Q + ((size_t)b*NN + n0)*NF);
    float4* Qs4 = (float4*)Qs;
    #pragma unroll
    for (int i = tid; i < 32*64; i += 512) Qs4[i] = Qg[i];
    if (tid < 32) msk[tid] = (float)mask[b*NN + n0 + tid];
    #pragma unroll
    for (int n = 0; n < 32; n++) Sacc[n*SP + k] = 0.f;
    __syncthreads();

    // q2 per row (warp per 2 rows)
    #pragma unroll
    for (int r = 0; r < 2; r++) {
        int n = warp*2 + r;
        float s = 0.f;
        #pragma unroll
        for (int j = 0; j < 8; j++) {
            float v = Qs[n*256 + lane + 32*j];
            s = __fadd_rn(s, __fmul_rn(v, v));
        }
        #pragma unroll
        for (int o = 16; o; o >>= 1)
            s = __fadd_rn(s, __shfl_xor_sync(0xffffffffu, s, o));
        if (!lane) q2s[n] = s;
    }
    __syncthreads();

    const ulonglong2* Qsv = (const ulonglong2*)Qs;   // 16B granules of Qs
    const ulonglong2* kb  = (const ulonglong2*)kbuf;

    for (int h = 0; h < NH; h++) {
        // previous head's Ctmp reads fully done before kbuf overwrite
        __syncthreads();

        u64 accA[16], accB[16];
        #pragma unroll
        for (int n = 0; n < 16; n++) { accA[n] = 0ull; accB[n] = 0ull; }

        const float* khead = keys + (size_t)h*NK*NF;

        issue_chunk(khead, kbuf, 0, tid);
        issue_chunk(khead, kbuf, 1, tid);

        #pragma unroll 1
        for (int chunk = 0; chunk < 16; chunk++) {
            // one barrier per chunk: wait for stage chunk%3, sync, then
            // issue chunk+2 (its stage was last read in compute(chunk-1),
            // which precedes this sync).
            if (chunk + 1 < 16) {
                asm volatile("cp.async.wait_group 1;");
            } else {
                asm volatile("cp.async.wait_group 0;");
            }
            __syncthreads();
            if (chunk + 2 < 16)
                issue_chunk(khead, kbuf, chunk + 2, tid);

            const int sbase = (chunk % 3) * 2048;
            const ulonglong2* qbase = &Qsv[nbase*64 + chunk*4];

            // granule-ascending accumulation (bitwise-frozen order)
            #pragma unroll
            for (int g = 0; g < 4; g++) {
                ulonglong2 kvA = kb[sbase + g*512 + k0];
                ulonglong2 kvB = kb[sbase + g*512 + k1];
                #pragma unroll
                for (int n = 0; n < 16; n++) {
                    ulonglong2 q = qbase[n*64 + g];
                    FMA2(accA[n], kvA.x, q.x);
                    FMA2(accA[n], kvA.y, q.y);
                    FMA2(accB[n], kvB.x, q.x);
                    FMA2(accB[n], kvB.y, q.y);
                }
            }
        }
        __syncthreads();   // GEMM reads done before Ctmp (alias) writes

        // d2 = (q2+k2) - 2*qk; c = 1/(1 + sqrt(max(d2,0))^2)
        const float k2A = g_k2[h*NK + k0];
        const float k2B = g_k2[h*NK + k1];
        #pragma unroll
        for (int n = 0; n < 16; n++) {
            int nn = nbase + n;
            float qkA = u64_pair_sum(accA[n]);
            float qkB = u64_pair_sum(accB[n]);
            float dA = __fsub_rn(__fadd_rn(q2s[nn], k2A), __fmul_rn(2.0f, qkA));
            float dB = __fsub_rn(__fadd_rn(q2s[nn], k2B), __fmul_rn(2.0f, qkB));
            float tA = sqrtf(fmaxf(dA, 0.0f));
            float tB = sqrtf(fmaxf(dB, 0.0f));
            Ctmp[nn*SP + k0] = __fdiv_rn(1.0f, __fadd_rn(1.0f, __fmul_rn(tA, tA)));
            Ctmp[nn*SP + k1] = __fdiv_rn(1.0f, __fadd_rn(1.0f, __fmul_rn(tB, tB)));
        }
        __syncthreads();

        // rowsum over k: PARALLEL reduction (warp per 2 rows) — order-
        // insensitive (per-row scale, cancels through softmax to ~1e-11)
        #pragma unroll
        for (int r = 0; r < 2; r++) {
            int n = warp*2 + r;
            float s = 0.f;
            #pragma unroll
            for (int j = 0; j < 16; j++)
                s = __fadd_rn(s, Ctmp[n*SP + lane + 32*j]);
            #pragma unroll
            for (int o = 16; o; o >>= 1)
                s = __fadd_rn(s, __shfl_xor_sync(0xffffffffu, s, o));
            if (!lane) rowv[n] = s;
        }
        __syncthreads();

        // logits += cw * ((c / rowsum) * msk), ascending h
        const float cw = conv_w[h];
        #pragma unroll
        for (int n = 0; n < 16; n++) {
            int nn = nbase + n;
            float inv = rowv[nn], m = msk[nn];
            float cA = __fmul_rn(cw, __fmul_rn(__fdiv_rn(Ctmp[nn*SP + k0], inv), m));
            float cB = __fmul_rn(cw, __fmul_rn(__fdiv_rn(Ctmp[nn*SP + k1], inv), m));
            Sacc[nn*SP + k0] = __fadd_rn(Sacc[nn*SP + k0], cA);
            Sacc[nn*SP + k1] = __fadd_rn(Sacc[nn*SP + k1], cB);
        }
    }
    __syncthreads();

    // softmax: row max
    #pragma unroll
    for (int r = 0; r < 2; r++) {
        int n = warp*2 + r;
        float mx = -3.402823466e38f;
        #pragma unroll
        for (int j = 0; j < 16; j++)
            mx = fmaxf(mx, Sacc[n*SP + lane + 32*j]);
        #pragma unroll
        for (int o = 16; o; o >>= 1)
            mx = fmaxf(mx, __shfl_xor_sync(0xffffffffu, mx, o));
        if (!lane) mxs[n] = mx;
    }
    __syncthreads();
    // e = exp(x - mx), correctly-rounded-grade (frozen)
    #pragma unroll
    for (int n = 0; n < 32; n++) {
        float x = __fsub_rn(Sacc[n*SP + k], mxs[n]);
        Sacc[n*SP + k] = exp_small(x);
    }
    __syncthreads();
    // denominator: strict sequential ascending fp32 (FROZEN order)
    if (tid < 32) {
        const float* row = &Sacc[tid*SP];
        float s = 0.f;
        #pragma unroll 8
        for (int j = 0; j < NK; j++)
            s = __fadd_rn(s, row[j]);
        rowv[tid] = s;
    }
    __syncthreads();

    // C = (e / s) * msk
    float* Cout = g_C + ((size_t)b*NN + n0)*NK + k;
    #pragma unroll
    for (int n = 0; n < 32; n++)
        Cout[(size_t)n*NK] = __fmul_rn(__fdiv_rn(Sacc[n*SP + k], rowv[n]), msk[n]);
}

// ------------------------------------------------------------------
// cn[b][k] = strict sequential ascending fp32 sum over n (FROZEN)
__global__ void __launch_bounds__(256) cn_kernel()
{
    int id = blockIdx.x * blockDim.x + threadIdx.x;   // < NB*NK
    int b = id >> 9, kk = id & 511;
    const float* base = g_C + ((size_t)b*NN)*NK + kk;
    float s = 0.f;
    #pragma unroll 8
    for (int n = 0; n < NN; n++)
        s = __fadd_rn(s, base[(size_t)n*NK]);
    g_cnf[id] = s;
}

// ------------------------------------------------------------------
// KL: warp per (b,n) row. Sequential fp32 pn (FROZEN); float-float logs.
__global__ void __launch_bounds__(256) kl_kernel()
{
    __shared__ float cbuf[8][SP];
    __shared__ float pbuf[8][SP];
    const int warp = threadIdx.x >> 5, lane = threadIdx.x & 31;
    const int row = blockIdx.x * 8 + warp;   // < NB*NN
    const int b = row >> 10;
    const float* crow = g_C + (size_t)row * NK;
    const float* cnb = g_cnf + b*NK;

    #pragma unroll
    for (int j = 0; j < 16; j++) {
        int kk = lane + 32*j;
        float c = crow[kk];
        float cnf = __fadd_rn(cnb[kk], EPSF);
        float p = __fdiv_rn(__fmul_rn(c, c), cnf);
        cbuf[warp][kk] = c;
        pbuf[warp][kk] = p;
    }
    __syncwarp();
    if (!lane) {
        float pn = 0.f;
        const float* prow = pbuf[warp];
        #pragma unroll 8
        for (int j = 0; j < NK; j++)
            pn = __fadd_rn(pn, prow[j]);
        pbuf[warp][512] = __fadd_rn(pn, EPSF);
    }
    __syncwarp();
    const float pnf = pbuf[warp][512];

    double t = 0.0;
    #pragma unroll
    for (int j = 0; j < 16; j++) {
        int kk = lane + 32*j;
        float pv = pbuf[warp][kk];
        if (pv != 0.f) {
            float P  = __fdiv_rn(pv, pnf);
            float la = log_near(__fadd_rn(P, EPSF));
            float lb = log_near(__fadd_rn(cbuf[warp][kk], EPSF));
            t += (double)__fmul_rn(P, __fsub_rn(la, lb));
        }
    }
    #pragma unroll
    for (int o = 16; o; o >>= 1) t += __shfl_xor_sync(0xffffffffu, t, o);
    if (!lane) atomicAdd(&g_kl, t);
}

// ------------------------------------------------------------------
// V[b][k][f] = sum_n C[b][n][k] * Q[b][n][f] ; 64x64 tile, packed f32x2
__global__ void __launch_bounds__(256) v_kernel(const float* __restrict__ Q)
{
    const int b = blockIdx.z;
    const int k0 = blockIdx.x * 64, f0 = blockIdx.y * 64;
    __shared__ __align__(16) float As[32][64];
    __shared__ __align__(16) float Bs[32][64];
    const int tid = threadIdx.x;
    const int tx = tid & 15, ty = tid >> 4;
    const int lr = tid >> 6, lc = tid & 63;

    u64 acc2[4][2];
    #pragma unroll
    for (int i = 0; i < 4; i++) { acc2[i][0] = 0ull; acc2[i][1] = 0ull; }

    for (int n0 = 0; n0 < NN; n0 += 32) {
        #pragma unroll
        for (int r = 0; r < 8; r++) {
            int nn = lr + r*4;
            As[nn][lc] = g_C[((size_t)b*NN + n0 + nn)*NK + k0 + lc];
            Bs[nn][lc] = Q[((size_t)b*NN + n0 + nn)*NF + f0 + lc];
        }
        __syncthreads();
        #pragma unroll
        for (int nn = 0; nn < 32; nn++) {
            const u64* Brow = (const u64*)&Bs[nn][ty*4];
            u64 b0 = Brow[0], b1 = Brow[1];
            #pragma unroll
            for (int i = 0; i < 4; i++) {
                unsigned ab = __float_as_uint(As[nn][tx*4 + i]);
                u64 ap;
                asm("mov.b64 %0, {%1, %1};" : "=l"(ap) : "r"(ab));
                FMA2(acc2[i][0], ap, b0);
                FMA2(acc2[i][1], ap, b1);
            }
        }
        __syncthreads();
    }
    #pragma unroll
    for (int i = 0; i < 4; i++)
        #pragma unroll
        for (int jp = 0; jp < 2; jp++) {
            unsigned lo, hi;
            asm("mov.b64 {%0, %1}, %2;" : "=r"(lo), "=r"(hi) : "l"(acc2[i][jp]));
            size_t base = ((size_t)b*NK + k0 + tx*4 + i)*NF + f0 + ty*4 + jp*2;
            g_V[base]     = __uint_as_float(lo);
            g_V[base + 1] = __uint_as_float(hi);
        }
}

// ------------------------------------------------------------------
// out[m][o] = lrelu( sum_f V[m][f]*W[o][f] + bias[o] )
__global__ void __launch_bounds__(256) out_kernel(
    const float* __restrict__ W, const float* __restrict__ bias,
    float* __restrict__ out)
{
    const int m0 = blockIdx.x * 64, o0 = blockIdx.y * 64;
    __shared__ float As[64][33];
    __shared__ float Ws[64][33];
    const int tid = threadIdx.x;
    const int tx = tid & 15, ty = tid >> 4;
    const int lr = tid >> 5, lc = tid & 31;

    float acc[4][4];
    #pragma unroll
    for (int i = 0; i < 4; i++)
        #pragma unroll
        for (int j = 0; j < 4; j++) acc[i][j] = 0.f;

    for (int fc = 0; fc < NF; fc += 32) {
        #pragma unroll
        for (int r = 0; r < 8; r++) {
            int mm = lr + r*8;
            As[mm][lc] = g_V[(size_t)(m0 + mm)*NF + fc + lc];
            Ws[mm][lc] = W[(size_t)(o0 + mm)*NF + fc + lc];
        }
        __syncthreads();
        #pragma unroll
        for (int ff = 0; ff < 32; ff++) {
            float a[4], w[4];
            #pragma unroll
            for (int i = 0; i < 4; i++) a[i] = As[tx*4 + i][ff];
            #pragma unroll
            for (int j = 0; j < 4; j++) w[j] = Ws[ty*4 + j][ff];
            #pragma unroll
            for (int i = 0; i < 4; i++)
                #pragma unroll
                for (int j = 0; j < 4; j++)
                    acc[i][j] = fmaf(a[i], w[j], acc[i][j]);
        }
        __syncthreads();
    }
    #pragma unroll
    for (int j = 0; j < 4; j++) {
        float bj = bias[o0 + ty*4 + j];
        #pragma unroll
        for (int i = 0; i < 4; i++) {
            float v = acc[i][j] + bj;
            v = (v >= 0.f) ? v : 0.01f * v;
            out[(size_t)(m0 + tx*4 + i)*NDOUT + o0 + ty*4 + j] = v;
        }
    }
}

// write kl scalar(s) after the out tensor
__global__ void finalize_kernel(float* __restrict__ out, int out_size)
{
    int i = OUT_ELEMS + blockIdx.x * blockDim.x + threadIdx.x;
    if (i < out_size) out[i] = __fmul_rn(100.0f, (float)g_kl);
}

// ------------------------------------------------------------------
extern "C" void kernel_launch(void* const* d_in, const int* in_sizes, int n_in,
                              void* d_out, int out_size)
{
    const float* Q      = (const float*)d_in[0];
    const float* keys   = (const float*)d_in[1];
    const float* conv_w = (const float*)d_in[2];
    const float* lin_w  = (const float*)d_in[3];
    const float* lin_b  = (const float*)d_in[4];
    const int*   mask   = (const int*)d_in[5];
    float* out = (float*)d_out;

    // smem: Qs 32768 + Sacc 65664 + max(kbuf 98304, Ctmp 65664) + 512
    const int smem = (32*256 + 32*SP + 3*2048*4 + 4*32) * (int)sizeof(float);
    cudaFuncSetAttribute(scores_kernel, cudaFuncAttributeMaxDynamicSharedMemorySize, smem);

    init_kernel<<<1, 32>>>();                      // my #0
    k2_kernel<<<(NH*NK)/8, 256>>>(keys);           // my #1
    dummy_kernel<<<1, 32>>>();                     // my #2
    scores_kernel<<<dim3(NN/32, NB), 512, smem>>>(Q, keys, conv_w, mask); // my #3 = ncu slot 5
    cn_kernel<<<(NB*NK)/256, 256>>>();
    kl_kernel<<<(NB*NN)/8, 256>>>();
    v_kernel<<<dim3(NK/64, NF/64, NB), 256>>>(Q);
    out_kernel<<<dim3((NB*NK)/64, NDOUT/64), 256>>>(lin_w, lin_b, out);

    int extra = out_size - OUT_ELEMS;
    if (extra > 0)
        finalize_kernel<<<(extra + 255)/256, 256>>>(out, out_size);
}

// round 11
// speedup vs baseline: 1.2700x; 1.1222x over previous
#include <cuda_runtime.h>
#include <cstdint>

#define NB   16
#define NN   1024
#define NF   256
#define NH   8
#define NK   512
#define NDOUT 256
#define EPSF 1e-8f
#define OUT_ELEMS (NB*NK*NDOUT)
#define SP   513   // padded row stride

typedef unsigned long long u64;

// packed fp32x2 FMA: acc = a*b + acc
#define FMA2(acc, a, b) \
    asm("fma.rn.f32x2 %0, %1, %2, %0;" : "+l"(acc) : "l"(a), "l"(b))

__device__ __forceinline__ float u64_pair_sum(u64 v) {
    unsigned lo, hi;
    asm("mov.b64 {%0, %1}, %2;" : "=r"(lo), "=r"(hi) : "l"(v));
    return __fadd_rn(__uint_as_float(lo), __uint_as_float(hi));
}

// ---- scratch ----
__device__ float  g_C[(size_t)NB*NN*NK];    // 32 MB
__device__ float  g_V[(size_t)NB*NK*NF];    // 8 MB
__device__ float  g_cnf[NB*NK];
__device__ float  g_k2[NH*NK];
__device__ double g_kl;

// ------------------------------------------------------------------
// exp(x) for x in [-0.125, 0], float-float, ~1e-11 accurate.
__device__ __forceinline__ float exp_small(float x) {
    if (x < -0.125f) return (float)exp((double)x);   // rare fallback
    float x2h = __fmul_rn(x, x);
    float x2l = fmaf(x, x, -x2h);
    float U = fmaf(x, fmaf(x, fmaf(x, fmaf(x, 1.f/5040.f, 1.f/720.f),
                                   1.f/120.f), 1.f/24.f), 1.f/6.f);
    float tail = fmaf(__fmul_rn(x2h, x), U, 0.5f*x2l);
    float sh = __fadd_rn(1.f, x);
    float sl = __fadd_rn(__fsub_rn(1.f, sh), x);
    float b  = 0.5f*x2h;
    float th = __fadd_rn(sh, b);
    float tl = __fadd_rn(__fsub_rn(sh, th), b);
    return __fadd_rn(th, __fadd_rn(__fadd_rn(tl, sl), tail));
}

// log(y) for y ~ 1/512*(1 +- 0.06), float-float, ~1e-11 accurate.
__device__ __forceinline__ float log_near(float y) {
    const double LN512 = 6.2383246250395078;
    const float LH = (float)LN512;
    const float LL = (float)(LN512 - (double)LH);
    float u = __fmul_rn(y, 512.f);
    float w = __fsub_rn(u, 1.f);
    if (fabsf(w) > 0.0625f) return (float)log((double)y);  // rare fallback
    float w2h = __fmul_rn(w, w);
    float w2l = fmaf(w, w, -w2h);
    float V = fmaf(w, fmaf(w, fmaf(w, fmaf(w, fmaf(w, -1.f/8.f, 1.f/7.f),
                                   -1.f/6.f), 1.f/5.f), -1.f/4.f), 1.f/3.f);
    float tail = fmaf(__fmul_rn(w2h, w), V, -0.5f*w2l);
    float b  = -0.5f*w2h;
    float sh = __fadd_rn(w, b);
    float sl = __fadd_rn(__fsub_rn(w, sh), b);
    float th = __fadd_rn(sh, -LH);
    float tl = __fadd_rn(__fsub_rn(-LH, th), sh);
    return __fadd_rn(th, __fsub_rn(__fadd_rn(__fadd_rn(tl, sl), tail), LL));
}

// ------------------------------------------------------------------
__global__ void init_kernel() {
    if (blockIdx.x == 0 && threadIdx.x == 0) g_kl = 0.0;
}

// one dummy: shifts scores_kernel to global ncu slot 5 (-s 5 -c 1)
__global__ void dummy_kernel() {}

// ||keys[h][k]||^2 : warp per row
__global__ void k2_kernel(const float* __restrict__ keys) {
    int warp = threadIdx.x >> 5, lane = threadIdx.x & 31;
    int row = blockIdx.x * 8 + warp;           // < NH*NK = 4096
    const float4* kr = (const float4*)(keys + (size_t)row * NF);
    float s = 0.f;
    #pragma unroll
    for (int j = lane; j < 64; j += 32) {
        float4 v = kr[j];
        s += v.x*v.x + v.y*v.y + v.z*v.z + v.w*v.w;
    }
    #pragma unroll
    for (int o = 16; o; o >>= 1) s += __shfl_xor_sync(0xffffffffu, s, o);
    if (!lane) g_k2[row] = s;
}

// ------------------------------------------------------------------
// issue one key chunk for a WARP PAIR's slice (64 rows x 16 floats) into
// stage chunk%3. Producer warp only (32 lanes, 8 x 16B cp.async each).
// slice layout: float4 index ((stage*8 + pair)*4 + g)*64 + lrow,
// lrow 0..31 = k rows pair*32+lrow, lrow 32..63 = 256+pair*32+(lrow-32).
__device__ __forceinline__ void issue_pair_chunk(
    const float* __restrict__ khead, float* kbuf, int chunk, int pair, int lane)
{
    const int st  = chunk % 3;
    const int seg = lane & 3;                  // constant per lane
    const int r4  = lane >> 2;                 // 0..7
    float4* base = (float4*)kbuf + (size_t)((st*8 + pair)*4 + seg)*64;
    const float* src0 = khead + (size_t)(pair*32 + r4)*NF + chunk*16 + seg*4;
    #pragma unroll
    for (int i = 0; i < 4; i++) {              // lower rows (k0 set)
        unsigned dst = (unsigned)__cvta_generic_to_shared(base + r4 + 8*i);
        asm volatile("cp.async.ca.shared.global [%0], [%1], 16;"
                     :: "r"(dst), "l"(src0 + (size_t)(8*i)*NF));
    }
    const float* src1 = src0 + (size_t)256*NF; // upper rows (k0+256 set)
    #pragma unroll
    for (int i = 0; i < 4; i++) {
        unsigned dst = (unsigned)__cvta_generic_to_shared(base + 32 + r4 + 8*i);
        asm volatile("cp.async.ca.shared.global [%0], [%1], 16;"
                     :: "r"(dst), "l"(src1 + (size_t)(8*i)*NF));
    }
    asm volatile("cp.async.commit_group;");
}

// ------------------------------------------------------------------
// Fused scores kernel: paired-warp key staging — NO block barrier in the
// GEMM chunk loop (2-warp named barriers instead). 512 threads, 32 rows,
// 3-stage cp.async, 2k x 16n tiling. Accumulation order per (n,k) and all
// frozen sums bitwise identical to R10.
__global__ void __launch_bounds__(512, 1) scores_kernel(
    const float* __restrict__ Q, const float* __restrict__ keys,
    const float* __restrict__ conv_w, const int* __restrict__ mask)
{
    extern __shared__ float sm[];
    float* Qs   = sm;                       // 32*256 floats
    float* Sacc = Qs + 32*256;              // 32*SP
    float* kbuf = Sacc + 32*SP;             // 3 stages * 32KB = 24576 floats
    float* Ctmp = kbuf;                     // aliased (disjoint phases)
    float* rowv = kbuf + 3*2048*4;          // 32
    float* q2s  = rowv + 32;                // 32
    float* mxs  = q2s + 32;                 // 32
    float* msk  = mxs + 32;                 // 32

    const int tid  = threadIdx.x;
    const int lane = tid & 31, warp = tid >> 5;
    const int b  = blockIdx.y;
    const int n0 = blockIdx.x * 32;
    const int k  = tid;             // 0..511 (softmax/C phases)

    // GEMM tiling: 2 k rows x 16 n per thread
    const int k0 = tid & 255;       // = pair*32 + lane
    const int k1 = k0 + 256;
    const int nbase = (tid >> 8) * 16;      // 0 or 16
    const int pair = warp & 7;              // pair id (warps p and p+8)
    const bool producer = (warp < 8);

    // load Q tile + mask, zero Sacc
    const float4* Qg = (const float4*)(Q + ((size_t)b*NN + n0)*NF);
    float4* Qs4 = (float4*)Qs;
    #pragma unroll
    for (int i = tid; i < 32*64; i += 512) Qs4[i] = Qg[i];
    if (tid < 32) msk[tid] = (float)mask[b*NN + n0 + tid];
    #pragma unroll
    for (int n = 0; n < 32; n++) Sacc[n*SP + k] = 0.f;
    __syncthreads();

    // q2 per row (warp per 2 rows)
    #pragma unroll
    for (int r = 0; r < 2; r++) {
        int n = warp*2 + r;
        float s = 0.f;
        #pragma unroll
        for (int j = 0; j < 8; j++) {
            float v = Qs[n*256 + lane + 32*j];
            s = __fadd_rn(s, __fmul_rn(v, v));
        }
        #pragma unroll
        for (int o = 16; o; o >>= 1)
            s = __fadd_rn(s, __shfl_xor_sync(0xffffffffu, s, o));
        if (!lane) q2s[n] = s;
    }
    __syncthreads();

    const ulonglong2* Qsv = (const ulonglong2*)Qs;   // 16B granules of Qs
    const ulonglong2* kb  = (const ulonglong2*)kbuf;

    for (int h = 0; h < NH; h++) {
        // previous head's Ctmp (alias of kbuf) reads fully done
        __syncthreads();

        u64 accA[16], accB[16];
        #pragma unroll
        for (int n = 0; n < 16; n++) { accA[n] = 0ull; accB[n] = 0ull; }

        const float* khead = keys + (size_t)h*NK*NF;

        if (producer) {
            issue_pair_chunk(khead, kbuf, 0, pair, lane);
            issue_pair_chunk(khead, kbuf, 1, pair, lane);
        }

        #pragma unroll 1
        for (int chunk = 0; chunk < 16; chunk++) {
            if (producer) {
                if (chunk + 1 < 16)
                    asm volatile("cp.async.wait_group 1;");
                else
                    asm volatile("cp.async.wait_group 0;");
            }
            // 2-warp pair barrier (ids 1..8); replaces block-wide sync
            asm volatile("bar.sync %0, 64;" :: "r"(pair + 1) : "memory");
            if (producer && chunk + 2 < 16)
                issue_pair_chunk(khead, kbuf, chunk + 2, pair, lane);

            // this pair's slice, this stage
            const ulonglong2* kbp =
                kb + (size_t)(((chunk % 3)*8 + pair)*4)*64;
            const ulonglong2* qbase = &Qsv[nbase*64 + chunk*4];

            // granule-ascending accumulation (bitwise-frozen order)
            #pragma unroll
            for (int g = 0; g < 4; g++) {
                ulonglong2 kvA = kbp[g*64 + lane];        // k0 row
                ulonglong2 kvB = kbp[g*64 + 32 + lane];   // k1 row
                #pragma unroll
                for (int n = 0; n < 16; n++) {
                    ulonglong2 q = qbase[n*64 + g];
                    FMA2(accA[n], kvA.x, q.x);
                    FMA2(accA[n], kvA.y, q.y);
                    FMA2(accB[n], kvB.x, q.x);
                    FMA2(accB[n], kvB.y, q.y);
                }
            }
        }
        __syncthreads();   // all GEMM reads done before Ctmp (alias) writes

        // d2 = (q2+k2) - 2*qk; c = 1/(1 + sqrt(max(d2,0))^2)
        const float k2A = g_k2[h*NK + k0];
        const float k2B = g_k2[h*NK + k1];
        #pragma unroll
        for (int n = 0; n < 16; n++) {
            int nn = nbase + n;
            float qkA = u64_pair_sum(accA[n]);
            float qkB = u64_pair_sum(accB[n]);
            float dA = __fsub_rn(__fadd_rn(q2s[nn], k2A), __fmul_rn(2.0f, qkA));
            float dB = __fsub_rn(__fadd_rn(q2s[nn], k2B), __fmul_rn(2.0f, qkB));
            float tA = sqrtf(fmaxf(dA, 0.0f));
            float tB = sqrtf(fmaxf(dB, 0.0f));
            Ctmp[nn*SP + k0] = __fdiv_rn(1.0f, __fadd_rn(1.0f, __fmul_rn(tA, tA)));
            Ctmp[nn*SP + k1] = __fdiv_rn(1.0f, __fadd_rn(1.0f, __fmul_rn(tB, tB)));
        }
        __syncthreads();

        // rowsum over k: PARALLEL reduction (order-insensitive per R10)
        #pragma unroll
        for (int r = 0; r < 2; r++) {
            int n = warp*2 + r;
            float s = 0.f;
            #pragma unroll
            for (int j = 0; j < 16; j++)
                s = __fadd_rn(s, Ctmp[n*SP + lane + 32*j]);
            #pragma unroll
            for (int o = 16; o; o >>= 1)
                s = __fadd_rn(s, __shfl_xor_sync(0xffffffffu, s, o));
            if (!lane) rowv[n] = s;
        }
        __syncthreads();

        // logits += cw * ((c / rowsum) * msk), ascending h
        const float cw = conv_w[h];
        #pragma unroll
        for (int n = 0; n < 16; n++) {
            int nn = nbase + n;
            float inv = rowv[nn], m = msk[nn];
            float cA = __fmul_rn(cw, __fmul_rn(__fdiv_rn(Ctmp[nn*SP + k0], inv), m));
            float cB = __fmul_rn(cw, __fmul_rn(__fdiv_rn(Ctmp[nn*SP + k1], inv), m));
            Sacc[nn*SP + k0] = __fadd_rn(Sacc[nn*SP + k0], cA);
            Sacc[nn*SP + k1] = __fadd_rn(Sacc[nn*SP + k1], cB);
        }
    }
    __syncthreads();

    // softmax: row max
    #pragma unroll
    for (int r = 0; r < 2; r++) {
        int n = warp*2 + r;
        float mx = -3.402823466e38f;
        #pragma unroll
        for (int j = 0; j < 16; j++)
            mx = fmaxf(mx, Sacc[n*SP + lane + 32*j]);
        #pragma unroll
        for (int o = 16; o; o >>= 1)
            mx = fmaxf(mx, __shfl_xor_sync(0xffffffffu, mx, o));
        if (!lane) mxs[n] = mx;
    }
    __syncthreads();
    // e = exp(x - mx), correctly-rounded-grade (frozen)
    #pragma unroll
    for (int n = 0; n < 32; n++) {
        float x = __fsub_rn(Sacc[n*SP + k], mxs[n]);
        Sacc[n*SP + k] = exp_small(x);
    }
    __syncthreads();
    // denominator: strict sequential ascending fp32 (FROZEN order)
    if (tid < 32) {
        const float* row = &Sacc[tid*SP];
        float s = 0.f;
        #pragma unroll 8
        for (int j = 0; j < NK; j++)
            s = __fadd_rn(s, row[j]);
        rowv[tid] = s;
    }
    __syncthreads();

    // C = (e / s) * msk
    float* Cout = g_C + ((size_t)b*NN + n0)*NK + k;
    #pragma unroll
    for (int n = 0; n < 32; n++)
        Cout[(size_t)n*NK] = __fmul_rn(__fdiv_rn(Sacc[n*SP + k], rowv[n]), msk[n]);
}

// ------------------------------------------------------------------
// cn[b][k] = strict sequential ascending fp32 sum over n (FROZEN)
__global__ void __launch_bounds__(256) cn_kernel()
{
    int id = blockIdx.x * blockDim.x + threadIdx.x;   // < NB*NK
    int b = id >> 9, kk = id & 511;
    const float* base = g_C + ((size_t)b*NN)*NK + kk;
    float s = 0.f;
    #pragma unroll 8
    for (int n = 0; n < NN; n++)
        s = __fadd_rn(s, base[(size_t)n*NK]);
    g_cnf[id] = s;
}

// ------------------------------------------------------------------
// KL: warp per (b,n) row. Sequential fp32 pn (FROZEN); float-float logs.
__global__ void __launch_bounds__(256) kl_kernel()
{
    __shared__ float cbuf[8][SP];
    __shared__ float pbuf[8][SP];
    const int warp = threadIdx.x >> 5, lane = threadIdx.x & 31;
    const int row = blockIdx.x * 8 + warp;   // < NB*NN
    const int b = row >> 10;
    const float* crow = g_C + (size_t)row * NK;
    const float* cnb = g_cnf + b*NK;

    #pragma unroll
    for (int j = 0; j < 16; j++) {
        int kk = lane + 32*j;
        float c = crow[kk];
        float cnf = __fadd_rn(cnb[kk], EPSF);
        float p = __fdiv_rn(__fmul_rn(c, c), cnf);
        cbuf[warp][kk] = c;
        pbuf[warp][kk] = p;
    }
    __syncwarp();
    if (!lane) {
        float pn = 0.f;
        const float* prow = pbuf[warp];
        #pragma unroll 8
        for (int j = 0; j < NK; j++)
            pn = __fadd_rn(pn, prow[j]);
        pbuf[warp][512] = __fadd_rn(pn, EPSF);
    }
    __syncwarp();
    const float pnf = pbuf[warp][512];

    double t = 0.0;
    #pragma unroll
    for (int j = 0; j < 16; j++) {
        int kk = lane + 32*j;
        float pv = pbuf[warp][kk];
        if (pv != 0.f) {
            float P  = __fdiv_rn(pv, pnf);
            float la = log_near(__fadd_rn(P, EPSF));
            float lb = log_near(__fadd_rn(cbuf[warp][kk], EPSF));
            t += (double)__fmul_rn(P, __fsub_rn(la, lb));
        }
    }
    #pragma unroll
    for (int o = 16; o; o >>= 1) t += __shfl_xor_sync(0xffffffffu, t, o);
    if (!lane) atomicAdd(&g_kl, t);
}

// ------------------------------------------------------------------
// V[b][k][f] = sum_n C[b][n][k] * Q[b][n][f] ; 64x64 tile, packed f32x2
__global__ void __launch_bounds__(256) v_kernel(const float* __restrict__ Q)
{
    const int b = blockIdx.z;
    const int k0 = blockIdx.x * 64, f0 = blockIdx.y * 64;
    __shared__ __align__(16) float As[32][64];
    __shared__ __align__(16) float Bs[32][64];
    const int tid = threadIdx.x;
    const int tx = tid & 15, ty = tid >> 4;
    const int lr = tid >> 6, lc = tid & 63;

    u64 acc2[4][2];
    #pragma unroll
    for (int i = 0; i < 4; i++) { acc2[i][0] = 0ull; acc2[i][1] = 0ull; }

    for (int n0 = 0; n0 < NN; n0 += 32) {
        #pragma unroll
        for (int r = 0; r < 8; r++) {
            int nn = lr + r*4;
            As[nn][lc] = g_C[((size_t)b*NN + n0 + nn)*NK + k0 + lc];
            Bs[nn][lc] = Q[((size_t)b*NN + n0 + nn)*NF + f0 + lc];
        }
        __syncthreads();
        #pragma unroll
        for (int nn = 0; nn < 32; nn++) {
            const u64* Brow = (const u64*)&Bs[nn][ty*4];
            u64 b0 = Brow[0], b1 = Brow[1];
            #pragma unroll
            for (int i = 0; i < 4; i++) {
                unsigned ab = __float_as_uint(As[nn][tx*4 + i]);
                u64 ap;
                asm("mov.b64 %0, {%1, %1};" : "=l"(ap) : "r"(ab));
                FMA2(acc2[i][0], ap, b0);
                FMA2(acc2[i][1], ap, b1);
            }
        }
        __syncthreads();
    }
    #pragma unroll
    for (int i = 0; i < 4; i++)
        #pragma unroll
        for (int jp = 0; jp < 2; jp++) {
            unsigned lo, hi;
            asm("mov.b64 {%0, %1}, %2;" : "=r"(lo), "=r"(hi) : "l"(acc2[i][jp]));
            size_t base = ((size_t)b*NK + k0 + tx*4 + i)*NF + f0 + ty*4 + jp*2;
            g_V[base]     = __uint_as_float(lo);
            g_V[base + 1] = __uint_as_float(hi);
        }
}

// ------------------------------------------------------------------
// out[m][o] = lrelu( sum_f V[m][f]*W[o][f] + bias[o] )
__global__ void __launch_bounds__(256) out_kernel(
    const float* __restrict__ W, const float* __restrict__ bias,
    float* __restrict__ out)
{
    const int m0 = blockIdx.x * 64, o0 = blockIdx.y * 64;
    __shared__ float As[64][33];
    __shared__ float Ws[64][33];
    const int tid = threadIdx.x;
    const int tx = tid & 15, ty = tid >> 4;
    const int lr = tid >> 5, lc = tid & 31;

    float acc[4][4];
    #pragma unroll
    for (int i = 0; i < 4; i++)
        #pragma unroll
        for (int j = 0; j < 4; j++) acc[i][j] = 0.f;

    for (int fc = 0; fc < NF; fc += 32) {
        #pragma unroll
        for (int r = 0; r < 8; r++) {
            int mm = lr + r*8;
            As[mm][lc] = g_V[(size_t)(m0 + mm)*NF + fc + lc];
            Ws[mm][lc] = W[(size_t)(o0 + mm)*NF + fc + lc];
        }
        __syncthreads();
        #pragma unroll
        for (int ff = 0; ff < 32; ff++) {
            float a[4], w[4];
            #pragma unroll
            for (int i = 0; i < 4; i++) a[i] = As[tx*4 + i][ff];
            #pragma unroll
            for (int j = 0; j < 4; j++) w[j] = Ws[ty*4 + j][ff];
            #pragma unroll
            for (int i = 0; i < 4; i++)
                #pragma unroll
                for (int j = 0; j < 4; j++)
                    acc[i][j] = fmaf(a[i], w[j], acc[i][j]);
        }
        __syncthreads();
    }
    #pragma unroll
    for (int j = 0; j < 4; j++) {
        float bj = bias[o0 + ty*4 + j];
        #pragma unroll
        for (int i = 0; i < 4; i++) {
            float v = acc[i][j] + bj;
            v = (v >= 0.f) ? v : 0.01f * v;
            out[(size_t)(m0 + tx*4 + i)*NDOUT + o0 + ty*4 + j] = v;
        }
    }
}

// write kl scalar(s) after the out tensor
__global__ void finalize_kernel(float* __restrict__ out, int out_size)
{
    int i = OUT_ELEMS + blockIdx.x * blockDim.x + threadIdx.x;
    if (i < out_size) out[i] = __fmul_rn(100.0f, (float)g_kl);
}

// ------------------------------------------------------------------
extern "C" void kernel_launch(void* const* d_in, const int* in_sizes, int n_in,
                              void* d_out, int out_size)
{
    const float* Q      = (const float*)d_in[0];
    const float* keys   = (const float*)d_in[1];
    const float* conv_w = (const float*)d_in[2];
    const float* lin_w  = (const float*)d_in[3];
    const float* lin_b  = (const float*)d_in[4];
    const int*   mask   = (const int*)d_in[5];
    float* out = (float*)d_out;

    // smem: Qs 32768 + Sacc 65664 + max(kbuf 98304, Ctmp 65664) + 512
    const int smem = (32*256 + 32*SP + 3*2048*4 + 4*32) * (int)sizeof(float);
    cudaFuncSetAttribute(scores_kernel, cudaFuncAttributeMaxDynamicSharedMemorySize, smem);

    init_kernel<<<1, 32>>>();                      // my #0
    k2_kernel<<<(NH*NK)/8, 256>>>(keys);           // my #1
    dummy_kernel<<<1, 32>>>();                     // my #2
    scores_kernel<<<dim3(NN/32, NB), 512, smem>>>(Q, keys, conv_w, mask); // my #3 = ncu slot 5
    cn_kernel<<<(NB*NK)/256, 256>>>();
    kl_kernel<<<(NB*NN)/8, 256>>>();
    v_kernel<<<dim3(NK/64, NF/64, NB), 256>>>(Q);
    out_kernel<<<dim3((NB*NK)/64, NDOUT/64), 256>>>(lin_w, lin_b, out);

    int extra = out_size - OUT_ELEMS;
    if (extra > 0)
        finalize_kernel<<<(extra + 255)/256, 256>>>(out, out_size);
}

// round 12
// speedup vs baseline: 1.3204x; 1.0396x over previous
#include <cuda_runtime.h>
#include <cstdint>

#define NB   16
#define NN   1024
#define NF   256
#define NH   8
#define NK   512
#define NDOUT 256
#define EPSF 1e-8f
#define OUT_ELEMS (NB*NK*NDOUT)
#define SP   513   // padded row stride

typedef unsigned long long u64;

// packed fp32x2 FMA: acc = a*b + acc
#define FMA2(acc, a, b) \
    asm("fma.rn.f32x2 %0, %1, %2, %0;" : "+l"(acc) : "l"(a), "l"(b))

__device__ __forceinline__ float u64_pair_sum(u64 v) {
    unsigned lo, hi;
    asm("mov.b64 {%0, %1}, %2;" : "=r"(lo), "=r"(hi) : "l"(v));
    return __fadd_rn(__uint_as_float(lo), __uint_as_float(hi));
}

// ---- scratch ----
__device__ float  g_C[(size_t)NB*NN*NK];    // 32 MB
__device__ float  g_V[(size_t)NB*NK*NF];    // 8 MB
__device__ float  g_cnf[NB*NK];
__device__ float  g_k2[NH*NK];
__device__ double g_kl;

// ------------------------------------------------------------------
// exp(x) for x in [-0.125, 0], float-float, ~1e-11 accurate.
__device__ __forceinline__ float exp_small(float x) {
    if (x < -0.125f) return (float)exp((double)x);   // rare fallback
    float x2h = __fmul_rn(x, x);
    float x2l = fmaf(x, x, -x2h);
    float U = fmaf(x, fmaf(x, fmaf(x, fmaf(x, 1.f/5040.f, 1.f/720.f),
                                   1.f/120.f), 1.f/24.f), 1.f/6.f);
    float tail = fmaf(__fmul_rn(x2h, x), U, 0.5f*x2l);
    float sh = __fadd_rn(1.f, x);
    float sl = __fadd_rn(__fsub_rn(1.f, sh), x);
    float b  = 0.5f*x2h;
    float th = __fadd_rn(sh, b);
    float tl = __fadd_rn(__fsub_rn(sh, th), b);
    return __fadd_rn(th, __fadd_rn(__fadd_rn(tl, sl), tail));
}

// log(y) for y ~ 1/512*(1 +- 0.06), float-float, ~1e-11 accurate.
__device__ __forceinline__ float log_near(float y) {
    const double LN512 = 6.2383246250395078;
    const float LH = (float)LN512;
    const float LL = (float)(LN512 - (double)LH);
    float u = __fmul_rn(y, 512.f);
    float w = __fsub_rn(u, 1.f);
    if (fabsf(w) > 0.0625f) return (float)log((double)y);  // rare fallback
    float w2h = __fmul_rn(w, w);
    float w2l = fmaf(w, w, -w2h);
    float V = fmaf(w, fmaf(w, fmaf(w, fmaf(w, fmaf(w, -1.f/8.f, 1.f/7.f),
                                   -1.f/6.f), 1.f/5.f), -1.f/4.f), 1.f/3.f);
    float tail = fmaf(__fmul_rn(w2h, w), V, -0.5f*w2l);
    float b  = -0.5f*w2h;
    float sh = __fadd_rn(w, b);
    float sl = __fadd_rn(__fsub_rn(w, sh), b);
    float th = __fadd_rn(sh, -LH);
    float tl = __fadd_rn(__fsub_rn(-LH, th), sh);
    return __fadd_rn(th, __fsub_rn(__fadd_rn(__fadd_rn(tl, sl), tail), LL));
}

// ------------------------------------------------------------------
__global__ void init_kernel() {
    if (blockIdx.x == 0 && threadIdx.x == 0) g_kl = 0.0;
}

// one dummy: shifts scores_kernel to global ncu slot 5 (-s 5 -c 1)
__global__ void dummy_kernel() {}

// ||keys[h][k]||^2 : warp per row
__global__ void k2_kernel(const float* __restrict__ keys) {
    int warp = threadIdx.x >> 5, lane = threadIdx.x & 31;
    int row = blockIdx.x * 8 + warp;           // < NH*NK = 4096
    const float4* kr = (const float4*)(keys + (size_t)row * NF);
    float s = 0.f;
    #pragma unroll
    for (int j = lane; j < 64; j += 32) {
        float4 v = kr[j];
        s += v.x*v.x + v.y*v.y + v.z*v.z + v.w*v.w;
    }
    #pragma unroll
    for (int o = 16; o; o >>= 1) s += __shfl_xor_sync(0xffffffffu, s, o);
    if (!lane) g_k2[row] = s;
}

// ------------------------------------------------------------------
// issue one key chunk for a WARP QUAD's slice (128 rows x 16 floats) into
// stage chunk%3. Producer warp only (32 lanes, 16 x 16B cp.async each).
// slice layout: float4 index ((stage*4 + quad)*4 + g)*128 + idx,
// idx = j*32 + r -> key row quad*32 + r + 128*j.
__device__ __forceinline__ void issue_quad_chunk(
    const float* __restrict__ khead, float* kbuf, int chunk, int quad, int lane)
{
    const int st  = chunk % 3;
    const int seg = lane & 3;                  // granule g this lane fills
    const int r8  = lane >> 2;                 // 0..7
    float4* base = (float4*)kbuf + (size_t)((st*4 + quad)*4 + seg)*128;
    #pragma unroll
    for (int i = 0; i < 16; i++) {
        int idx  = r8 + 8*i;                   // 0..127
        int grow = quad*32 + (idx & 31) + 128*(idx >> 5);
        const float* src = khead + (size_t)grow*NF + chunk*16 + seg*4;
        unsigned dst = (unsigned)__cvta_generic_to_shared(base + idx);
        asm volatile("cp.async.ca.shared.global [%0], [%1], 16;"
                     :: "r"(dst), "l"(src));
    }
    asm volatile("cp.async.commit_group;");
}

// ------------------------------------------------------------------
// Fused scores kernel: quad-warp key staging (4-warp named barriers, no
// block barrier in GEMM loop), 3-stage cp.async, 4k x 8n register tiling
// (Q-broadcast LDS halved -> crossbar == FMA2 pipe). Accumulation order
// per (n,k) and all frozen sums bitwise identical to R11.
__global__ void __launch_bounds__(512, 1) scores_kernel(
    const float* __restrict__ Q, const float* __restrict__ keys,
    const float* __restrict__ conv_w, const int* __restrict__ mask)
{
    extern __shared__ float sm[];
    float* Qs   = sm;                       // 32*256 floats
    float* Sacc = Qs + 32*256;              // 32*SP
    float* kbuf = Sacc + 32*SP;             // 3 stages * 32KB = 24576 floats
    float* Ctmp = kbuf;                     // aliased (disjoint phases)
    float* rowv = kbuf + 3*2048*4;          // 32
    float* q2s  = rowv + 32;                // 32
    float* mxs  = q2s + 32;                 // 32
    float* msk  = mxs + 32;                 // 32

    const int tid  = threadIdx.x;
    const int lane = tid & 31, warp = tid >> 5;
    const int b  = blockIdx.y;
    const int n0 = blockIdx.x * 32;
    const int k  = tid;             // 0..511 (softmax/C phases)

    // GEMM tiling: 4 k rows x 8 n per thread
    const int quad = warp & 3;              // quad id (warps q,q+4,q+8,q+12)
    const int k0 = quad*32 + lane;          // = tid & 127
    const int nbase = (tid >> 7) * 8;       // 0, 8, 16, 24
    const bool producer = (warp < 4);

    // load Q tile + mask, zero Sacc
    const float4* Qg = (const float4*)(Q + ((size_t)b*NN + n0)*NF);
    float4* Qs4 = (float4*)Qs;
    #pragma unroll
    for (int i = tid; i < 32*64; i += 512) Qs4[i] = Qg[i];
    if (tid < 32) msk[tid] = (float)mask[b*NN + n0 + tid];
    #pragma unroll
    for (int n = 0; n < 32; n++) Sacc[n*SP + k] = 0.f;
    __syncthreads();

    // q2 per row (warp per 2 rows)
    #pragma unroll
    for (int r = 0; r < 2; r++) {
        int n = warp*2 + r;
        float s = 0.f;
        #pragma unroll
        for (int j = 0; j < 8; j++) {
            float v = Qs[n*256 + lane + 32*j];
            s = __fadd_rn(s, __fmul_rn(v, v));
        }
        #pragma unroll
        for (int o = 16; o; o >>= 1)
            s = __fadd_rn(s, __shfl_xor_sync(0xffffffffu, s, o));
        if (!lane) q2s[n] = s;
    }
    __syncthreads();

    const ulonglong2* Qsv = (const ulonglong2*)Qs;   // 16B granules of Qs
    const ulonglong2* kb  = (const ulonglong2*)kbuf;

    for (int h = 0; h < NH; h++) {
        // previous head's Ctmp (alias of kbuf) reads fully done
        __syncthreads();

        u64 acc[4][8];
        #pragma unroll
        for (int j = 0; j < 4; j++)
            #pragma unroll
            for (int n = 0; n < 8; n++) acc[j][n] = 0ull;

        const float* khead = keys + (size_t)h*NK*NF;

        if (producer) {
            issue_quad_chunk(khead, kbuf, 0, quad, lane);
            issue_quad_chunk(khead, kbuf, 1, quad, lane);
        }

        #pragma unroll 1
        for (int chunk = 0; chunk < 16; chunk++) {
            if (producer) {
                if (chunk + 1 < 16)
                    asm volatile("cp.async.wait_group 1;");
                else
                    asm volatile("cp.async.wait_group 0;");
            }
            // 4-warp quad barrier (ids 1..4); replaces block-wide sync
            asm volatile("bar.sync %0, 128;" :: "r"(quad + 1) : "memory");
            if (producer && chunk + 2 < 16)
                issue_quad_chunk(khead, kbuf, chunk + 2, quad, lane);

            // this quad's slice, this stage
            const ulonglong2* kbp =
                kb + (size_t)(((chunk % 3)*4 + quad)*4)*128;
            const ulonglong2* qbase = &Qsv[nbase*64 + chunk*4];

            // granule-ascending accumulation (bitwise-frozen order)
            #pragma unroll
            for (int g = 0; g < 4; g++) {
                ulonglong2 kv0 = kbp[g*128 + lane];        // k0
                ulonglong2 kv1 = kbp[g*128 + 32 + lane];   // k0+128
                ulonglong2 kv2 = kbp[g*128 + 64 + lane];   // k0+256
                ulonglong2 kv3 = kbp[g*128 + 96 + lane];   // k0+384
                #pragma unroll
                for (int n = 0; n < 8; n++) {
                    ulonglong2 q = qbase[n*64 + g];
                    FMA2(acc[0][n], kv0.x, q.x);
                    FMA2(acc[0][n], kv0.y, q.y);
                    FMA2(acc[1][n], kv1.x, q.x);
                    FMA2(acc[1][n], kv1.y, q.y);
                    FMA2(acc[2][n], kv2.x, q.x);
                    FMA2(acc[2][n], kv2.y, q.y);
                    FMA2(acc[3][n], kv3.x, q.x);
                    FMA2(acc[3][n], kv3.y, q.y);
                }
            }
        }
        __syncthreads();   // all GEMM reads done before Ctmp (alias) writes

        // d2 = (q2+k2) - 2*qk; c = 1/(1 + sqrt(max(d2,0))^2)
        #pragma unroll
        for (int j = 0; j < 4; j++) {
            int kx = k0 + 128*j;
            float k2v = g_k2[h*NK + kx];
            #pragma unroll
            for (int n = 0; n < 8; n++) {
                int nn = nbase + n;
                float qk = u64_pair_sum(acc[j][n]);
                float d2 = __fsub_rn(__fadd_rn(q2s[nn], k2v),
                                     __fmul_rn(2.0f, qk));
                float t  = sqrtf(fmaxf(d2, 0.0f));
                Ctmp[nn*SP + kx] =
                    __fdiv_rn(1.0f, __fadd_rn(1.0f, __fmul_rn(t, t)));
            }
        }
        __syncthreads();

        // rowsum over k: PARALLEL reduction (order-insensitive per R10)
        #pragma unroll
        for (int r = 0; r < 2; r++) {
            int n = warp*2 + r;
            float s = 0.f;
            #pragma unroll
            for (int j = 0; j < 16; j++)
                s = __fadd_rn(s, Ctmp[n*SP + lane + 32*j]);
            #pragma unroll
            for (int o = 16; o; o >>= 1)
                s = __fadd_rn(s, __shfl_xor_sync(0xffffffffu, s, o));
            if (!lane) rowv[n] = s;
        }
        __syncthreads();

        // logits += cw * ((c / rowsum) * msk), ascending h
        const float cw = conv_w[h];
        #pragma unroll
        for (int j = 0; j < 4; j++) {
            int kx = k0 + 128*j;
            #pragma unroll
            for (int n = 0; n < 8; n++) {
                int nn = nbase + n;
                float cdiv = __fdiv_rn(Ctmp[nn*SP + kx], rowv[nn]);
                float term = __fmul_rn(cw, __fmul_rn(cdiv, msk[nn]));
                Sacc[nn*SP + kx] = __fadd_rn(Sacc[nn*SP + kx], term);
            }
        }
    }
    __syncthreads();

    // softmax: row max
    #pragma unroll
    for (int r = 0; r < 2; r++) {
        int n = warp*2 + r;
        float mx = -3.402823466e38f;
        #pragma unroll
        for (int j = 0; j < 16; j++)
            mx = fmaxf(mx, Sacc[n*SP + lane + 32*j]);
        #pragma unroll
        for (int o = 16; o; o >>= 1)
            mx = fmaxf(mx, __shfl_xor_sync(0xffffffffu, mx, o));
        if (!lane) mxs[n] = mx;
    }
    __syncthreads();
    // e = exp(x - mx), correctly-rounded-grade (frozen)
    #pragma unroll
    for (int n = 0; n < 32; n++) {
        float x = __fsub_rn(Sacc[n*SP + k], mxs[n]);
        Sacc[n*SP + k] = exp_small(x);
    }
    __syncthreads();
    // denominator: strict sequential ascending fp32 (FROZEN order)
    if (tid < 32) {
        const float* row = &Sacc[tid*SP];
        float s = 0.f;
        #pragma unroll 8
        for (int j = 0; j < NK; j++)
            s = __fadd_rn(s, row[j]);
        rowv[tid] = s;
    }
    __syncthreads();

    // C = (e / s) * msk
    float* Cout = g_C + ((size_t)b*NN + n0)*NK + k;
    #pragma unroll
    for (int n = 0; n < 32; n++)
        Cout[(size_t)n*NK] = __fmul_rn(__fdiv_rn(Sacc[n*SP + k], rowv[n]), msk[n]);
}

// ------------------------------------------------------------------
// cn[b][k] = strict sequential ascending fp32 sum over n (FROZEN)
__global__ void __launch_bounds__(256) cn_kernel()
{
    int id = blockIdx.x * blockDim.x + threadIdx.x;   // < NB*NK
    int b = id >> 9, kk = id & 511;
    const float* base = g_C + ((size_t)b*NN)*NK + kk;
    float s = 0.f;
    #pragma unroll 8
    for (int n = 0; n < NN; n++)
        s = __fadd_rn(s, base[(size_t)n*NK]);
    g_cnf[id] = s;
}

// ------------------------------------------------------------------
// KL: warp per (b,n) row. Sequential fp32 pn (FROZEN); float-float logs.
__global__ void __launch_bounds__(256) kl_kernel()
{
    __shared__ float cbuf[8][SP];
    __shared__ float pbuf[8][SP];
    const int warp = threadIdx.x >> 5, lane = threadIdx.x & 31;
    const int row = blockIdx.x * 8 + warp;   // < NB*NN
    const int b = row >> 10;
    const float* crow = g_C + (size_t)row * NK;
    const float* cnb = g_cnf + b*NK;

    #pragma unroll
    for (int j = 0; j < 16; j++) {
        int kk = lane + 32*j;
        float c = crow[kk];
        float cnf = __fadd_rn(cnb[kk], EPSF);
        float p = __fdiv_rn(__fmul_rn(c, c), cnf);
        cbuf[warp][kk] = c;
        pbuf[warp][kk] = p;
    }
    __syncwarp();
    if (!lane) {
        float pn = 0.f;
        const float* prow = pbuf[warp];
        #pragma unroll 8
        for (int j = 0; j < NK; j++)
            pn = __fadd_rn(pn, prow[j]);
        pbuf[warp][512] = __fadd_rn(pn, EPSF);
    }
    __syncwarp();
    const float pnf = pbuf[warp][512];

    double t = 0.0;
    #pragma unroll
    for (int j = 0; j < 16; j++) {
        int kk = lane + 32*j;
        float pv = pbuf[warp][kk];
        if (pv != 0.f) {
            float P  = __fdiv_rn(pv, pnf);
            float la = log_near(__fadd_rn(P, EPSF));
            float lb = log_near(__fadd_rn(cbuf[warp][kk], EPSF));
            t += (double)__fmul_rn(P, __fsub_rn(la, lb));
        }
    }
    #pragma unroll
    for (int o = 16; o; o >>= 1) t += __shfl_xor_sync(0xffffffffu, t, o);
    if (!lane) atomicAdd(&g_kl, t);
}

// ------------------------------------------------------------------
// V[b][k][f] = sum_n C[b][n][k] * Q[b][n][f] ; 64x64 tile, packed f32x2
__global__ void __launch_bounds__(256) v_kernel(const float* __restrict__ Q)
{
    const int b = blockIdx.z;
    const int k0 = blockIdx.x * 64, f0 = blockIdx.y * 64;
    __shared__ __align__(16) float As[32][64];
    __shared__ __align__(16) float Bs[32][64];
    const int tid = threadIdx.x;
    const int tx = tid & 15, ty = tid >> 4;
    const int lr = tid >> 6, lc = tid & 63;

    u64 acc2[4][2];
    #pragma unroll
    for (int i = 0; i < 4; i++) { acc2[i][0] = 0ull; acc2[i][1] = 0ull; }

    for (int n0 = 0; n0 < NN; n0 += 32) {
        #pragma unroll
        for (int r = 0; r < 8; r++) {
            int nn = lr + r*4;
            As[nn][lc] = g_C[((size_t)b*NN + n0 + nn)*NK + k0 + lc];
            Bs[nn][lc] = Q[((size_t)b*NN + n0 + nn)*NF + f0 + lc];
        }
        __syncthreads();
        #pragma unroll
        for (int nn = 0; nn < 32; nn++) {
            const u64* Brow = (const u64*)&Bs[nn][ty*4];
            u64 b0 = Brow[0], b1 = Brow[1];
            #pragma unroll
            for (int i = 0; i < 4; i++) {
                unsigned ab = __float_as_uint(As[nn][tx*4 + i]);
                u64 ap;
                asm("mov.b64 %0, {%1, %1};" : "=l"(ap) : "r"(ab));
                FMA2(acc2[i][0], ap, b0);
                FMA2(acc2[i][1], ap, b1);
            }
        }
        __syncthreads();
    }
    #pragma unroll
    for (int i = 0; i < 4; i++)
        #pragma unroll
        for (int jp = 0; jp < 2; jp++) {
            unsigned lo, hi;
            asm("mov.b64 {%0, %1}, %2;" : "=r"(lo), "=r"(hi) : "l"(acc2[i][jp]));
            size_t base = ((size_t)b*NK + k0 + tx*4 + i)*NF + f0 + ty*4 + jp*2;
            g_V[base]     = __uint_as_float(lo);
            g_V[base + 1] = __uint_as_float(hi);
        }
}

// ------------------------------------------------------------------
// out[m][o] = lrelu( sum_f V[m][f]*W[o][f] + bias[o] )
__global__ void __launch_bounds__(256) out_kernel(
    const float* __restrict__ W, const float* __restrict__ bias,
    float* __restrict__ out)
{
    const int m0 = blockIdx.x * 64, o0 = blockIdx.y * 64;
    __shared__ float As[64][33];
    __shared__ float Ws[64][33];
    const int tid = threadIdx.x;
    const int tx = tid & 15, ty = tid >> 4;
    const int lr = tid >> 5, lc = tid & 31;

    float acc[4][4];
    #pragma unroll
    for (int i = 0; i < 4; i++)
        #pragma unroll
        for (int j = 0; j < 4; j++) acc[i][j] = 0.f;

    for (int fc = 0; fc < NF; fc += 32) {
        #pragma unroll
        for (int r = 0; r < 8; r++) {
            int mm = lr + r*8;
            As[mm][lc] = g_V[(size_t)(m0 + mm)*NF + fc + lc];
            Ws[mm][lc] = W[(size_t)(o0 + mm)*NF + fc + lc];
        }
        __syncthreads();
        #pragma unroll
        for (int ff = 0; ff < 32; ff++) {
            float a[4], w[4];
            #pragma unroll
            for (int i = 0; i < 4; i++) a[i] = As[tx*4 + i][ff];
            #pragma unroll
            for (int j = 0; j < 4; j++) w[j] = Ws[ty*4 + j][ff];
            #pragma unroll
            for (int i = 0; i < 4; i++)
                #pragma unroll
                for (int j = 0; j < 4; j++)
                    acc[i][j] = fmaf(a[i], w[j], acc[i][j]);
        }
        __syncthreads();
    }
    #pragma unroll
    for (int j = 0; j < 4; j++) {
        float bj = bias[o0 + ty*4 + j];
        #pragma unroll
        for (int i = 0; i < 4; i++) {
            float v = acc[i][j] + bj;
            v = (v >= 0.f) ? v : 0.01f * v;
            out[(size_t)(m0 + tx*4 + i)*NDOUT + o0 + ty*4 + j] = v;
        }
    }
}

// write kl scalar(s) after the out tensor
__global__ void finalize_kernel(float* __restrict__ out, int out_size)
{
    int i = OUT_ELEMS + blockIdx.x * blockDim.x + threadIdx.x;
    if (i < out_size) out[i] = __fmul_rn(100.0f, (float)g_kl);
}

// ------------------------------------------------------------------
extern "C" void kernel_launch(void* const* d_in, const int* in_sizes, int n_in,
                              void* d_out, int out_size)
{
    const float* Q      = (const float*)d_in[0];
    const float* keys   = (const float*)d_in[1];
    const float* conv_w = (const float*)d_in[2];
    const float* lin_w  = (const float*)d_in[3];
    const float* lin_b  = (const float*)d_in[4];
    const int*   mask   = (const int*)d_in[5];
    float* out = (float*)d_out;

    // smem: Qs 32768 + Sacc 65664 + max(kbuf 98304, Ctmp 65664) + 512
    const int smem = (32*256 + 32*SP + 3*2048*4 + 4*32) * (int)sizeof(float);
    cudaFuncSetAttribute(scores_kernel, cudaFuncAttributeMaxDynamicSharedMemorySize, smem);

    init_kernel<<<1, 32>>>();                      // my #0
    k2_kernel<<<(NH*NK)/8, 256>>>(keys);           // my #1
    dummy_kernel<<<1, 32>>>();                     // my #2
    scores_kernel<<<dim3(NN/32, NB), 512, smem>>>(Q, keys, conv_w, mask); // my #3 = ncu slot 5
    cn_kernel<<<(NB*NK)/256, 256>>>();
    kl_kernel<<<(NB*NN)/8, 256>>>();
    v_kernel<<<dim3(NK/64, NF/64, NB), 256>>>(Q);
    out_kernel<<<dim3((NB*NK)/64, NDOUT/64), 256>>>(lin_w, lin_b, out);

    int extra = out_size - OUT_ELEMS;
    if (extra > 0)
        finalize_kernel<<<(extra + 255)/256, 256>>>(out, out_size);
}

// round 13
// speedup vs baseline: 2.4807x; 1.8788x over previous
#include <cuda_runtime.h>
#include <cuda_bf16.h>
#include <cstdint>

#define NB   16
#define NN   1024
#define NF   256
#define NH   8
#define NK   512
#define NDOUT 256
#define EPSF 1e-8f
#define OUT_ELEMS (NB*NK*NDOUT)
#define SP   513   // padded row stride
#define QW   132   // Qhi/Qlo row stride in u32 (264 bf16 = conflict-free)

typedef unsigned long long u64;

// packed fp32x2 FMA (kept for v_kernel)
#define FMA2(acc, a, b) \
    asm("fma.rn.f32x2 %0, %1, %2, %0;" : "+l"(acc) : "l"(a), "l"(b))

// m16n8k16 bf16 MMA, fp32 accumulate in place
__device__ __forceinline__ void mma_bf16(
    float& d0, float& d1, float& d2, float& d3,
    unsigned a0, unsigned a1, unsigned a2, unsigned a3,
    unsigned b0, unsigned b1)
{
    asm volatile(
        "mma.sync.aligned.m16n8k16.row.col.f32.bf16.bf16.f32 "
        "{%0,%1,%2,%3}, {%4,%5,%6,%7}, {%8,%9}, {%0,%1,%2,%3};"
        : "+f"(d0), "+f"(d1), "+f"(d2), "+f"(d3)
        : "r"(a0), "r"(a1), "r"(a2), "r"(a3), "r"(b0), "r"(b1));
}

// ---- scratch ----
__device__ float  g_C[(size_t)NB*NN*NK];    // 32 MB
__device__ float  g_V[(size_t)NB*NK*NF];    // 8 MB
__device__ float  g_cnf[NB*NK];
__device__ float  g_k2[NH*NK];
__device__ double g_kl;
// keys split into bf16 hi/lo, layout [h][fchunk 16][seg 2][k 512][f 8]
__device__ __nv_bfloat16 g_khi[(size_t)NH*NK*NF];
__device__ __nv_bfloat16 g_klo[(size_t)NH*NK*NF];

// ------------------------------------------------------------------
// exp(x) for x in [-0.125, 0], float-float, ~1e-11 accurate.
__device__ __forceinline__ float exp_small(float x) {
    if (x < -0.125f) return (float)exp((double)x);   // rare fallback
    float x2h = __fmul_rn(x, x);
    float x2l = fmaf(x, x, -x2h);
    float U = fmaf(x, fmaf(x, fmaf(x, fmaf(x, 1.f/5040.f, 1.f/720.f),
                                   1.f/120.f), 1.f/24.f), 1.f/6.f);
    float tail = fmaf(__fmul_rn(x2h, x), U, 0.5f*x2l);
    float sh = __fadd_rn(1.f, x);
    float sl = __fadd_rn(__fsub_rn(1.f, sh), x);
    float b  = 0.5f*x2h;
    float th = __fadd_rn(sh, b);
    float tl = __fadd_rn(__fsub_rn(sh, th), b);
    return __fadd_rn(th, __fadd_rn(__fadd_rn(tl, sl), tail));
}

// log(y) for y ~ 1/512*(1 +- 0.06), float-float, ~1e-11 accurate.
__device__ __forceinline__ float log_near(float y) {
    const double LN512 = 6.2383246250395078;
    const float LH = (float)LN512;
    const float LL = (float)(LN512 - (double)LH);
    float u = __fmul_rn(y, 512.f);
    float w = __fsub_rn(u, 1.f);
    if (fabsf(w) > 0.0625f) return (float)log((double)y);  // rare fallback
    float w2h = __fmul_rn(w, w);
    float w2l = fmaf(w, w, -w2h);
    float V = fmaf(w, fmaf(w, fmaf(w, fmaf(w, fmaf(w, -1.f/8.f, 1.f/7.f),
                                   -1.f/6.f), 1.f/5.f), -1.f/4.f), 1.f/3.f);
    float tail = fmaf(__fmul_rn(w2h, w), V, -0.5f*w2l);
    float b  = -0.5f*w2h;
    float sh = __fadd_rn(w, b);
    float sl = __fadd_rn(__fsub_rn(w, sh), b);
    float th = __fadd_rn(sh, -LH);
    float tl = __fadd_rn(__fsub_rn(-LH, th), sh);
    return __fadd_rn(th, __fsub_rn(__fadd_rn(__fadd_rn(tl, sl), tail), LL));
}

// ------------------------------------------------------------------
__global__ void init_kernel() {
    if (blockIdx.x == 0 && threadIdx.x == 0) g_kl = 0.0;
}

// ||keys[h][k]||^2 : warp per row (fp32 source, unchanged)
__global__ void k2_kernel(const float* __restrict__ keys) {
    int warp = threadIdx.x >> 5, lane = threadIdx.x & 31;
    int row = blockIdx.x * 8 + warp;           // < NH*NK = 4096
    const float4* kr = (const float4*)(keys + (size_t)row * NF);
    float s = 0.f;
    #pragma unroll
    for (int j = lane; j < 64; j += 32) {
        float4 v = kr[j];
        s += v.x*v.x + v.y*v.y + v.z*v.z + v.w*v.w;
    }
    #pragma unroll
    for (int o = 16; o; o >>= 1) s += __shfl_xor_sync(0xffffffffu, s, o);
    if (!lane) g_k2[row] = s;
}

// keys -> bf16 hi/lo split, staged layout [h][fc][seg][k][8f]
__global__ void __launch_bounds__(256) prep_keys(const float* __restrict__ keys)
{
    int gid = blockIdx.x * 256 + threadIdx.x;   // < 8*16*2*512 = 131072
    int k   = gid & 511;
    int seg = (gid >> 9) & 1;
    int fc  = (gid >> 10) & 15;
    int h   = gid >> 14;
    const float* src = keys + ((size_t)(h*NK + k))*NF + fc*16 + seg*8;
    __nv_bfloat16* dhi = g_khi + (size_t)gid*8;
    __nv_bfloat16* dlo = g_klo + (size_t)gid*8;
    #pragma unroll
    for (int j = 0; j < 8; j++) {
        float x = src[j];
        __nv_bfloat16 hi = __float2bfloat16_rn(x);
        __nv_bfloat16 lo =
            __float2bfloat16_rn(__fsub_rn(x, __bfloat162float(hi)));
        dhi[j] = hi; dlo[j] = lo;
    }
}

// ------------------------------------------------------------------
// cp.async one chunk of THIS WARP's private key slice (32 k rows x 16 f,
// hi+lo) into stage chunk%3. Slice: kbuf + ((st*16+w)*2+t)*1024 bytes,
// inner layout [seg 2][32 k][8 f] bf16 (512B per seg).
__device__ __forceinline__ void issue_slice(
    float* kbuf, int h, int chunk, int w, int lane)
{
    const int st = chunk % 3;
    char* dstbase = (char*)kbuf + (size_t)((st*16 + w)*2)*1024;
    #pragma unroll
    for (int i = 0; i < 4; i++) {
        int t = i >> 1, seg = i & 1;
        const __nv_bfloat16* src = (t ? g_klo : g_khi)
            + ((size_t)(((h*16 + chunk)*2 + seg)*512) + 32*w + lane)*8;
        char* dst = dstbase + t*1024 + seg*512 + lane*16;
        unsigned d = (unsigned)__cvta_generic_to_shared(dst);
        asm volatile("cp.async.ca.shared.global [%0], [%1], 16;"
                     :: "r"(d), "l"(src));
    }
    asm volatile("cp.async.commit_group;");
}

// ------------------------------------------------------------------
// Fused scores kernel: tensor-core qk (bf16 3-product, fp32 accum),
// per-warp-private key slices (NO sync in GEMM loop), frozen epilogue.
// Warp w owns k in [32w, 32w+32), all 32 n rows (2 m-tiles x 4 k-tiles).
__global__ void __launch_bounds__(512, 1) scores_kernel(
    const float* __restrict__ Q, const float* __restrict__ conv_w,
    const int* __restrict__ mask)
{
    extern __shared__ float sm[];
    float* QsU  = sm;                      // 8704 floats: fp32 Q then Qhi/Qlo
    float* Sacc = sm + 8704;               // 32*SP
    float* kbuf = Sacc + 32*SP;            // 24576 floats (96KB, 3 stages)
    float* Ctmp = kbuf;                    // alias (disjoint phases)
    float* k2s  = kbuf + 24576;            // 512
    float* rowv = k2s + 512;               // 32
    float* q2s  = rowv + 32;               // 32
    float* mxs  = q2s + 32;                // 32
    float* msk  = mxs + 32;                // 32

    const int tid  = threadIdx.x;
    const int lane = tid & 31, warp = tid >> 5;
    const int g = lane >> 2, c = lane & 3;     // mma group/quad ids
    const int b  = blockIdx.y;
    const int n0 = blockIdx.x * 32;
    const int k  = tid;                        // softmax/C phases

    // --- load Q tile (fp32) + mask, zero Sacc ---
    float* Qs = QsU;   // fp32 view, row stride 256
    const float4* Qg = (const float4*)(Q + ((size_t)b*NN + n0)*NF);
    float4* Qs4 = (float4*)Qs;
    #pragma unroll
    for (int i = tid; i < 32*64; i += 512) Qs4[i] = Qg[i];
    if (tid < 32) msk[tid] = (float)mask[b*NN + n0 + tid];
    #pragma unroll
    for (int n = 0; n < 32; n++) Sacc[n*SP + k] = 0.f;
    __syncthreads();

    // --- q2 per row (fp32, unchanged) ---
    #pragma unroll
    for (int r = 0; r < 2; r++) {
        int n = warp*2 + r;
        float s = 0.f;
        #pragma unroll
        for (int j = 0; j < 8; j++) {
            float v = Qs[n*256 + lane + 32*j];
            s = __fadd_rn(s, __fmul_rn(v, v));
        }
        #pragma unroll
        for (int o = 16; o; o >>= 1)
            s = __fadd_rn(s, __shfl_xor_sync(0xffffffffu, s, o));
        if (!lane) q2s[n] = s;
    }

    // --- convert Q fp32 -> bf16 hi/lo in place (buffer in regs) ---
    float vals[16];
    #pragma unroll
    for (int j = 0; j < 16; j++) vals[j] = Qs[tid + 512*j];
    __syncthreads();   // all fp32 reads (incl q2) done before overwrite
    {
        __nv_bfloat16* Qhb = (__nv_bfloat16*)QsU;
        __nv_bfloat16* Qlb = Qhb + 8448;   // 32*264
        #pragma unroll
        for (int j = 0; j < 16; j++) {
            int idx = tid + 512*j;
            int n = idx >> 8, f = idx & 255;
            __nv_bfloat16 hi = __float2bfloat16_rn(vals[j]);
            __nv_bfloat16 lo = __float2bfloat16_rn(
                __fsub_rn(vals[j], __bfloat162float(hi)));
            Qhb[n*264 + f] = hi;
            Qlb[n*264 + f] = lo;
        }
    }
    __syncthreads();

    const unsigned* QhiU = (const unsigned*)QsU;
    const unsigned* QloU = QhiU + 4224;    // 16896B / 4

    for (int h = 0; h < NH; h++) {
        __syncthreads();   // Ctmp (alias of kbuf) reads done; k2s reusable
        k2s[tid] = g_k2[h*NK + tid];

        float d[2][4][4];
        #pragma unroll
        for (int mt = 0; mt < 2; mt++)
            #pragma unroll
            for (int kt = 0; kt < 4; kt++)
                #pragma unroll
                for (int e = 0; e < 4; e++) d[mt][kt][e] = 0.f;

        issue_slice(kbuf, h, 0, warp, lane);
        issue_slice(kbuf, h, 1, warp, lane);

        #pragma unroll 1
        for (int chunk = 0; chunk < 16; chunk++) {
            if (chunk + 1 < 16)
                asm volatile("cp.async.wait_group 1;");
            else
                asm volatile("cp.async.wait_group 0;");
            __syncwarp();
            if (chunk + 2 < 16)
                issue_slice(kbuf, h, chunk + 2, warp, lane);

            // A fragments (Q hi/lo) for both m-tiles, this f-chunk
            unsigned ah[2][4], al[2][4];
            #pragma unroll
            for (int mt = 0; mt < 2; mt++) {
                int r0 = (mt*16 + g)*QW + chunk*8 + c;
                int r1 = (mt*16 + g + 8)*QW + chunk*8 + c;
                ah[mt][0] = QhiU[r0];     ah[mt][1] = QhiU[r1];
                ah[mt][2] = QhiU[r0 + 4]; ah[mt][3] = QhiU[r1 + 4];
                al[mt][0] = QloU[r0];     al[mt][1] = QloU[r1];
                al[mt][2] = QloU[r0 + 4]; al[mt][3] = QloU[r1 + 4];
            }

            const unsigned* BhiU = (const unsigned*)
                ((char*)kbuf + (size_t)(((chunk%3)*16 + warp)*2)*1024);
            const unsigned* BloU = BhiU + 256;   // +1024B

            #pragma unroll
            for (int kt = 0; kt < 4; kt++) {
                int bo = (kt*8 + g)*4 + c;
                unsigned bh0 = BhiU[bo], bh1 = BhiU[128 + bo];
                unsigned bl0 = BloU[bo], bl1 = BloU[128 + bo];
                #pragma unroll
                for (int mt = 0; mt < 2; mt++) {
                    mma_bf16(d[mt][kt][0], d[mt][kt][1],
                             d[mt][kt][2], d[mt][kt][3],
                             ah[mt][0], ah[mt][1], ah[mt][2], ah[mt][3],
                             bh0, bh1);
                    mma_bf16(d[mt][kt][0], d[mt][kt][1],
                             d[mt][kt][2], d[mt][kt][3],
                             ah[mt][0], ah[mt][1], ah[mt][2], ah[mt][3],
                             bl0, bl1);
                    mma_bf16(d[mt][kt][0], d[mt][kt][1],
                             d[mt][kt][2], d[mt][kt][3],
                             al[mt][0], al[mt][1], al[mt][2], al[mt][3],
                             bh0, bh1);
                }
            }
        }
        __syncthreads();   // all warps' GEMM done before Ctmp (alias) writes

        // d2 = (q2+k2) - 2*qk; cv = 1/(1 + sqrt(max(d2,0))^2)  (frozen ops)
        #pragma unroll
        for (int mt = 0; mt < 2; mt++)
            #pragma unroll
            for (int kt = 0; kt < 4; kt++)
                #pragma unroll
                for (int e = 0; e < 4; e++) {
                    int n  = mt*16 + g + ((e & 2) ? 8 : 0);
                    int kx = 32*warp + kt*8 + 2*c + (e & 1);
                    float qk = d[mt][kt][e];
                    float d2 = __fsub_rn(__fadd_rn(q2s[n], k2s[kx]),
                                         __fmul_rn(2.0f, qk));
                    float t  = sqrtf(fmaxf(d2, 0.0f));
                    float cv = __fdiv_rn(1.0f,
                                 __fadd_rn(1.0f, __fmul_rn(t, t)));
                    d[mt][kt][e] = cv;          // keep c in regs
                    Ctmp[n*SP + kx] = cv;
                }
        __syncthreads();

        // rowsum over k: PARALLEL reduction (order-insensitive)
        #pragma unroll
        for (int r = 0; r < 2; r++) {
            int n = warp*2 + r;
            float s = 0.f;
            #pragma unroll
            for (int j = 0; j < 16; j++)
                s = __fadd_rn(s, Ctmp[n*SP + lane + 32*j]);
            #pragma unroll
            for (int o = 16; o; o >>= 1)
                s = __fadd_rn(s, __shfl_xor_sync(0xffffffffu, s, o));
            if (!lane) rowv[n] = s;
        }
        __syncthreads();

        // logits += cw * ((c / rowsum) * msk), ascending h (frozen ops)
        const float cw = conv_w[h];
        #pragma unroll
        for (int mt = 0; mt < 2; mt++)
            #pragma unroll
            for (int kt = 0; kt < 4; kt++)
                #pragma unroll
                for (int e = 0; e < 4; e++) {
                    int n  = mt*16 + g + ((e & 2) ? 8 : 0);
                    int kx = 32*warp + kt*8 + 2*c + (e & 1);
                    float cdiv = __fdiv_rn(d[mt][kt][e], rowv[n]);
                    float term = __fmul_rn(cw, __fmul_rn(cdiv, msk[n]));
                    Sacc[n*SP + kx] = __fadd_rn(Sacc[n*SP + kx], term);
                }
    }
    __syncthreads();

    // softmax: row max
    #pragma unroll
    for (int r = 0; r < 2; r++) {
        int n = warp*2 + r;
        float mx = -3.402823466e38f;
        #pragma unroll
        for (int j = 0; j < 16; j++)
            mx = fmaxf(mx, Sacc[n*SP + lane + 32*j]);
        #pragma unroll
        for (int o = 16; o; o >>= 1)
            mx = fmaxf(mx, __shfl_xor_sync(0xffffffffu, mx, o));
        if (!lane) mxs[n] = mx;
    }
    __syncthreads();
    // e = exp(x - mx), correctly-rounded-grade (FROZEN)
    #pragma unroll
    for (int n = 0; n < 32; n++) {
        float x = __fsub_rn(Sacc[n*SP + k], mxs[n]);
        Sacc[n*SP + k] = exp_small(x);
    }
    __syncthreads();
    // denominator: strict sequential ascending fp32 (FROZEN order)
    if (tid < 32) {
        const float* row = &Sacc[tid*SP];
        float s = 0.f;
        #pragma unroll 8
        for (int j = 0; j < NK; j++)
            s = __fadd_rn(s, row[j]);
        rowv[tid] = s;
    }
    __syncthreads();

    // C = (e / s) * msk
    float* Cout = g_C + ((size_t)b*NN + n0)*NK + k;
    #pragma unroll
    for (int n = 0; n < 32; n++)
        Cout[(size_t)n*NK] = __fmul_rn(__fdiv_rn(Sacc[n*SP + k], rowv[n]), msk[n]);
}

// ------------------------------------------------------------------
// cn[b][k] = strict sequential ascending fp32 sum over n (FROZEN)
__global__ void __launch_bounds__(256) cn_kernel()
{
    int id = blockIdx.x * blockDim.x + threadIdx.x;   // < NB*NK
    int b = id >> 9, kk = id & 511;
    const float* base = g_C + ((size_t)b*NN)*NK + kk;
    float s = 0.f;
    #pragma unroll 8
    for (int n = 0; n < NN; n++)
        s = __fadd_rn(s, base[(size_t)n*NK]);
    g_cnf[id] = s;
}

// ------------------------------------------------------------------
// KL: warp per (b,n) row. Sequential fp32 pn (FROZEN); float-float logs.
__global__ void __launch_bounds__(256) kl_kernel()
{
    __shared__ float cbuf[8][SP];
    __shared__ float pbuf[8][SP];
    const int warp = threadIdx.x >> 5, lane = threadIdx.x & 31;
    const int row = blockIdx.x * 8 + warp;   // < NB*NN
    const int b = row >> 10;
    const float* crow = g_C + (size_t)row * NK;
    const float* cnb = g_cnf + b*NK;

    #pragma unroll
    for (int j = 0; j < 16; j++) {
        int kk = lane + 32*j;
        float c = crow[kk];
        float cnf = __fadd_rn(cnb[kk], EPSF);
        float p = __fdiv_rn(__fmul_rn(c, c), cnf);
        cbuf[warp][kk] = c;
        pbuf[warp][kk] = p;
    }
    __syncwarp();
    if (!lane) {
        float pn = 0.f;
        const float* prow = pbuf[warp];
        #pragma unroll 8
        for (int j = 0; j < NK; j++)
            pn = __fadd_rn(pn, prow[j]);
        pbuf[warp][512] = __fadd_rn(pn, EPSF);
    }
    __syncwarp();
    const float pnf = pbuf[warp][512];

    double t = 0.0;
    #pragma unroll
    for (int j = 0; j < 16; j++) {
        int kk = lane + 32*j;
        float pv = pbuf[warp][kk];
        if (pv != 0.f) {
            float P  = __fdiv_rn(pv, pnf);
            float la = log_near(__fadd_rn(P, EPSF));
            float lb = log_near(__fadd_rn(cbuf[warp][kk], EPSF));
            t += (double)__fmul_rn(P, __fsub_rn(la, lb));
        }
    }
    #pragma unroll
    for (int o = 16; o; o >>= 1) t += __shfl_xor_sync(0xffffffffu, t, o);
    if (!lane) atomicAdd(&g_kl, t);
}

// ------------------------------------------------------------------
// V[b][k][f] = sum_n C[b][n][k] * Q[b][n][f] ; 64x64 tile, packed f32x2
__global__ void __launch_bounds__(256) v_kernel(const float* __restrict__ Q)
{
    const int b = blockIdx.z;
    const int k0 = blockIdx.x * 64, f0 = blockIdx.y * 64;
    __shared__ __align__(16) float As[32][64];
    __shared__ __align__(16) float Bs[32][64];
    const int tid = threadIdx.x;
    const int tx = tid & 15, ty = tid >> 4;
    const int lr = tid >> 6, lc = tid & 63;

    u64 acc2[4][2];
    #pragma unroll
    for (int i = 0; i < 4; i++) { acc2[i][0] = 0ull; acc2[i][1] = 0ull; }

    for (int n0 = 0; n0 < NN; n0 += 32) {
        #pragma unroll
        for (int r = 0; r < 8; r++) {
            int nn = lr + r*4;
            As[nn][lc] = g_C[((size_t)b*NN + n0 + nn)*NK + k0 + lc];
            Bs[nn][lc] = Q[((size_t)b*NN + n0 + nn)*NF + f0 + lc];
        }
        __syncthreads();
        #pragma unroll
        for (int nn = 0; nn < 32; nn++) {
            const u64* Brow = (const u64*)&Bs[nn][ty*4];
            u64 b0 = Brow[0], b1 = Brow[1];
            #pragma unroll
            for (int i = 0; i < 4; i++) {
                unsigned ab = __float_as_uint(As[nn][tx*4 + i]);
                u64 ap;
                asm("mov.b64 %0, {%1, %1};" : "=l"(ap) : "r"(ab));
                FMA2(acc2[i][0], ap, b0);
                FMA2(acc2[i][1], ap, b1);
            }
        }
        __syncthreads();
    }
    #pragma unroll
    for (int i = 0; i < 4; i++)
        #pragma unroll
        for (int jp = 0; jp < 2; jp++) {
            unsigned lo, hi;
            asm("mov.b64 {%0, %1}, %2;" : "=r"(lo), "=r"(hi) : "l"(acc2[i][jp]));
            size_t base = ((size_t)b*NK + k0 + tx*4 + i)*NF + f0 + ty*4 + jp*2;
            g_V[base]     = __uint_as_float(lo);
            g_V[base + 1] = __uint_as_float(hi);
        }
}

// ------------------------------------------------------------------
// out[m][o] = lrelu( sum_f V[m][f]*W[o][f] + bias[o] )
__global__ void __launch_bounds__(256) out_kernel(
    const float* __restrict__ W, const float* __restrict__ bias,
    float* __restrict__ out)
{
    const int m0 = blockIdx.x * 64, o0 = blockIdx.y * 64;
    __shared__ float As[64][33];
    __shared__ float Ws[64][33];
    const int tid = threadIdx.x;
    const int tx = tid & 15, ty = tid >> 4;
    const int lr = tid >> 5, lc = tid & 31;

    float acc[4][4];
    #pragma unroll
    for (int i = 0; i < 4; i++)
        #pragma unroll
        for (int j = 0; j < 4; j++) acc[i][j] = 0.f;

    for (int fc = 0; fc < NF; fc += 32) {
        #pragma unroll
        for (int r = 0; r < 8; r++) {
            int mm = lr + r*8;
            As[mm][lc] = g_V[(size_t)(m0 + mm)*NF + fc + lc];
            Ws[mm][lc] = W[(size_t)(o0 + mm)*NF + fc + lc];
        }
        __syncthreads();
        #pragma unroll
        for (int ff = 0; ff < 32; ff++) {
            float a[4], w[4];
            #pragma unroll
            for (int i = 0; i < 4; i++) a[i] = As[tx*4 + i][ff];
            #pragma unroll
            for (int j = 0; j < 4; j++) w[j] = Ws[ty*4 + j][ff];
            #pragma unroll
            for (int i = 0; i < 4; i++)
                #pragma unroll
                for (int j = 0; j < 4; j++)
                    acc[i][j] = fmaf(a[i], w[j], acc[i][j]);
        }
        __syncthreads();
    }
    #pragma unroll
    for (int j = 0; j < 4; j++) {
        float bj = bias[o0 + ty*4 + j];
        #pragma unroll
        for (int i = 0; i < 4; i++) {
            float v = acc[i][j] + bj;
            v = (v >= 0.f) ? v : 0.01f * v;
            out[(size_t)(m0 + tx*4 + i)*NDOUT + o0 + ty*4 + j] = v;
        }
    }
}

// write kl scalar(s) after the out tensor
__global__ void finalize_kernel(float* __restrict__ out, int out_size)
{
    int i = OUT_ELEMS + blockIdx.x * blockDim.x + threadIdx.x;
    if (i < out_size) out[i] = __fmul_rn(100.0f, (float)g_kl);
}

// ------------------------------------------------------------------
extern "C" void kernel_launch(void* const* d_in, const int* in_sizes, int n_in,
                              void* d_out, int out_size)
{
    const float* Q      = (const float*)d_in[0];
    const float* keys   = (const float*)d_in[1];
    const float* conv_w = (const float*)d_in[2];
    const float* lin_w  = (const float*)d_in[3];
    const float* lin_b  = (const float*)d_in[4];
    const int*   mask   = (const int*)d_in[5];
    float* out = (float*)d_out;

    // smem: QsU 34816 + Sacc 65664 + kbuf 98304 + k2s 2048 + misc 512
    const int smem = (8704 + 32*SP + 24576 + 512 + 4*32) * (int)sizeof(float);
    cudaFuncSetAttribute(scores_kernel, cudaFuncAttributeMaxDynamicSharedMemorySize, smem);

    init_kernel<<<1, 32>>>();                      // my #0
    k2_kernel<<<(NH*NK)/8, 256>>>(keys);           // my #1
    prep_keys<<<512, 256>>>(keys);                 // my #2
    scores_kernel<<<dim3(NN/32, NB), 512, smem>>>(Q, conv_w, mask); // my #3 = ncu slot 5
    cn_kernel<<<(NB*NK)/256, 256>>>();
    kl_kernel<<<(NB*NN)/8, 256>>>();
    v_kernel<<<dim3(NK/64, NF/64, NB), 256>>>(Q);
    out_kernel<<<dim3((NB*NK)/64, NDOUT/64), 256>>>(lin_w, lin_b, out);

    int extra = out_size - OUT_ELEMS;
    if (extra > 0)
        finalize_kernel<<<(extra + 255)/256, 256>>>(out, out_size);
}

// round 14
// speedup vs baseline: 2.7094x; 1.0922x over previous
#include <cuda_runtime.h>
#include <cuda_bf16.h>
#include <cstdint>

#define NB   16
#define NN   1024
#define NF   256
#define NH   8
#define NK   512
#define NDOUT 256
#define EPSF 1e-8f
#define OUT_ELEMS (NB*NK*NDOUT)
#define SP   513   // padded row stride
#define QW   132   // Qhi/Qlo row stride in u32 (264 bf16 = conflict-free)

typedef unsigned long long u64;

// packed fp32x2 FMA (kept for v_kernel)
#define FMA2(acc, a, b) \
    asm("fma.rn.f32x2 %0, %1, %2, %0;" : "+l"(acc) : "l"(a), "l"(b))

// m16n8k16 bf16 MMA, fp32 accumulate in place
__device__ __forceinline__ void mma_bf16(
    float& d0, float& d1, float& d2, float& d3,
    unsigned a0, unsigned a1, unsigned a2, unsigned a3,
    unsigned b0, unsigned b1)
{
    asm volatile(
        "mma.sync.aligned.m16n8k16.row.col.f32.bf16.bf16.f32 "
        "{%0,%1,%2,%3}, {%4,%5,%6,%7}, {%8,%9}, {%0,%1,%2,%3};"
        : "+f"(d0), "+f"(d1), "+f"(d2), "+f"(d3)
        : "r"(a0), "r"(a1), "r"(a2), "r"(a3), "r"(b0), "r"(b1));
}

// ---- scratch ----
__device__ float  g_C[(size_t)NB*NN*NK];    // 32 MB
__device__ float  g_V[(size_t)NB*NK*NF];    // 8 MB
__device__ float  g_cnp[(size_t)NB*32*NK];  // per-block colsum partials (1MB)
__device__ float  g_cnf[NB*NK];
__device__ float  g_k2[NH*NK];
__device__ double g_kl;
// keys split into bf16 hi/lo, layout [h][fchunk 16][seg 2][k 512][f 8]
__device__ __nv_bfloat16 g_khi[(size_t)NH*NK*NF];
__device__ __nv_bfloat16 g_klo[(size_t)NH*NK*NF];

// ------------------------------------------------------------------
// exp(x) for x in [-0.125, 0], float-float, ~1e-11 accurate.
__device__ __forceinline__ float exp_small(float x) {
    if (x < -0.125f) return (float)exp((double)x);   // rare fallback
    float x2h = __fmul_rn(x, x);
    float x2l = fmaf(x, x, -x2h);
    float U = fmaf(x, fmaf(x, fmaf(x, fmaf(x, 1.f/5040.f, 1.f/720.f),
                                   1.f/120.f), 1.f/24.f), 1.f/6.f);
    float tail = fmaf(__fmul_rn(x2h, x), U, 0.5f*x2l);
    float sh = __fadd_rn(1.f, x);
    float sl = __fadd_rn(__fsub_rn(1.f, sh), x);
    float b  = 0.5f*x2h;
    float th = __fadd_rn(sh, b);
    float tl = __fadd_rn(__fsub_rn(sh, th), b);
    return __fadd_rn(th, __fadd_rn(__fadd_rn(tl, sl), tail));
}

// log(y) for y ~ 1/512*(1 +- 0.06), float-float, ~1e-11 accurate.
__device__ __forceinline__ float log_near(float y) {
    const double LN512 = 6.2383246250395078;
    const float LH = (float)LN512;
    const float LL = (float)(LN512 - (double)LH);
    float u = __fmul_rn(y, 512.f);
    float w = __fsub_rn(u, 1.f);
    if (fabsf(w) > 0.0625f) return (float)log((double)y);  // rare fallback
    float w2h = __fmul_rn(w, w);
    float w2l = fmaf(w, w, -w2h);
    float V = fmaf(w, fmaf(w, fmaf(w, fmaf(w, fmaf(w, -1.f/8.f, 1.f/7.f),
                                   -1.f/6.f), 1.f/5.f), -1.f/4.f), 1.f/3.f);
    float tail = fmaf(__fmul_rn(w2h, w), V, -0.5f*w2l);
    float b  = -0.5f*w2h;
    float sh = __fadd_rn(w, b);
    float sl = __fadd_rn(__fsub_rn(w, sh), b);
    float th = __fadd_rn(sh, -LH);
    float tl = __fadd_rn(__fsub_rn(-LH, th), sh);
    return __fadd_rn(th, __fsub_rn(__fadd_rn(__fadd_rn(tl, sl), tail), LL));
}

// ------------------------------------------------------------------
__global__ void init_kernel() {
    if (blockIdx.x == 0 && threadIdx.x == 0) g_kl = 0.0;
}

// ||keys[h][k]||^2 : warp per row
__global__ void k2_kernel(const float* __restrict__ keys) {
    int warp = threadIdx.x >> 5, lane = threadIdx.x & 31;
    int row = blockIdx.x * 8 + warp;           // < NH*NK = 4096
    const float4* kr = (const float4*)(keys + (size_t)row * NF);
    float s = 0.f;
    #pragma unroll
    for (int j = lane; j < 64; j += 32) {
        float4 v = kr[j];
        s += v.x*v.x + v.y*v.y + v.z*v.z + v.w*v.w;
    }
    #pragma unroll
    for (int o = 16; o; o >>= 1) s += __shfl_xor_sync(0xffffffffu, s, o);
    if (!lane) g_k2[row] = s;
}

// keys -> bf16 hi/lo split, staged layout [h][fc][seg][k][8f]
__global__ void __launch_bounds__(256) prep_keys(const float* __restrict__ keys)
{
    int gid = blockIdx.x * 256 + threadIdx.x;   // < 131072
    int k   = gid & 511;
    int seg = (gid >> 9) & 1;
    int fc  = (gid >> 10) & 15;
    int h   = gid >> 14;
    const float* src = keys + ((size_t)(h*NK + k))*NF + fc*16 + seg*8;
    __nv_bfloat16* dhi = g_khi + (size_t)gid*8;
    __nv_bfloat16* dlo = g_klo + (size_t)gid*8;
    #pragma unroll
    for (int j = 0; j < 8; j++) {
        float x = src[j];
        __nv_bfloat16 hi = __float2bfloat16_rn(x);
        __nv_bfloat16 lo =
            __float2bfloat16_rn(__fsub_rn(x, __bfloat162float(hi)));
        dhi[j] = hi; dlo[j] = lo;
    }
}

// ------------------------------------------------------------------
// cp.async one chunk of THIS WARP's private key slice (32 k rows x 16 f,
// hi+lo) into stage chunk%3.
__device__ __forceinline__ void issue_slice(
    float* kbuf, int h, int chunk, int w, int lane)
{
    const int st = chunk % 3;
    char* dstbase = (char*)kbuf + (size_t)((st*16 + w)*2)*1024;
    #pragma unroll
    for (int i = 0; i < 4; i++) {
        int t = i >> 1, seg = i & 1;
        const __nv_bfloat16* src = (t ? g_klo : g_khi)
            + ((size_t)(((h*16 + chunk)*2 + seg)*512) + 32*w + lane)*8;
        char* dst = dstbase + t*1024 + seg*512 + lane*16;
        unsigned d = (unsigned)__cvta_generic_to_shared(dst);
        asm volatile("cp.async.ca.shared.global [%0], [%1], 16;"
                     :: "r"(d), "l"(src));
    }
    asm volatile("cp.async.commit_group;");
}

// ------------------------------------------------------------------
// Fused scores kernel: tensor-core qk (bf16 3-product), warp-private key
// slices (no sync in GEMM loop), register epilogue (no Ctmp), warp-partial
// deterministic rowsum, 2 block barriers per head, fused cn partials.
__global__ void __launch_bounds__(512, 1) scores_kernel(
    const float* __restrict__ Q, const float* __restrict__ conv_w,
    const int* __restrict__ mask)
{
    extern __shared__ float sm[];
    float* QsU  = sm;                      // 8704 floats: fp32 Q then Qhi/Qlo
    float* Sacc = sm + 8704;               // 32*SP
    float* kbuf = Sacc + 32*SP;            // 24576 floats (96KB, 3 stages)
    float* redw = kbuf + 24576;            // 16*32 rowsum partials
    float* rowv = redw + 512;              // 32
    float* q2s  = rowv + 32;               // 32
    float* mxs  = q2s + 32;                // 32
    float* msk  = mxs + 32;                // 32

    const int tid  = threadIdx.x;
    const int lane = tid & 31, warp = tid >> 5;
    const int g = lane >> 2, c = lane & 3;     // mma group/quad ids
    const int b  = blockIdx.y;
    const int n0 = blockIdx.x * 32;
    const int k  = tid;                        // softmax/C phases

    // --- load Q tile (fp32) + mask, zero Sacc ---
    float* Qs = QsU;
    const float4* Qg = (const float4*)(Q + ((size_t)b*NN + n0)*NF);
    float4* Qs4 = (float4*)Qs;
    #pragma unroll
    for (int i = tid; i < 32*64; i += 512) Qs4[i] = Qg[i];
    if (tid < 32) msk[tid] = (float)mask[b*NN + n0 + tid];
    #pragma unroll
    for (int n = 0; n < 32; n++) Sacc[n*SP + k] = 0.f;
    __syncthreads();

    // --- q2 per row (fp32, unchanged) ---
    #pragma unroll
    for (int r = 0; r < 2; r++) {
        int n = warp*2 + r;
        float s = 0.f;
        #pragma unroll
        for (int j = 0; j < 8; j++) {
            float v = Qs[n*256 + lane + 32*j];
            s = __fadd_rn(s, __fmul_rn(v, v));
        }
        #pragma unroll
        for (int o = 16; o; o >>= 1)
            s = __fadd_rn(s, __shfl_xor_sync(0xffffffffu, s, o));
        if (!lane) q2s[n] = s;
    }

    // --- convert Q fp32 -> bf16 hi/lo in place ---
    float vals[16];
    #pragma unroll
    for (int j = 0; j < 16; j++) vals[j] = Qs[tid + 512*j];
    __syncthreads();
    {
        __nv_bfloat16* Qhb = (__nv_bfloat16*)QsU;
        __nv_bfloat16* Qlb = Qhb + 8448;
        #pragma unroll
        for (int j = 0; j < 16; j++) {
            int idx = tid + 512*j;
            int n = idx >> 8, f = idx & 255;
            __nv_bfloat16 hi = __float2bfloat16_rn(vals[j]);
            __nv_bfloat16 lo = __float2bfloat16_rn(
                __fsub_rn(vals[j], __bfloat162float(hi)));
            Qhb[n*264 + f] = hi;
            Qlb[n*264 + f] = lo;
        }
    }
    __syncthreads();

    const unsigned* QhiU = (const unsigned*)QsU;
    const unsigned* QloU = QhiU + 4224;

    issue_slice(kbuf, 0, 0, warp, lane);
    issue_slice(kbuf, 0, 1, warp, lane);

    for (int h = 0; h < NH; h++) {
        float d[2][4][4];
        #pragma unroll
        for (int mt = 0; mt < 2; mt++)
            #pragma unroll
            for (int kt = 0; kt < 4; kt++)
                #pragma unroll
                for (int e = 0; e < 4; e++) d[mt][kt][e] = 0.f;

        #pragma unroll 1
        for (int chunk = 0; chunk < 16; chunk++) {
            if (chunk + 1 < 16)
                asm volatile("cp.async.wait_group 1;");
            else
                asm volatile("cp.async.wait_group 0;");
            __syncwarp();
            if (chunk + 2 < 16)
                issue_slice(kbuf, h, chunk + 2, warp, lane);

            unsigned ah[2][4], al[2][4];
            #pragma unroll
            for (int mt = 0; mt < 2; mt++) {
                int r0 = (mt*16 + g)*QW + chunk*8 + c;
                int r1 = (mt*16 + g + 8)*QW + chunk*8 + c;
                ah[mt][0] = QhiU[r0];     ah[mt][1] = QhiU[r1];
                ah[mt][2] = QhiU[r0 + 4]; ah[mt][3] = QhiU[r1 + 4];
                al[mt][0] = QloU[r0];     al[mt][1] = QloU[r1];
                al[mt][2] = QloU[r0 + 4]; al[mt][3] = QloU[r1 + 4];
            }

            const unsigned* BhiU = (const unsigned*)
                ((char*)kbuf + (size_t)(((chunk%3)*16 + warp)*2)*1024);
            const unsigned* BloU = BhiU + 256;

            #pragma unroll
            for (int kt = 0; kt < 4; kt++) {
                int bo = (kt*8 + g)*4 + c;
                unsigned bh0 = BhiU[bo], bh1 = BhiU[128 + bo];
                unsigned bl0 = BloU[bo], bl1 = BloU[128 + bo];
                #pragma unroll
                for (int mt = 0; mt < 2; mt++) {
                    mma_bf16(d[mt][kt][0], d[mt][kt][1],
                             d[mt][kt][2], d[mt][kt][3],
                             ah[mt][0], ah[mt][1], ah[mt][2], ah[mt][3],
                             bh0, bh1);
                    mma_bf16(d[mt][kt][0], d[mt][kt][1],
                             d[mt][kt][2], d[mt][kt][3],
                             ah[mt][0], ah[mt][1], ah[mt][2], ah[mt][3],
                             bl0, bl1);
                    mma_bf16(d[mt][kt][0], d[mt][kt][1],
                             d[mt][kt][2], d[mt][kt][3],
                             al[mt][0], al[mt][1], al[mt][2], al[mt][3],
                             bh0, bh1);
                }
            }
        }

        // prefetch next head's first two chunks under the epilogue
        if (h + 1 < NH) {
            issue_slice(kbuf, h + 1, 0, warp, lane);
            issue_slice(kbuf, h + 1, 1, warp, lane);
        }

        // d2 = (q2+k2) - 2*qk; cv = 1/(1 + sqrt(max(d2,0))^2)  (frozen ops)
        float k2r[4][2];
        {
            const float* k2p = g_k2 + h*NK + 32*warp + 2*c;
            #pragma unroll
            for (int kt = 0; kt < 4; kt++) {
                k2r[kt][0] = __ldg(k2p + kt*8);
                k2r[kt][1] = __ldg(k2p + kt*8 + 1);
            }
        }
        #pragma unroll
        for (int mt = 0; mt < 2; mt++)
            #pragma unroll
            for (int kt = 0; kt < 4; kt++)
                #pragma unroll
                for (int e = 0; e < 4; e++) {
                    int n  = mt*16 + g + ((e & 2) ? 8 : 0);
                    float qk = d[mt][kt][e];
                    float d2 = __fsub_rn(__fadd_rn(q2s[n], k2r[kt][e & 1]),
                                         __fmul_rn(2.0f, qk));
                    float t  = sqrtf(fmaxf(d2, 0.0f));
                    d[mt][kt][e] = __fdiv_rn(1.0f,
                                     __fadd_rn(1.0f, __fmul_rn(t, t)));
                }

        // warp-partial rowsum (deterministic; order-insensitive quantity)
        #pragma unroll
        for (int mt = 0; mt < 2; mt++)
            #pragma unroll
            for (int e2 = 0; e2 < 2; e2++) {
                float s = 0.f;
                #pragma unroll
                for (int kt = 0; kt < 4; kt++) {
                    s = __fadd_rn(s, d[mt][kt][2*e2]);
                    s = __fadd_rn(s, d[mt][kt][2*e2 + 1]);
                }
                s = __fadd_rn(s, __shfl_xor_sync(0xffffffffu, s, 1));
                s = __fadd_rn(s, __shfl_xor_sync(0xffffffffu, s, 2));
                if (c == 0)
                    redw[warp*32 + mt*16 + 8*e2 + g] = s;
            }
        __syncthreads();
        if (tid < 32) {
            float s = 0.f;
            #pragma unroll
            for (int w = 0; w < 16; w++)
                s = __fadd_rn(s, redw[w*32 + tid]);
            rowv[tid] = s;
        }
        __syncthreads();

        // logits += cw * ((c / rowsum) * msk), ascending h (frozen ops)
        const float cw = conv_w[h];
        #pragma unroll
        for (int mt = 0; mt < 2; mt++)
            #pragma unroll
            for (int kt = 0; kt < 4; kt++)
                #pragma unroll
                for (int e = 0; e < 4; e++) {
                    int n  = mt*16 + g + ((e & 2) ? 8 : 0);
                    int kx = 32*warp + kt*8 + 2*c + (e & 1);
                    float cdiv = __fdiv_rn(d[mt][kt][e], rowv[n]);
                    float term = __fmul_rn(cw, __fmul_rn(cdiv, msk[n]));
                    Sacc[n*SP + kx] = __fadd_rn(Sacc[n*SP + kx], term);
                }
    }
    __syncthreads();

    // softmax: row max
    #pragma unroll
    for (int r = 0; r < 2; r++) {
        int n = warp*2 + r;
        float mx = -3.402823466e38f;
        #pragma unroll
        for (int j = 0; j < 16; j++)
            mx = fmaxf(mx, Sacc[n*SP + lane + 32*j]);
        #pragma unroll
        for (int o = 16; o; o >>= 1)
            mx = fmaxf(mx, __shfl_xor_sync(0xffffffffu, mx, o));
        if (!lane) mxs[n] = mx;
    }
    __syncthreads();
    // e = exp(x - mx), correctly-rounded-grade (FROZEN)
    #pragma unroll
    for (int n = 0; n < 32; n++) {
        float x = __fsub_rn(Sacc[n*SP + k], mxs[n]);
        Sacc[n*SP + k] = exp_small(x);
    }
    __syncthreads();
    // denominator: strict sequential ascending fp32 (FROZEN order)
    if (tid < 32) {
        const float* row = &Sacc[tid*SP];
        float s = 0.f;
        #pragma unroll 8
        for (int j = 0; j < NK; j++)
            s = __fadd_rn(s, row[j]);
        rowv[tid] = s;
    }
    __syncthreads();

    // C = (e / s) * msk; fused sequential-ascending colsum partial
    float* Cout = g_C + ((size_t)b*NN + n0)*NK + k;
    float cs = 0.f;
    #pragma unroll
    for (int n = 0; n < 32; n++) {
        float cvv = __fmul_rn(__fdiv_rn(Sacc[n*SP + k], rowv[n]), msk[n]);
        Cout[(size_t)n*NK] = cvv;
        cs = __fadd_rn(cs, cvv);
    }
    g_cnp[((size_t)b*32 + blockIdx.x)*NK + k] = cs;
}

// ------------------------------------------------------------------
// cn[b][k] = sum of 32 block partials, ascending block order (matches
// strict ascending-n grouping; cn is order-insensitive in kl anyway)
__global__ void __launch_bounds__(256) cn_kernel()
{
    int id = blockIdx.x * blockDim.x + threadIdx.x;   // < NB*NK
    int b = id >> 9, kk = id & 511;
    const float* p = g_cnp + ((size_t)b*32)*NK + kk;
    float s = 0.f;
    #pragma unroll
    for (int j = 0; j < 32; j++)
        s = __fadd_rn(s, p[(size_t)j*NK]);
    g_cnf[id] = s;
}

// ------------------------------------------------------------------
// KL: warp per (b,n) row. Sequential fp32 pn (FROZEN); float-float logs.
__global__ void __launch_bounds__(256) kl_kernel()
{
    __shared__ float cbuf[8][SP];
    __shared__ float pbuf[8][SP];
    const int warp = threadIdx.x >> 5, lane = threadIdx.x & 31;
    const int row = blockIdx.x * 8 + warp;   // < NB*NN
    const int b = row >> 10;
    const float* crow = g_C + (size_t)row * NK;
    const float* cnb = g_cnf + b*NK;

    #pragma unroll
    for (int j = 0; j < 16; j++) {
        int kk = lane + 32*j;
        float c = crow[kk];
        float cnf = __fadd_rn(cnb[kk], EPSF);
        float p = __fdiv_rn(__fmul_rn(c, c), cnf);
        cbuf[warp][kk] = c;
        pbuf[warp][kk] = p;
    }
    __syncwarp();
    if (!lane) {
        float pn = 0.f;
        const float* prow = pbuf[warp];
        #pragma unroll 8
        for (int j = 0; j < NK; j++)
            pn = __fadd_rn(pn, prow[j]);
        pbuf[warp][512] = __fadd_rn(pn, EPSF);
    }
    __syncwarp();
    const float pnf = pbuf[warp][512];

    double t = 0.0;
    #pragma unroll
    for (int j = 0; j < 16; j++) {
        int kk = lane + 32*j;
        float pv = pbuf[warp][kk];
        if (pv != 0.f) {
            float P  = __fdiv_rn(pv, pnf);
            float la = log_near(__fadd_rn(P, EPSF));
            float lb = log_near(__fadd_rn(cbuf[warp][kk], EPSF));
            t += (double)__fmul_rn(P, __fsub_rn(la, lb));
        }
    }
    #pragma unroll
    for (int o = 16; o; o >>= 1) t += __shfl_xor_sync(0xffffffffu, t, o);
    if (!lane) atomicAdd(&g_kl, t);
}

// ------------------------------------------------------------------
// V[b][k][f] = sum_n C[b][n][k] * Q[b][n][f] ; 64x64 tile, packed f32x2
__global__ void __launch_bounds__(256) v_kernel(const float* __restrict__ Q)
{
    const int b = blockIdx.z;
    const int k0 = blockIdx.x * 64, f0 = blockIdx.y * 64;
    __shared__ __align__(16) float As[32][64];
    __shared__ __align__(16) float Bs[32][64];
    const int tid = threadIdx.x;
    const int tx = tid & 15, ty = tid >> 4;
    const int lr = tid >> 6, lc = tid & 63;

    u64 acc2[4][2];
    #pragma unroll
    for (int i = 0; i < 4; i++) { acc2[i][0] = 0ull; acc2[i][1] = 0ull; }

    for (int n0 = 0; n0 < NN; n0 += 32) {
        #pragma unroll
        for (int r = 0; r < 8; r++) {
            int nn = lr + r*4;
            As[nn][lc] = g_C[((size_t)b*NN + n0 + nn)*NK + k0 + lc];
            Bs[nn][lc] = Q[((size_t)b*NN + n0 + nn)*NF + f0 + lc];
        }
        __syncthreads();
        #pragma unroll
        for (int nn = 0; nn < 32; nn++) {
            const u64* Brow = (const u64*)&Bs[nn][ty*4];
            u64 b0 = Brow[0], b1 = Brow[1];
            #pragma unroll
            for (int i = 0; i < 4; i++) {
                unsigned ab = __float_as_uint(As[nn][tx*4 + i]);
                u64 ap;
                asm("mov.b64 %0, {%1, %1};" : "=l"(ap) : "r"(ab));
                FMA2(acc2[i][0], ap, b0);
                FMA2(acc2[i][1], ap, b1);
            }
        }
        __syncthreads();
    }
    #pragma unroll
    for (int i = 0; i < 4; i++)
        #pragma unroll
        for (int jp = 0; jp < 2; jp++) {
            unsigned lo, hi;
            asm("mov.b64 {%0, %1}, %2;" : "=r"(lo), "=r"(hi) : "l"(acc2[i][jp]));
            size_t base = ((size_t)b*NK + k0 + tx*4 + i)*NF + f0 + ty*4 + jp*2;
            g_V[base]     = __uint_as_float(lo);
            g_V[base + 1] = __uint_as_float(hi);
        }
}

// ------------------------------------------------------------------
// out[m][o] = lrelu( sum_f V[m][f]*W[o][f] + bias[o] )
__global__ void __launch_bounds__(256) out_kernel(
    const float* __restrict__ W, const float* __restrict__ bias,
    float* __restrict__ out)
{
    const int m0 = blockIdx.x * 64, o0 = blockIdx.y * 64;
    __shared__ float As[64][33];
    __shared__ float Ws[64][33];
    const int tid = threadIdx.x;
    const int tx = tid & 15, ty = tid >> 4;
    const int lr = tid >> 5, lc = tid & 31;

    float acc[4][4];
    #pragma unroll
    for (int i = 0; i < 4; i++)
        #pragma unroll
        for (int j = 0; j < 4; j++) acc[i][j] = 0.f;

    for (int fc = 0; fc < NF; fc += 32) {
        #pragma unroll
        for (int r = 0; r < 8; r++) {
            int mm = lr + r*8;
            As[mm][lc] = g_V[(size_t)(m0 + mm)*NF + fc + lc];
            Ws[mm][lc] = W[(size_t)(o0 + mm)*NF + fc + lc];
        }
        __syncthreads();
        #pragma unroll
        for (int ff = 0; ff < 32; ff++) {
            float a[4], w[4];
            #pragma unroll
            for (int i = 0; i < 4; i++) a[i] = As[tx*4 + i][ff];
            #pragma unroll
            for (int j = 0; j < 4; j++) w[j] = Ws[ty*4 + j][ff];
            #pragma unroll
            for (int i = 0; i < 4; i++)
                #pragma unroll
                for (int j = 0; j < 4; j++)
                    acc[i][j] = fmaf(a[i], w[j], acc[i][j]);
        }
        __syncthreads();
    }
    #pragma unroll
    for (int j = 0; j < 4; j++) {
        float bj = bias[o0 + ty*4 + j];
        #pragma unroll
        for (int i = 0; i < 4; i++) {
            float v = acc[i][j] + bj;
            v = (v >= 0.f) ? v : 0.01f * v;
            out[(size_t)(m0 + tx*4 + i)*NDOUT + o0 + ty*4 + j] = v;
        }
    }
}

// write kl scalar(s) after the out tensor
__global__ void finalize_kernel(float* __restrict__ out, int out_size)
{
    int i = OUT_ELEMS + blockIdx.x * blockDim.x + threadIdx.x;
    if (i < out_size) out[i] = __fmul_rn(100.0f, (float)g_kl);
}

// ------------------------------------------------------------------
extern "C" void kernel_launch(void* const* d_in, const int* in_sizes, int n_in,
                              void* d_out, int out_size)
{
    const float* Q      = (const float*)d_in[0];
    const float* keys   = (const float*)d_in[1];
    const float* conv_w = (const float*)d_in[2];
    const float* lin_w  = (const float*)d_in[3];
    const float* lin_b  = (const float*)d_in[4];
    const int*   mask   = (const int*)d_in[5];
    float* out = (float*)d_out;

    // smem: QsU 34816 + Sacc 65664 + kbuf 98304 + redw 2048 + misc 512
    const int smem = (8704 + 32*SP + 24576 + 512 + 4*32) * (int)sizeof(float);
    cudaFuncSetAttribute(scores_kernel, cudaFuncAttributeMaxDynamicSharedMemorySize, smem);

    init_kernel<<<1, 32>>>();                      // my #0
    k2_kernel<<<(NH*NK)/8, 256>>>(keys);           // my #1
    prep_keys<<<512, 256>>>(keys);                 // my #2
    scores_kernel<<<dim3(NN/32, NB), 512, smem>>>(Q, conv_w, mask); // my #3 = ncu slot 5
    cn_kernel<<<(NB*NK)/256, 256>>>();
    kl_kernel<<<(NB*NN)/8, 256>>>();
    v_kernel<<<dim3(NK/64, NF/64, NB), 256>>>(Q);
    out_kernel<<<dim3((NB*NK)/64, NDOUT/64), 256>>>(lin_w, lin_b, out);

    int extra = out_size - OUT_ELEMS;
    if (extra > 0)
        finalize_kernel<<<(extra + 255)/256, 256>>>(out, out_size);
}

// round 15
// speedup vs baseline: 2.7886x; 1.0292x over previous
#include <cuda_runtime.h>
#include <cuda_bf16.h>
#include <cstdint>

#define NB   16
#define NN   1024
#define NF   256
#define NH   8
#define NK   512
#define NDOUT 256
#define EPSF 1e-8f
#define OUT_ELEMS (NB*NK*NDOUT)
#define SP   513   // padded row stride
#define QW   132   // Qhi/Qlo row stride in u32 (264 bf16 = conflict-free)

typedef unsigned long long u64;

// packed fp32x2 FMA (kept for v_kernel)
#define FMA2(acc, a, b) \
    asm("fma.rn.f32x2 %0, %1, %2, %0;" : "+l"(acc) : "l"(a), "l"(b))

// m16n8k16 bf16 MMA, fp32 accumulate in place
__device__ __forceinline__ void mma_bf16(
    float& d0, float& d1, float& d2, float& d3,
    unsigned a0, unsigned a1, unsigned a2, unsigned a3,
    unsigned b0, unsigned b1)
{
    asm volatile(
        "mma.sync.aligned.m16n8k16.row.col.f32.bf16.bf16.f32 "
        "{%0,%1,%2,%3}, {%4,%5,%6,%7}, {%8,%9}, {%0,%1,%2,%3};"
        : "+f"(d0), "+f"(d1), "+f"(d2), "+f"(d3)
        : "r"(a0), "r"(a1), "r"(a2), "r"(a3), "r"(b0), "r"(b1));
}

// ---- scratch ----
__device__ float  g_C[(size_t)NB*NN*NK];    // 32 MB
__device__ float  g_V[(size_t)NB*NK*NF];    // 8 MB
__device__ float  g_cnp[(size_t)NB*32*NK];  // per-block colsum partials (1MB)
__device__ float  g_cnf[NB*NK];
__device__ float  g_k2[NH*NK];
__device__ double g_kl;
// keys split into bf16 hi/lo, layout [h][fchunk 16][seg 2][k 512][f 8]
__device__ __nv_bfloat16 g_khi[(size_t)NH*NK*NF];
__device__ __nv_bfloat16 g_klo[(size_t)NH*NK*NF];

// ------------------------------------------------------------------
// exp(x) for x in [-0.125, 0], float-float, ~1e-11 accurate.
__device__ __forceinline__ float exp_small(float x) {
    if (x < -0.125f) return (float)exp((double)x);   // rare fallback
    float x2h = __fmul_rn(x, x);
    float x2l = fmaf(x, x, -x2h);
    float U = fmaf(x, fmaf(x, fmaf(x, fmaf(x, 1.f/5040.f, 1.f/720.f),
                                   1.f/120.f), 1.f/24.f), 1.f/6.f);
    float tail = fmaf(__fmul_rn(x2h, x), U, 0.5f*x2l);
    float sh = __fadd_rn(1.f, x);
    float sl = __fadd_rn(__fsub_rn(1.f, sh), x);
    float b  = 0.5f*x2h;
    float th = __fadd_rn(sh, b);
    float tl = __fadd_rn(__fsub_rn(sh, th), b);
    return __fadd_rn(th, __fadd_rn(__fadd_rn(tl, sl), tail));
}

// log(y) for y ~ 1/512*(1 +- 0.06), float-float, ~1e-11 accurate.
__device__ __forceinline__ float log_near(float y) {
    const double LN512 = 6.2383246250395078;
    const float LH = (float)LN512;
    const float LL = (float)(LN512 - (double)LH);
    float u = __fmul_rn(y, 512.f);
    float w = __fsub_rn(u, 1.f);
    if (fabsf(w) > 0.0625f) return (float)log((double)y);  // rare fallback
    float w2h = __fmul_rn(w, w);
    float w2l = fmaf(w, w, -w2h);
    float V = fmaf(w, fmaf(w, fmaf(w, fmaf(w, fmaf(w, -1.f/8.f, 1.f/7.f),
                                   -1.f/6.f), 1.f/5.f), -1.f/4.f), 1.f/3.f);
    float tail = fmaf(__fmul_rn(w2h, w), V, -0.5f*w2l);
    float b  = -0.5f*w2h;
    float sh = __fadd_rn(w, b);
    float sl = __fadd_rn(__fsub_rn(w, sh), b);
    float th = __fadd_rn(sh, -LH);
    float tl = __fadd_rn(__fsub_rn(-LH, th), sh);
    return __fadd_rn(th, __fsub_rn(__fadd_rn(__fadd_rn(tl, sl), tail), LL));
}

// ------------------------------------------------------------------
__global__ void init_kernel() {
    if (blockIdx.x == 0 && threadIdx.x == 0) g_kl = 0.0;
}

// ||keys[h][k]||^2 : warp per row
__global__ void k2_kernel(const float* __restrict__ keys) {
    int warp = threadIdx.x >> 5, lane = threadIdx.x & 31;
    int row = blockIdx.x * 8 + warp;           // < NH*NK = 4096
    const float4* kr = (const float4*)(keys + (size_t)row * NF);
    float s = 0.f;
    #pragma unroll
    for (int j = lane; j < 64; j += 32) {
        float4 v = kr[j];
        s += v.x*v.x + v.y*v.y + v.z*v.z + v.w*v.w;
    }
    #pragma unroll
    for (int o = 16; o; o >>= 1) s += __shfl_xor_sync(0xffffffffu, s, o);
    if (!lane) g_k2[row] = s;
}

// keys -> bf16 hi/lo split, staged layout [h][fc][seg][k][8f]
__global__ void __launch_bounds__(256) prep_keys(const float* __restrict__ keys)
{
    int gid = blockIdx.x * 256 + threadIdx.x;   // < 131072
    int k   = gid & 511;
    int seg = (gid >> 9) & 1;
    int fc  = (gid >> 10) & 15;
    int h   = gid >> 14;
    const float* src = keys + ((size_t)(h*NK + k))*NF + fc*16 + seg*8;
    __nv_bfloat16* dhi = g_khi + (size_t)gid*8;
    __nv_bfloat16* dlo = g_klo + (size_t)gid*8;
    #pragma unroll
    for (int j = 0; j < 8; j++) {
        float x = src[j];
        __nv_bfloat16 hi = __float2bfloat16_rn(x);
        __nv_bfloat16 lo =
            __float2bfloat16_rn(__fsub_rn(x, __bfloat162float(hi)));
        dhi[j] = hi; dlo[j] = lo;
    }
}

// ------------------------------------------------------------------
// cp.async one chunk of THIS WARP's private key slice (32 k rows x 16 f,
// hi+lo) into stage chunk%3.
__device__ __forceinline__ void issue_slice(
    float* kbuf, int h, int chunk, int w, int lane)
{
    const int st = chunk % 3;
    char* dstbase = (char*)kbuf + (size_t)((st*16 + w)*2)*1024;
    #pragma unroll
    for (int i = 0; i < 4; i++) {
        int t = i >> 1, seg = i & 1;
        const __nv_bfloat16* src = (t ? g_klo : g_khi)
            + ((size_t)(((h*16 + chunk)*2 + seg)*512) + 32*w + lane)*8;
        char* dst = dstbase + t*1024 + seg*512 + lane*16;
        unsigned d = (unsigned)__cvta_generic_to_shared(dst);
        asm volatile("cp.async.ca.shared.global [%0], [%1], 16;"
                     :: "r"(d), "l"(src));
    }
    asm volatile("cp.async.commit_group;");
}

// ------------------------------------------------------------------
// Fused scores kernel: tensor-core qk (bf16 3-product), warp-private key
// slices (no sync in GEMM loop), REGISTER logits accumulator (zero Sacc
// smem traffic in the head loop; bitwise-identical adds), warp-partial
// rowsum, fused cn partials.
__global__ void __launch_bounds__(512, 1) scores_kernel(
    const float* __restrict__ Q, const float* __restrict__ conv_w,
    const int* __restrict__ mask)
{
    extern __shared__ float sm[];
    float* QsU  = sm;                      // 8704 floats: fp32 Q then Qhi/Qlo
    float* Sacc = sm + 8704;               // 32*SP (used only after head loop)
    float* kbuf = Sacc + 32*SP;            // 24576 floats (96KB, 3 stages)
    float* redw = kbuf + 24576;            // 16*32 rowsum partials
    float* rowv = redw + 512;              // 32
    float* q2s  = rowv + 32;               // 32
    float* mxs  = q2s + 32;                // 32
    float* msk  = mxs + 32;                // 32

    const int tid  = threadIdx.x;
    const int lane = tid & 31, warp = tid >> 5;
    const int g = lane >> 2, c = lane & 3;     // mma group/quad ids
    const int b  = blockIdx.y;
    const int n0 = blockIdx.x * 32;
    const int k  = tid;                        // softmax/C phases

    // --- load Q tile (fp32) + mask ---
    float* Qs = QsU;
    const float4* Qg = (const float4*)(Q + ((size_t)b*NN + n0)*NF);
    float4* Qs4 = (float4*)Qs;
    #pragma unroll
    for (int i = tid; i < 32*64; i += 512) Qs4[i] = Qg[i];
    if (tid < 32) msk[tid] = (float)mask[b*NN + n0 + tid];
    __syncthreads();

    // --- q2 per row (fp32, unchanged) ---
    #pragma unroll
    for (int r = 0; r < 2; r++) {
        int n = warp*2 + r;
        float s = 0.f;
        #pragma unroll
        for (int j = 0; j < 8; j++) {
            float v = Qs[n*256 + lane + 32*j];
            s = __fadd_rn(s, __fmul_rn(v, v));
        }
        #pragma unroll
        for (int o = 16; o; o >>= 1)
            s = __fadd_rn(s, __shfl_xor_sync(0xffffffffu, s, o));
        if (!lane) q2s[n] = s;
    }

    // --- convert Q fp32 -> bf16 hi/lo in place ---
    float vals[16];
    #pragma unroll
    for (int j = 0; j < 16; j++) vals[j] = Qs[tid + 512*j];
    __syncthreads();
    {
        __nv_bfloat16* Qhb = (__nv_bfloat16*)QsU;
        __nv_bfloat16* Qlb = Qhb + 8448;
        #pragma unroll
        for (int j = 0; j < 16; j++) {
            int idx = tid + 512*j;
            int n = idx >> 8, f = idx & 255;
            __nv_bfloat16 hi = __float2bfloat16_rn(vals[j]);
            __nv_bfloat16 lo = __float2bfloat16_rn(
                __fsub_rn(vals[j], __bfloat162float(hi)));
            Qhb[n*264 + f] = hi;
            Qlb[n*264 + f] = lo;
        }
    }
    __syncthreads();

    const unsigned* QhiU = (const unsigned*)QsU;
    const unsigned* QloU = QhiU + 4224;

    issue_slice(kbuf, 0, 0, warp, lane);
    issue_slice(kbuf, 0, 1, warp, lane);

    // register logits accumulator (head-invariant (n,kx) ownership)
    float lg[2][4][4];
    #pragma unroll
    for (int mt = 0; mt < 2; mt++)
        #pragma unroll
        for (int kt = 0; kt < 4; kt++)
            #pragma unroll
            for (int e = 0; e < 4; e++) lg[mt][kt][e] = 0.f;

    for (int h = 0; h < NH; h++) {
        float d[2][4][4];
        #pragma unroll
        for (int mt = 0; mt < 2; mt++)
            #pragma unroll
            for (int kt = 0; kt < 4; kt++)
                #pragma unroll
                for (int e = 0; e < 4; e++) d[mt][kt][e] = 0.f;

        #pragma unroll 1
        for (int chunk = 0; chunk < 16; chunk++) {
            if (chunk + 1 < 16)
                asm volatile("cp.async.wait_group 1;");
            else
                asm volatile("cp.async.wait_group 0;");
            __syncwarp();
            if (chunk + 2 < 16)
                issue_slice(kbuf, h, chunk + 2, warp, lane);

            unsigned ah[2][4], al[2][4];
            #pragma unroll
            for (int mt = 0; mt < 2; mt++) {
                int r0 = (mt*16 + g)*QW + chunk*8 + c;
                int r1 = (mt*16 + g + 8)*QW + chunk*8 + c;
                ah[mt][0] = QhiU[r0];     ah[mt][1] = QhiU[r1];
                ah[mt][2] = QhiU[r0 + 4]; ah[mt][3] = QhiU[r1 + 4];
                al[mt][0] = QloU[r0];     al[mt][1] = QloU[r1];
                al[mt][2] = QloU[r0 + 4]; al[mt][3] = QloU[r1 + 4];
            }

            const unsigned* BhiU = (const unsigned*)
                ((char*)kbuf + (size_t)(((chunk%3)*16 + warp)*2)*1024);
            const unsigned* BloU = BhiU + 256;

            #pragma unroll
            for (int kt = 0; kt < 4; kt++) {
                int bo = (kt*8 + g)*4 + c;
                unsigned bh0 = BhiU[bo], bh1 = BhiU[128 + bo];
                unsigned bl0 = BloU[bo], bl1 = BloU[128 + bo];
                #pragma unroll
                for (int mt = 0; mt < 2; mt++) {
                    mma_bf16(d[mt][kt][0], d[mt][kt][1],
                             d[mt][kt][2], d[mt][kt][3],
                             ah[mt][0], ah[mt][1], ah[mt][2], ah[mt][3],
                             bh0, bh1);
                    mma_bf16(d[mt][kt][0], d[mt][kt][1],
                             d[mt][kt][2], d[mt][kt][3],
                             ah[mt][0], ah[mt][1], ah[mt][2], ah[mt][3],
                             bl0, bl1);
                    mma_bf16(d[mt][kt][0], d[mt][kt][1],
                             d[mt][kt][2], d[mt][kt][3],
                             al[mt][0], al[mt][1], al[mt][2], al[mt][3],
                             bh0, bh1);
                }
            }
        }

        // prefetch next head's first two chunks under the epilogue
        if (h + 1 < NH) {
            issue_slice(kbuf, h + 1, 0, warp, lane);
            issue_slice(kbuf, h + 1, 1, warp, lane);
        }

        // d2 = (q2+k2) - 2*qk; cv = 1/(1 + sqrt(max(d2,0))^2)  (frozen ops)
        float k2r[4][2];
        {
            const float* k2p = g_k2 + h*NK + 32*warp + 2*c;
            #pragma unroll
            for (int kt = 0; kt < 4; kt++) {
                k2r[kt][0] = __ldg(k2p + kt*8);
                k2r[kt][1] = __ldg(k2p + kt*8 + 1);
            }
        }
        #pragma unroll
        for (int mt = 0; mt < 2; mt++)
            #pragma unroll
            for (int kt = 0; kt < 4; kt++)
                #pragma unroll
                for (int e = 0; e < 4; e++) {
                    int n  = mt*16 + g + ((e & 2) ? 8 : 0);
                    float qk = d[mt][kt][e];
                    float d2 = __fsub_rn(__fadd_rn(q2s[n], k2r[kt][e & 1]),
                                         __fmul_rn(2.0f, qk));
                    float t  = sqrtf(fmaxf(d2, 0.0f));
                    d[mt][kt][e] = __fdiv_rn(1.0f,
                                     __fadd_rn(1.0f, __fmul_rn(t, t)));
                }

        // warp-partial rowsum (deterministic; order-insensitive quantity)
        #pragma unroll
        for (int mt = 0; mt < 2; mt++)
            #pragma unroll
            for (int e2 = 0; e2 < 2; e2++) {
                float s = 0.f;
                #pragma unroll
                for (int kt = 0; kt < 4; kt++) {
                    s = __fadd_rn(s, d[mt][kt][2*e2]);
                    s = __fadd_rn(s, d[mt][kt][2*e2 + 1]);
                }
                s = __fadd_rn(s, __shfl_xor_sync(0xffffffffu, s, 1));
                s = __fadd_rn(s, __shfl_xor_sync(0xffffffffu, s, 2));
                if (c == 0)
                    redw[warp*32 + mt*16 + 8*e2 + g] = s;
            }
        __syncthreads();
        if (tid < 32) {
            float s = 0.f;
            #pragma unroll
            for (int w = 0; w < 16; w++)
                s = __fadd_rn(s, redw[w*32 + tid]);
            rowv[tid] = s;
        }
        __syncthreads();

        // logits += cw * ((c / rowsum) * msk), ascending h — REGISTERS
        const float cw = conv_w[h];
        #pragma unroll
        for (int mt = 0; mt < 2; mt++)
            #pragma unroll
            for (int kt = 0; kt < 4; kt++)
                #pragma unroll
                for (int e = 0; e < 4; e++) {
                    int n = mt*16 + g + ((e & 2) ? 8 : 0);
                    float cdiv = __fdiv_rn(d[mt][kt][e], rowv[n]);
                    float term = __fmul_rn(cw, __fmul_rn(cdiv, msk[n]));
                    lg[mt][kt][e] = __fadd_rn(lg[mt][kt][e], term);
                }
    }

    // write logits to Sacc once (values bitwise identical to R14)
    #pragma unroll
    for (int mt = 0; mt < 2; mt++)
        #pragma unroll
        for (int kt = 0; kt < 4; kt++)
            #pragma unroll
            for (int e = 0; e < 4; e++) {
                int n  = mt*16 + g + ((e & 2) ? 8 : 0);
                int kx = 32*warp + kt*8 + 2*c + (e & 1);
                Sacc[n*SP + kx] = lg[mt][kt][e];
            }
    __syncthreads();

    // softmax: row max
    #pragma unroll
    for (int r = 0; r < 2; r++) {
        int n = warp*2 + r;
        float mx = -3.402823466e38f;
        #pragma unroll
        for (int j = 0; j < 16; j++)
            mx = fmaxf(mx, Sacc[n*SP + lane + 32*j]);
        #pragma unroll
        for (int o = 16; o; o >>= 1)
            mx = fmaxf(mx, __shfl_xor_sync(0xffffffffu, mx, o));
        if (!lane) mxs[n] = mx;
    }
    __syncthreads();
    // e = exp(x - mx), correctly-rounded-grade (FROZEN)
    #pragma unroll
    for (int n = 0; n < 32; n++) {
        float x = __fsub_rn(Sacc[n*SP + k], mxs[n]);
        Sacc[n*SP + k] = exp_small(x);
    }
    __syncthreads();
    // denominator: strict sequential ascending fp32 (FROZEN order)
    if (tid < 32) {
        const float* row = &Sacc[tid*SP];
        float s = 0.f;
        #pragma unroll 8
        for (int j = 0; j < NK; j++)
            s = __fadd_rn(s, row[j]);
        rowv[tid] = s;
    }
    __syncthreads();

    // C = (e / s) * msk; fused sequential-ascending colsum partial
    float* Cout = g_C + ((size_t)b*NN + n0)*NK + k;
    float cs = 0.f;
    #pragma unroll
    for (int n = 0; n < 32; n++) {
        float cvv = __fmul_rn(__fdiv_rn(Sacc[n*SP + k], rowv[n]), msk[n]);
        Cout[(size_t)n*NK] = cvv;
        cs = __fadd_rn(cs, cvv);
    }
    g_cnp[((size_t)b*32 + blockIdx.x)*NK + k] = cs;
}

// ------------------------------------------------------------------
// cn[b][k] = sum of 32 block partials, ascending block order
__global__ void __launch_bounds__(256) cn_kernel()
{
    int id = blockIdx.x * blockDim.x + threadIdx.x;   // < NB*NK
    int b = id >> 9, kk = id & 511;
    const float* p = g_cnp + ((size_t)b*32)*NK + kk;
    float s = 0.f;
    #pragma unroll
    for (int j = 0; j < 32; j++)
        s = __fadd_rn(s, p[(size_t)j*NK]);
    g_cnf[id] = s;
}

// ------------------------------------------------------------------
// KL: warp per (b,n) row. Sequential fp32 pn (FROZEN); float-float logs.
__global__ void __launch_bounds__(256) kl_kernel()
{
    __shared__ float cbuf[8][SP];
    __shared__ float pbuf[8][SP];
    const int warp = threadIdx.x >> 5, lane = threadIdx.x & 31;
    const int row = blockIdx.x * 8 + warp;   // < NB*NN
    const int b = row >> 10;
    const float* crow = g_C + (size_t)row * NK;
    const float* cnb = g_cnf + b*NK;

    #pragma unroll
    for (int j = 0; j < 16; j++) {
        int kk = lane + 32*j;
        float c = crow[kk];
        float cnf = __fadd_rn(cnb[kk], EPSF);
        float p = __fdiv_rn(__fmul_rn(c, c), cnf);
        cbuf[warp][kk] = c;
        pbuf[warp][kk] = p;
    }
    __syncwarp();
    if (!lane) {
        float pn = 0.f;
        const float* prow = pbuf[warp];
        #pragma unroll 8
        for (int j = 0; j < NK; j++)
            pn = __fadd_rn(pn, prow[j]);
        pbuf[warp][512] = __fadd_rn(pn, EPSF);
    }
    __syncwarp();
    const float pnf = pbuf[warp][512];

    double t = 0.0;
    #pragma unroll
    for (int j = 0; j < 16; j++) {
        int kk = lane + 32*j;
        float pv = pbuf[warp][kk];
        if (pv != 0.f) {
            float P  = __fdiv_rn(pv, pnf);
            float la = log_near(__fadd_rn(P, EPSF));
            float lb = log_near(__fadd_rn(cbuf[warp][kk], EPSF));
            t += (double)__fmul_rn(P, __fsub_rn(la, lb));
        }
    }
    #pragma unroll
    for (int o = 16; o; o >>= 1) t += __shfl_xor_sync(0xffffffffu, t, o);
    if (!lane) atomicAdd(&g_kl, t);
}

// ------------------------------------------------------------------
// V[b][k][f] = sum_n C[b][n][k] * Q[b][n][f] ; 64x64 tile, packed f32x2
__global__ void __launch_bounds__(256) v_kernel(const float* __restrict__ Q)
{
    const int b = blockIdx.z;
    const int k0 = blockIdx.x * 64, f0 = blockIdx.y * 64;
    __shared__ __align__(16) float As[32][64];
    __shared__ __align__(16) float Bs[32][64];
    const int tid = threadIdx.x;
    const int tx = tid & 15, ty = tid >> 4;
    const int lr = tid >> 6, lc = tid & 63;

    u64 acc2[4][2];
    #pragma unroll
    for (int i = 0; i < 4; i++) { acc2[i][0] = 0ull; acc2[i][1] = 0ull; }

    for (int n0 = 0; n0 < NN; n0 += 32) {
        #pragma unroll
        for (int r = 0; r < 8; r++) {
            int nn = lr + r*4;
            As[nn][lc] = g_C[((size_t)b*NN + n0 + nn)*NK + k0 + lc];
            Bs[nn][lc] = Q[((size_t)b*NN + n0 + nn)*NF + f0 + lc];
        }
        __syncthreads();
        #pragma unroll
        for (int nn = 0; nn < 32; nn++) {
            const u64* Brow = (const u64*)&Bs[nn][ty*4];
            u64 b0 = Brow[0], b1 = Brow[1];
            #pragma unroll
            for (int i = 0; i < 4; i++) {
                unsigned ab = __float_as_uint(As[nn][tx*4 + i]);
                u64 ap;
                asm("mov.b64 %0, {%1, %1};" : "=l"(ap) : "r"(ab));
                FMA2(acc2[i][0], ap, b0);
                FMA2(acc2[i][1], ap, b1);
            }
        }
        __syncthreads();
    }
    #pragma unroll
    for (int i = 0; i < 4; i++)
        #pragma unroll
        for (int jp = 0; jp < 2; jp++) {
            unsigned lo, hi;
            asm("mov.b64 {%0, %1}, %2;" : "=r"(lo), "=r"(hi) : "l"(acc2[i][jp]));
            size_t base = ((size_t)b*NK + k0 + tx*4 + i)*NF + f0 + ty*4 + jp*2;
            g_V[base]     = __uint_as_float(lo);
            g_V[base + 1] = __uint_as_float(hi);
        }
}

// ------------------------------------------------------------------
// out[m][o] = lrelu( sum_f V[m][f]*W[o][f] + bias[o] )
__global__ void __launch_bounds__(256) out_kernel(
    const float* __restrict__ W, const float* __restrict__ bias,
    float* __restrict__ out)
{
    const int m0 = blockIdx.x * 64, o0 = blockIdx.y * 64;
    __shared__ float As[64][33];
    __shared__ float Ws[64][33];
    const int tid = threadIdx.x;
    const int tx = tid & 15, ty = tid >> 4;
    const int lr = tid >> 5, lc = tid & 31;

    float acc[4][4];
    #pragma unroll
    for (int i = 0; i < 4; i++)
        #pragma unroll
        for (int j = 0; j < 4; j++) acc[i][j] = 0.f;

    for (int fc = 0; fc < NF; fc += 32) {
        #pragma unroll
        for (int r = 0; r < 8; r++) {
            int mm = lr + r*8;
            As[mm][lc] = g_V[(size_t)(m0 + mm)*NF + fc + lc];
            Ws[mm][lc] = W[(size_t)(o0 + mm)*NF + fc + lc];
        }
        __syncthreads();
        #pragma unroll
        for (int ff = 0; ff < 32; ff++) {
            float a[4], w[4];
            #pragma unroll
            for (int i = 0; i < 4; i++) a[i] = As[tx*4 + i][ff];
            #pragma unroll
            for (int j = 0; j < 4; j++) w[j] = Ws[ty*4 + j][ff];
            #pragma unroll
            for (int i = 0; i < 4; i++)
                #pragma unroll
                for (int j = 0; j < 4; j++)
                    acc[i][j] = fmaf(a[i], w[j], acc[i][j]);
        }
        __syncthreads();
    }
    #pragma unroll
    for (int j = 0; j < 4; j++) {
        float bj = bias[o0 + ty*4 + j];
        #pragma unroll
        for (int i = 0; i < 4; i++) {
            float v = acc[i][j] + bj;
            v = (v >= 0.f) ? v : 0.01f * v;
            out[(size_t)(m0 + tx*4 + i)*NDOUT + o0 + ty*4 + j] = v;
        }
    }
}

// write kl scalar(s) after the out tensor
__global__ void finalize_kernel(float* __restrict__ out, int out_size)
{
    int i = OUT_ELEMS + blockIdx.x * blockDim.x + threadIdx.x;
    if (i < out_size) out[i] = __fmul_rn(100.0f, (float)g_kl);
}

// ------------------------------------------------------------------
extern "C" void kernel_launch(void* const* d_in, const int* in_sizes, int n_in,
                              void* d_out, int out_size)
{
    const float* Q      = (const float*)d_in[0];
    const float* keys   = (const float*)d_in[1];
    const float* conv_w = (const float*)d_in[2];
    const float* lin_w  = (const float*)d_in[3];
    const float* lin_b  = (const float*)d_in[4];
    const int*   mask   = (const int*)d_in[5];
    float* out = (float*)d_out;

    // smem: QsU 34816 + Sacc 65664 + kbuf 98304 + redw 2048 + misc 512
    const int smem = (8704 + 32*SP + 24576 + 512 + 4*32) * (int)sizeof(float);
    cudaFuncSetAttribute(scores_kernel, cudaFuncAttributeMaxDynamicSharedMemorySize, smem);

    init_kernel<<<1, 32>>>();                      // my #0
    k2_kernel<<<(NH*NK)/8, 256>>>(keys);           // my #1
    prep_keys<<<512, 256>>>(keys);                 // my #2
    scores_kernel<<<dim3(NN/32, NB), 512, smem>>>(Q, conv_w, mask); // my #3 = ncu slot 5
    cn_kernel<<<(NB*NK)/256, 256>>>();
    kl_kernel<<<(NB*NN)/8, 256>>>();
    v_kernel<<<dim3(NK/64, NF/64, NB), 256>>>(Q);
    out_kernel<<<dim3((NB*NK)/64, NDOUT/64), 256>>>(lin_w, lin_b, out);

    int extra = out_size - OUT_ELEMS;
    if (extra > 0)
        finalize_kernel<<<(extra + 255)/256, 256>>>(out, out_size);
}

// round 16
// speedup vs baseline: 2.9300x; 1.0507x over previous
#include <cuda_runtime.h>
#include <cuda_bf16.h>
#include <cstdint>

#define NB   16
#define NN   1024
#define NF   256
#define NH   8
#define NK   512
#define NDOUT 256
#define EPSF 1e-8f
#define OUT_ELEMS (NB*NK*NDOUT)
#define SP   513   // padded row stride
#define QW   132   // Qhi/Qlo row stride in u32 (264 bf16 = conflict-free)

typedef unsigned long long u64;

// packed fp32x2 FMA (kept for v_kernel)
#define FMA2(acc, a, b) \
    asm("fma.rn.f32x2 %0, %1, %2, %0;" : "+l"(acc) : "l"(a), "l"(b))

// m16n8k16 bf16 MMA, fp32 accumulate in place
__device__ __forceinline__ void mma_bf16(
    float& d0, float& d1, float& d2, float& d3,
    unsigned a0, unsigned a1, unsigned a2, unsigned a3,
    unsigned b0, unsigned b1)
{
    asm volatile(
        "mma.sync.aligned.m16n8k16.row.col.f32.bf16.bf16.f32 "
        "{%0,%1,%2,%3}, {%4,%5,%6,%7}, {%8,%9}, {%0,%1,%2,%3};"
        : "+f"(d0), "+f"(d1), "+f"(d2), "+f"(d3)
        : "r"(a0), "r"(a1), "r"(a2), "r"(a3), "r"(b0), "r"(b1));
}

// ldmatrix x4 (non-transposed)
__device__ __forceinline__ void ldsm_x4(
    unsigned& r0, unsigned& r1, unsigned& r2, unsigned& r3, unsigned addr)
{
    asm volatile(
        "ldmatrix.sync.aligned.m8n8.x4.shared.b16 {%0,%1,%2,%3}, [%4];"
        : "=r"(r0), "=r"(r1), "=r"(r2), "=r"(r3) : "r"(addr));
}

// ---- scratch ----
__device__ float  g_C[(size_t)NB*NN*NK];    // 32 MB
__device__ float  g_V[(size_t)NB*NK*NF];    // 8 MB
__device__ float  g_cnp[(size_t)NB*32*NK];  // per-block colsum partials (1MB)
__device__ float  g_cnf[NB*NK];
__device__ float  g_k2[NH*NK];
__device__ double g_kl;
// keys split into bf16 hi/lo, layout [h][fchunk 16][seg 2][k 512][f 8]
__device__ __nv_bfloat16 g_khi[(size_t)NH*NK*NF];
__device__ __nv_bfloat16 g_klo[(size_t)NH*NK*NF];

// ------------------------------------------------------------------
// exp(x) for x in [-0.125, 0], float-float, ~1e-11 accurate.
__device__ __forceinline__ float exp_small(float x) {
    if (x < -0.125f) return (float)exp((double)x);   // rare fallback
    float x2h = __fmul_rn(x, x);
    float x2l = fmaf(x, x, -x2h);
    float U = fmaf(x, fmaf(x, fmaf(x, fmaf(x, 1.f/5040.f, 1.f/720.f),
                                   1.f/120.f), 1.f/24.f), 1.f/6.f);
    float tail = fmaf(__fmul_rn(x2h, x), U, 0.5f*x2l);
    float sh = __fadd_rn(1.f, x);
    float sl = __fadd_rn(__fsub_rn(1.f, sh), x);
    float b  = 0.5f*x2h;
    float th = __fadd_rn(sh, b);
    float tl = __fadd_rn(__fsub_rn(sh, th), b);
    return __fadd_rn(th, __fadd_rn(__fadd_rn(tl, sl), tail));
}

// log(y) for y ~ 1/512*(1 +- 0.06), float-float, ~1e-11 accurate.
__device__ __forceinline__ float log_near(float y) {
    const double LN512 = 6.2383246250395078;
    const float LH = (float)LN512;
    const float LL = (float)(LN512 - (double)LH);
    float u = __fmul_rn(y, 512.f);
    float w = __fsub_rn(u, 1.f);
    if (fabsf(w) > 0.0625f) return (float)log((double)y);  // rare fallback
    float w2h = __fmul_rn(w, w);
    float w2l = fmaf(w, w, -w2h);
    float V = fmaf(w, fmaf(w, fmaf(w, fmaf(w, fmaf(w, -1.f/8.f, 1.f/7.f),
                                   -1.f/6.f), 1.f/5.f), -1.f/4.f), 1.f/3.f);
    float tail = fmaf(__fmul_rn(w2h, w), V, -0.5f*w2l);
    float b  = -0.5f*w2h;
    float sh = __fadd_rn(w, b);
    float sl = __fadd_rn(__fsub_rn(w, sh), b);
    float th = __fadd_rn(sh, -LH);
    float tl = __fadd_rn(__fsub_rn(-LH, th), sh);
    return __fadd_rn(th, __fsub_rn(__fadd_rn(__fadd_rn(tl, sl), tail), LL));
}

// ------------------------------------------------------------------
__global__ void init_kernel() {
    if (blockIdx.x == 0 && threadIdx.x == 0) g_kl = 0.0;
}

// ||keys[h][k]||^2 : warp per row
__global__ void k2_kernel(const float* __restrict__ keys) {
    int warp = threadIdx.x >> 5, lane = threadIdx.x & 31;
    int row = blockIdx.x * 8 + warp;           // < NH*NK = 4096
    const float4* kr = (const float4*)(keys + (size_t)row * NF);
    float s = 0.f;
    #pragma unroll
    for (int j = lane; j < 64; j += 32) {
        float4 v = kr[j];
        s += v.x*v.x + v.y*v.y + v.z*v.z + v.w*v.w;
    }
    #pragma unroll
    for (int o = 16; o; o >>= 1) s += __shfl_xor_sync(0xffffffffu, s, o);
    if (!lane) g_k2[row] = s;
}

// keys -> bf16 hi/lo split, staged layout [h][fc][seg][k][8f]
__global__ void __launch_bounds__(256) prep_keys(const float* __restrict__ keys)
{
    int gid = blockIdx.x * 256 + threadIdx.x;   // < 131072
    int k   = gid & 511;
    int seg = (gid >> 9) & 1;
    int fc  = (gid >> 10) & 15;
    int h   = gid >> 14;
    const float* src = keys + ((size_t)(h*NK + k))*NF + fc*16 + seg*8;
    __nv_bfloat16* dhi = g_khi + (size_t)gid*8;
    __nv_bfloat16* dlo = g_klo + (size_t)gid*8;
    #pragma unroll
    for (int j = 0; j < 8; j++) {
        float x = src[j];
        __nv_bfloat16 hi = __float2bfloat16_rn(x);
        __nv_bfloat16 lo =
            __float2bfloat16_rn(__fsub_rn(x, __bfloat162float(hi)));
        dhi[j] = hi; dlo[j] = lo;
    }
}

// ------------------------------------------------------------------
// cp.async one chunk of THIS WARP's private key slice (32 k rows x 16 f,
// hi+lo) into stage chunk%3.
__device__ __forceinline__ void issue_slice(
    float* kbuf, int h, int chunk, int w, int lane)
{
    const int st = chunk % 3;
    char* dstbase = (char*)kbuf + (size_t)((st*16 + w)*2)*1024;
    #pragma unroll
    for (int i = 0; i < 4; i++) {
        int t = i >> 1, seg = i & 1;
        const __nv_bfloat16* src = (t ? g_klo : g_khi)
            + ((size_t)(((h*16 + chunk)*2 + seg)*512) + 32*w + lane)*8;
        char* dst = dstbase + t*1024 + seg*512 + lane*16;
        unsigned d = (unsigned)__cvta_generic_to_shared(dst);
        asm volatile("cp.async.ca.shared.global [%0], [%1], 16;"
                     :: "r"(d), "l"(src));
    }
    asm volatile("cp.async.commit_group;");
}

// ------------------------------------------------------------------
// Fused scores kernel: tensor-core qk (bf16 3-product) with LDMATRIX
// fragment loads (8 LDSM.x4 per chunk vs 32 LDS.32), warp-private key
// slices, register logits accumulator. Fragment values and MMA order
// bitwise identical to R15.
__global__ void __launch_bounds__(512, 1) scores_kernel(
    const float* __restrict__ Q, const float* __restrict__ conv_w,
    const int* __restrict__ mask)
{
    extern __shared__ float sm[];
    float* QsU  = sm;                      // 8704 floats: fp32 Q then Qhi/Qlo
    float* Sacc = sm + 8704;               // 32*SP (used only after head loop)
    float* kbuf = Sacc + 32*SP;            // 24576 floats (96KB, 3 stages)
    float* redw = kbuf + 24576;            // 16*32 rowsum partials
    float* rowv = redw + 512;              // 32
    float* q2s  = rowv + 32;               // 32
    float* mxs  = q2s + 32;                // 32
    float* msk  = mxs + 32;                // 32

    const int tid  = threadIdx.x;
    const int lane = tid & 31, warp = tid >> 5;
    const int g = lane >> 2, c = lane & 3;     // mma group/quad ids
    const int b  = blockIdx.y;
    const int n0 = blockIdx.x * 32;
    const int k  = tid;                        // softmax/C phases

    // --- load Q tile (fp32) + mask ---
    float* Qs = QsU;
    const float4* Qg = (const float4*)(Q + ((size_t)b*NN + n0)*NF);
    float4* Qs4 = (float4*)Qs;
    #pragma unroll
    for (int i = tid; i < 32*64; i += 512) Qs4[i] = Qg[i];
    if (tid < 32) msk[tid] = (float)mask[b*NN + n0 + tid];
    __syncthreads();

    // --- q2 per row (fp32, unchanged) ---
    #pragma unroll
    for (int r = 0; r < 2; r++) {
        int n = warp*2 + r;
        float s = 0.f;
        #pragma unroll
        for (int j = 0; j < 8; j++) {
            float v = Qs[n*256 + lane + 32*j];
            s = __fadd_rn(s, __fmul_rn(v, v));
        }
        #pragma unroll
        for (int o = 16; o; o >>= 1)
            s = __fadd_rn(s, __shfl_xor_sync(0xffffffffu, s, o));
        if (!lane) q2s[n] = s;
    }

    // --- convert Q fp32 -> bf16 hi/lo in place ---
    float vals[16];
    #pragma unroll
    for (int j = 0; j < 16; j++) vals[j] = Qs[tid + 512*j];
    __syncthreads();
    {
        __nv_bfloat16* Qhb = (__nv_bfloat16*)QsU;
        __nv_bfloat16* Qlb = Qhb + 8448;
        #pragma unroll
        for (int j = 0; j < 16; j++) {
            int idx = tid + 512*j;
            int n = idx >> 8, f = idx & 255;
            __nv_bfloat16 hi = __float2bfloat16_rn(vals[j]);
            __nv_bfloat16 lo = __float2bfloat16_rn(
                __fsub_rn(vals[j], __bfloat162float(hi)));
            Qhb[n*264 + f] = hi;
            Qlb[n*264 + f] = lo;
        }
    }
    __syncthreads();

    // --- ldmatrix base addresses (thread-constant parts hoisted) ---
    const unsigned smQ = (unsigned)__cvta_generic_to_shared(QsU);
    const unsigned smK = (unsigned)__cvta_generic_to_shared(kbuf);
    // A: row = mt*16 + (lane&15), col-half = lane>>4 (+8 bf16 = +16B)
    const unsigned aoff = (unsigned)((lane & 15)*528 + (lane >> 4)*16);
    const unsigned aHi0 = smQ + aoff;            // mt=0 hi (+chunk*32)
    const unsigned aHi1 = aHi0 + 16*528;         // mt=1 hi
    const unsigned aLo0 = aHi0 + 16896;          // Qlo = Qhi + 8448 bf16
    const unsigned aLo1 = aLo0 + 16*528;
    // B: seg = (lane>>3)&1, row-in-16 = (lane&7) + 8*(lane>>4)
    const unsigned boff = (unsigned)((((lane >> 3) & 1)*512)
                        + (((lane & 7) + 8*(lane >> 4))*16));
    const unsigned bwarp = smK + (unsigned)(warp*2048) + boff;

    issue_slice(kbuf, 0, 0, warp, lane);
    issue_slice(kbuf, 0, 1, warp, lane);

    // register logits accumulator (head-invariant (n,kx) ownership)
    float lg[2][4][4];
    #pragma unroll
    for (int mt = 0; mt < 2; mt++)
        #pragma unroll
        for (int kt = 0; kt < 4; kt++)
            #pragma unroll
            for (int e = 0; e < 4; e++) lg[mt][kt][e] = 0.f;

    for (int h = 0; h < NH; h++) {
        float d[2][4][4];
        #pragma unroll
        for (int mt = 0; mt < 2; mt++)
            #pragma unroll
            for (int kt = 0; kt < 4; kt++)
                #pragma unroll
                for (int e = 0; e < 4; e++) d[mt][kt][e] = 0.f;

        #pragma unroll 1
        for (int chunk = 0; chunk < 16; chunk++) {
            if (chunk + 1 < 16)
                asm volatile("cp.async.wait_group 1;");
            else
                asm volatile("cp.async.wait_group 0;");
            __syncwarp();
            if (chunk + 2 < 16)
                issue_slice(kbuf, h, chunk + 2, warp, lane);

            // A fragments via ldmatrix (values identical to LDS path)
            unsigned ah[2][4], al[2][4];
            {
                unsigned cb = (unsigned)(chunk*32);
                ldsm_x4(ah[0][0], ah[0][1], ah[0][2], ah[0][3], aHi0 + cb);
                ldsm_x4(ah[1][0], ah[1][1], ah[1][2], ah[1][3], aHi1 + cb);
                ldsm_x4(al[0][0], al[0][1], al[0][2], al[0][3], aLo0 + cb);
                ldsm_x4(al[1][0], al[1][1], al[1][2], al[1][3], aLo1 + cb);
            }
            // B fragments via ldmatrix: bh[kt][0..1], bl[kt][0..1]
            unsigned bh[4][2], bl[4][2];
            {
                unsigned bb = bwarp + (unsigned)((chunk % 3)*32768);
                ldsm_x4(bh[0][0], bh[0][1], bh[1][0], bh[1][1], bb);
                ldsm_x4(bh[2][0], bh[2][1], bh[3][0], bh[3][1], bb + 256);
                ldsm_x4(bl[0][0], bl[0][1], bl[1][0], bl[1][1], bb + 1024);
                ldsm_x4(bl[2][0], bl[2][1], bl[3][0], bl[3][1], bb + 1280);
            }

            #pragma unroll
            for (int kt = 0; kt < 4; kt++) {
                #pragma unroll
                for (int mt = 0; mt < 2; mt++) {
                    mma_bf16(d[mt][kt][0], d[mt][kt][1],
                             d[mt][kt][2], d[mt][kt][3],
                             ah[mt][0], ah[mt][1], ah[mt][2], ah[mt][3],
                             bh[kt][0], bh[kt][1]);
                    mma_bf16(d[mt][kt][0], d[mt][kt][1],
                             d[mt][kt][2], d[mt][kt][3],
                             ah[mt][0], ah[mt][1], ah[mt][2], ah[mt][3],
                             bl[kt][0], bl[kt][1]);
                    mma_bf16(d[mt][kt][0], d[mt][kt][1],
                             d[mt][kt][2], d[mt][kt][3],
                             al[mt][0], al[mt][1], al[mt][2], al[mt][3],
                             bh[kt][0], bh[kt][1]);
                }
            }
        }

        // prefetch next head's first two chunks under the epilogue
        if (h + 1 < NH) {
            issue_slice(kbuf, h + 1, 0, warp, lane);
            issue_slice(kbuf, h + 1, 1, warp, lane);
        }

        // d2 = (q2+k2) - 2*qk; cv = 1/(1 + sqrt(max(d2,0))^2)  (frozen ops)
        float k2r[4][2];
        {
            const float* k2p = g_k2 + h*NK + 32*warp + 2*c;
            #pragma unroll
            for (int kt = 0; kt < 4; kt++) {
                k2r[kt][0] = __ldg(k2p + kt*8);
                k2r[kt][1] = __ldg(k2p + kt*8 + 1);
            }
        }
        #pragma unroll
        for (int mt = 0; mt < 2; mt++)
            #pragma unroll
            for (int kt = 0; kt < 4; kt++)
                #pragma unroll
                for (int e = 0; e < 4; e++) {
                    int n  = mt*16 + g + ((e & 2) ? 8 : 0);
                    float qk = d[mt][kt][e];
                    float d2 = __fsub_rn(__fadd_rn(q2s[n], k2r[kt][e & 1]),
                                         __fmul_rn(2.0f, qk));
                    float t  = sqrtf(fmaxf(d2, 0.0f));
                    d[mt][kt][e] = __fdiv_rn(1.0f,
                                     __fadd_rn(1.0f, __fmul_rn(t, t)));
                }

        // warp-partial rowsum (deterministic; order-insensitive quantity)
        #pragma unroll
        for (int mt = 0; mt < 2; mt++)
            #pragma unroll
            for (int e2 = 0; e2 < 2; e2++) {
                float s = 0.f;
                #pragma unroll
                for (int kt = 0; kt < 4; kt++) {
                    s = __fadd_rn(s, d[mt][kt][2*e2]);
                    s = __fadd_rn(s, d[mt][kt][2*e2 + 1]);
                }
                s = __fadd_rn(s, __shfl_xor_sync(0xffffffffu, s, 1));
                s = __fadd_rn(s, __shfl_xor_sync(0xffffffffu, s, 2));
                if (c == 0)
                    redw[warp*32 + mt*16 + 8*e2 + g] = s;
            }
        __syncthreads();
        if (tid < 32) {
            float s = 0.f;
            #pragma unroll
            for (int w = 0; w < 16; w++)
                s = __fadd_rn(s, redw[w*32 + tid]);
            rowv[tid] = s;
        }
        __syncthreads();

        // logits += cw * ((c / rowsum) * msk), ascending h — REGISTERS
        const float cw = conv_w[h];
        #pragma unroll
        for (int mt = 0; mt < 2; mt++)
            #pragma unroll
            for (int kt = 0; kt < 4; kt++)
                #pragma unroll
                for (int e = 0; e < 4; e++) {
                    int n = mt*16 + g + ((e & 2) ? 8 : 0);
                    float cdiv = __fdiv_rn(d[mt][kt][e], rowv[n]);
                    float term = __fmul_rn(cw, __fmul_rn(cdiv, msk[n]));
                    lg[mt][kt][e] = __fadd_rn(lg[mt][kt][e], term);
                }
    }

    // write logits to Sacc once (values bitwise identical)
    #pragma unroll
    for (int mt = 0; mt < 2; mt++)
        #pragma unroll
        for (int kt = 0; kt < 4; kt++)
            #pragma unroll
            for (int e = 0; e < 4; e++) {
                int n  = mt*16 + g + ((e & 2) ? 8 : 0);
                int kx = 32*warp + kt*8 + 2*c + (e & 1);
                Sacc[n*SP + kx] = lg[mt][kt][e];
            }
    __syncthreads();

    // softmax: row max
    #pragma unroll
    for (int r = 0; r < 2; r++) {
        int n = warp*2 + r;
        float mx = -3.402823466e38f;
        #pragma unroll
        for (int j = 0; j < 16; j++)
            mx = fmaxf(mx, Sacc[n*SP + lane + 32*j]);
        #pragma unroll
        for (int o = 16; o; o >>= 1)
            mx = fmaxf(mx, __shfl_xor_sync(0xffffffffu, mx, o));
        if (!lane) mxs[n] = mx;
    }
    __syncthreads();
    // e = exp(x - mx), correctly-rounded-grade (FROZEN)
    #pragma unroll
    for (int n = 0; n < 32; n++) {
        float x = __fsub_rn(Sacc[n*SP + k], mxs[n]);
        Sacc[n*SP + k] = exp_small(x);
    }
    __syncthreads();
    // denominator: strict sequential ascending fp32 (FROZEN order)
    if (tid < 32) {
        const float* row = &Sacc[tid*SP];
        float s = 0.f;
        #pragma unroll 8
        for (int j = 0; j < NK; j++)
            s = __fadd_rn(s, row[j]);
        rowv[tid] = s;
    }
    __syncthreads();

    // C = (e / s) * msk; fused sequential-ascending colsum partial
    float* Cout = g_C + ((size_t)b*NN + n0)*NK + k;
    float cs = 0.f;
    #pragma unroll
    for (int n = 0; n < 32; n++) {
        float cvv = __fmul_rn(__fdiv_rn(Sacc[n*SP + k], rowv[n]), msk[n]);
        Cout[(size_t)n*NK] = cvv;
        cs = __fadd_rn(cs, cvv);
    }
    g_cnp[((size_t)b*32 + blockIdx.x)*NK + k] = cs;
}

// ------------------------------------------------------------------
// cn[b][k] = sum of 32 block partials, ascending block order
__global__ void __launch_bounds__(256) cn_kernel()
{
    int id = blockIdx.x * blockDim.x + threadIdx.x;   // < NB*NK
    int b = id >> 9, kk = id & 511;
    const float* p = g_cnp + ((size_t)b*32)*NK + kk;
    float s = 0.f;
    #pragma unroll
    for (int j = 0; j < 32; j++)
        s = __fadd_rn(s, p[(size_t)j*NK]);
    g_cnf[id] = s;
}

// ------------------------------------------------------------------
// KL: warp per (b,n) row. Sequential fp32 pn (FROZEN); float-float logs.
__global__ void __launch_bounds__(256) kl_kernel()
{
    __shared__ float cbuf[8][SP];
    __shared__ float pbuf[8][SP];
    const int warp = threadIdx.x >> 5, lane = threadIdx.x & 31;
    const int row = blockIdx.x * 8 + warp;   // < NB*NN
    const int b = row >> 10;
    const float* crow = g_C + (size_t)row * NK;
    const float* cnb = g_cnf + b*NK;

    #pragma unroll
    for (int j = 0; j < 16; j++) {
        int kk = lane + 32*j;
        float c = crow[kk];
        float cnf = __fadd_rn(cnb[kk], EPSF);
        float p = __fdiv_rn(__fmul_rn(c, c), cnf);
        cbuf[warp][kk] = c;
        pbuf[warp][kk] = p;
    }
    __syncwarp();
    if (!lane) {
        float pn = 0.f;
        const float* prow = pbuf[warp];
        #pragma unroll 8
        for (int j = 0; j < NK; j++)
            pn = __fadd_rn(pn, prow[j]);
        pbuf[warp][512] = __fadd_rn(pn, EPSF);
    }
    __syncwarp();
    const float pnf = pbuf[warp][512];

    double t = 0.0;
    #pragma unroll
    for (int j = 0; j < 16; j++) {
        int kk = lane + 32*j;
        float pv = pbuf[warp][kk];
        if (pv != 0.f) {
            float P  = __fdiv_rn(pv, pnf);
            float la = log_near(__fadd_rn(P, EPSF));
            float lb = log_near(__fadd_rn(cbuf[warp][kk], EPSF));
            t += (double)__fmul_rn(P, __fsub_rn(la, lb));
        }
    }
    #pragma unroll
    for (int o = 16; o; o >>= 1) t += __shfl_xor_sync(0xffffffffu, t, o);
    if (!lane) atomicAdd(&g_kl, t);
}

// ------------------------------------------------------------------
// V[b][k][f] = sum_n C[b][n][k] * Q[b][n][f] ; 64x64 tile, packed f32x2
__global__ void __launch_bounds__(256) v_kernel(const float* __restrict__ Q)
{
    const int b = blockIdx.z;
    const int k0 = blockIdx.x * 64, f0 = blockIdx.y * 64;
    __shared__ __align__(16) float As[32][64];
    __shared__ __align__(16) float Bs[32][64];
    const int tid = threadIdx.x;
    const int tx = tid & 15, ty = tid >> 4;
    const int lr = tid >> 6, lc = tid & 63;

    u64 acc2[4][2];
    #pragma unroll
    for (int i = 0; i < 4; i++) { acc2[i][0] = 0ull; acc2[i][1] = 0ull; }

    for (int n0 = 0; n0 < NN; n0 += 32) {
        #pragma unroll
        for (int r = 0; r < 8; r++) {
            int nn = lr + r*4;
            As[nn][lc] = g_C[((size_t)b*NN + n0 + nn)*NK + k0 + lc];
            Bs[nn][lc] = Q[((size_t)b*NN + n0 + nn)*NF + f0 + lc];
        }
        __syncthreads();
        #pragma unroll
        for (int nn = 0; nn < 32; nn++) {
            const u64* Brow = (const u64*)&Bs[nn][ty*4];
            u64 b0 = Brow[0], b1 = Brow[1];
            #pragma unroll
            for (int i = 0; i < 4; i++) {
                unsigned ab = __float_as_uint(As[nn][tx*4 + i]);
                u64 ap;
                asm("mov.b64 %0, {%1, %1};" : "=l"(ap) : "r"(ab));
                FMA2(acc2[i][0], ap, b0);
                FMA2(acc2[i][1], ap, b1);
            }
        }
        __syncthreads();
    }
    #pragma unroll
    for (int i = 0; i < 4; i++)
        #pragma unroll
        for (int jp = 0; jp < 2; jp++) {
            unsigned lo, hi;
            asm("mov.b64 {%0, %1}, %2;" : "=r"(lo), "=r"(hi) : "l"(acc2[i][jp]));
            size_t base = ((size_t)b*NK + k0 + tx*4 + i)*NF + f0 + ty*4 + jp*2;
            g_V[base]     = __uint_as_float(lo);
            g_V[base + 1] = __uint_as_float(hi);
        }
}

// ------------------------------------------------------------------
// out[m][o] = lrelu( sum_f V[m][f]*W[o][f] + bias[o] )
__global__ void __launch_bounds__(256) out_kernel(
    const float* __restrict__ W, const float* __restrict__ bias,
    float* __restrict__ out)
{
    const int m0 = blockIdx.x * 64, o0 = blockIdx.y * 64;
    __shared__ float As[64][33];
    __shared__ float Ws[64][33];
    const int tid = threadIdx.x;
    const int tx = tid & 15, ty = tid >> 4;
    const int lr = tid >> 5, lc = tid & 31;

    float acc[4][4];
    #pragma unroll
    for (int i = 0; i < 4; i++)
        #pragma unroll
        for (int j = 0; j < 4; j++) acc[i][j] = 0.f;

    for (int fc = 0; fc < NF; fc += 32) {
        #pragma unroll
        for (int r = 0; r < 8; r++) {
            int mm = lr + r*8;
            As[mm][lc] = g_V[(size_t)(m0 + mm)*NF + fc + lc];
            Ws[mm][lc] = W[(size_t)(o0 + mm)*NF + fc + lc];
        }
        __syncthreads();
        #pragma unroll
        for (int ff = 0; ff < 32; ff++) {
            float a[4], w[4];
            #pragma unroll
            for (int i = 0; i < 4; i++) a[i] = As[tx*4 + i][ff];
            #pragma unroll
            for (int j = 0; j < 4; j++) w[j] = Ws[ty*4 + j][ff];
            #pragma unroll
            for (int i = 0; i < 4; i++)
                #pragma unroll
                for (int j = 0; j < 4; j++)
                    acc[i][j] = fmaf(a[i], w[j], acc[i][j]);
        }
        __syncthreads();
    }
    #pragma unroll
    for (int j = 0; j < 4; j++) {
        float bj = bias[o0 + ty*4 + j];
        #pragma unroll
        for (int i = 0; i < 4; i++) {
            float v = acc[i][j] + bj;
            v = (v >= 0.f) ? v : 0.01f * v;
            out[(size_t)(m0 + tx*4 + i)*NDOUT + o0 + ty*4 + j] = v;
        }
    }
}

// write kl scalar(s) after the out tensor
__global__ void finalize_kernel(float* __restrict__ out, int out_size)
{
    int i = OUT_ELEMS + blockIdx.x * blockDim.x + threadIdx.x;
    if (i < out_size) out[i] = __fmul_rn(100.0f, (float)g_kl);
}

// ------------------------------------------------------------------
extern "C" void kernel_launch(void* const* d_in, const int* in_sizes, int n_in,
                              void* d_out, int out_size)
{
    const float* Q      = (const float*)d_in[0];
    const float* keys   = (const float*)d_in[1];
    const float* conv_w = (const float*)d_in[2];
    const float* lin_w  = (const float*)d_in[3];
    const float* lin_b  = (const float*)d_in[4];
    const int*   mask   = (const int*)d_in[5];
    float* out = (float*)d_out;

    // smem: QsU 34816 + Sacc 65664 + kbuf 98304 + redw 2048 + misc 512
    const int smem = (8704 + 32*SP + 24576 + 512 + 4*32) * (int)sizeof(float);
    cudaFuncSetAttribute(scores_kernel, cudaFuncAttributeMaxDynamicSharedMemorySize, smem);

    init_kernel<<<1, 32>>>();                      // my #0
    k2_kernel<<<(NH*NK)/8, 256>>>(keys);           // my #1
    prep_keys<<<512, 256>>>(keys);                 // my #2
    scores_kernel<<<dim3(NN/32, NB), 512, smem>>>(Q, conv_w, mask); // my #3 = ncu slot 5
    cn_kernel<<<(NB*NK)/256, 256>>>();
    kl_kernel<<<(NB*NN)/8, 256>>>();
    v_kernel<<<dim3(NK/64, NF/64, NB), 256>>>(Q);
    out_kernel<<<dim3((NB*NK)/64, NDOUT/64), 256>>>(lin_w, lin_b, out);

    int extra = out_size - OUT_ELEMS;
    if (extra > 0)
        finalize_kernel<<<(extra + 255)/256, 256>>>(out, out_size);
}

// round 17
// speedup vs baseline: 3.1039x; 1.0593x over previous
#include <cuda_runtime.h>
#include <cuda_bf16.h>
#include <cstdint>

#define NB   16
#define NN   1024
#define NF   256
#define NH   8
#define NK   512
#define NDOUT 256
#define EPSF 1e-8f
#define OUT_ELEMS (NB*NK*NDOUT)
#define SP   513   // padded row stride
#define QW   132   // Qhi row stride in u32 (264 bf16 = conflict-free)

typedef unsigned long long u64;

// packed fp32x2 FMA (kept for legacy paths)
#define FMA2(acc, a, b) \
    asm("fma.rn.f32x2 %0, %1, %2, %0;" : "+l"(acc) : "l"(a), "l"(b))

// m16n8k16 bf16 MMA, fp32 accumulate in place
__device__ __forceinline__ void mma_bf16(
    float& d0, float& d1, float& d2, float& d3,
    unsigned a0, unsigned a1, unsigned a2, unsigned a3,
    unsigned b0, unsigned b1)
{
    asm volatile(
        "mma.sync.aligned.m16n8k16.row.col.f32.bf16.bf16.f32 "
        "{%0,%1,%2,%3}, {%4,%5,%6,%7}, {%8,%9}, {%0,%1,%2,%3};"
        : "+f"(d0), "+f"(d1), "+f"(d2), "+f"(d3)
        : "r"(a0), "r"(a1), "r"(a2), "r"(a3), "r"(b0), "r"(b1));
}

// ldmatrix x4 (non-transposed)
__device__ __forceinline__ void ldsm_x4(
    unsigned& r0, unsigned& r1, unsigned& r2, unsigned& r3, unsigned addr)
{
    asm volatile(
        "ldmatrix.sync.aligned.m8n8.x4.shared.b16 {%0,%1,%2,%3}, [%4];"
        : "=r"(r0), "=r"(r1), "=r"(r2), "=r"(r3) : "r"(addr));
}

// ---- scratch ----
__device__ float  g_C[(size_t)NB*NN*NK];    // 32 MB exact C (kl needs it)
__device__ float  g_V[(size_t)NB*NK*NF];    // 8 MB
__device__ float  g_cnp[(size_t)NB*32*NK];  // per-block colsum partials
__device__ float  g_cnf[NB*NK];
__device__ float  g_k2[NH*NK];
__device__ double g_kl;
// keys bf16 hi/lo, layout [h][fchunk 16][seg 2][k 512][f 8]
__device__ __nv_bfloat16 g_khi[(size_t)NH*NK*NF];
__device__ __nv_bfloat16 g_klo[(size_t)NH*NK*NF];
// C^T bf16 hi/lo [b][k][n] and Q^T bf16 hi/lo [b][f][n] (for tensor V)
__device__ __nv_bfloat16 g_cthi[(size_t)NB*NK*NN];
__device__ __nv_bfloat16 g_ctlo[(size_t)NB*NK*NN];
__device__ __nv_bfloat16 g_qthi[(size_t)NB*NF*NN];
__device__ __nv_bfloat16 g_qtlo[(size_t)NB*NF*NN];

// ------------------------------------------------------------------
// exp(x) for x in [-0.125, 0], float-float, ~1e-11 accurate.
__device__ __forceinline__ float exp_small(float x) {
    if (x < -0.125f) return (float)exp((double)x);   // rare fallback
    float x2h = __fmul_rn(x, x);
    float x2l = fmaf(x, x, -x2h);
    float U = fmaf(x, fmaf(x, fmaf(x, fmaf(x, 1.f/5040.f, 1.f/720.f),
                                   1.f/120.f), 1.f/24.f), 1.f/6.f);
    float tail = fmaf(__fmul_rn(x2h, x), U, 0.5f*x2l);
    float sh = __fadd_rn(1.f, x);
    float sl = __fadd_rn(__fsub_rn(1.f, sh), x);
    float b  = 0.5f*x2h;
    float th = __fadd_rn(sh, b);
    float tl = __fadd_rn(__fsub_rn(sh, th), b);
    return __fadd_rn(th, __fadd_rn(__fadd_rn(tl, sl), tail));
}

// log(y) for y ~ 1/512*(1 +- 0.06), float-float, ~1e-11 accurate.
__device__ __forceinline__ float log_near(float y) {
    const double LN512 = 6.2383246250395078;
    const float LH = (float)LN512;
    const float LL = (float)(LN512 - (double)LH);
    float u = __fmul_rn(y, 512.f);
    float w = __fsub_rn(u, 1.f);
    if (fabsf(w) > 0.0625f) return (float)log((double)y);  // rare fallback
    float w2h = __fmul_rn(w, w);
    float w2l = fmaf(w, w, -w2h);
    float V = fmaf(w, fmaf(w, fmaf(w, fmaf(w, fmaf(w, -1.f/8.f, 1.f/7.f),
                                   -1.f/6.f), 1.f/5.f), -1.f/4.f), 1.f/3.f);
    float tail = fmaf(__fmul_rn(w2h, w), V, -0.5f*w2l);
    float b  = -0.5f*w2h;
    float sh = __fadd_rn(w, b);
    float sl = __fadd_rn(__fsub_rn(w, sh), b);
    float th = __fadd_rn(sh, -LH);
    float tl = __fadd_rn(__fsub_rn(-LH, th), sh);
    return __fadd_rn(th, __fsub_rn(__fadd_rn(__fadd_rn(tl, sl), tail), LL));
}

// ------------------------------------------------------------------
__global__ void init_kernel() {
    if (blockIdx.x == 0 && threadIdx.x == 0) g_kl = 0.0;
}

// ||keys[h][k]||^2 : warp per row
__global__ void k2_kernel(const float* __restrict__ keys) {
    int warp = threadIdx.x >> 5, lane = threadIdx.x & 31;
    int row = blockIdx.x * 8 + warp;           // < NH*NK = 4096
    const float4* kr = (const float4*)(keys + (size_t)row * NF);
    float s = 0.f;
    #pragma unroll
    for (int j = lane; j < 64; j += 32) {
        float4 v = kr[j];
        s += v.x*v.x + v.y*v.y + v.z*v.z + v.w*v.w;
    }
    #pragma unroll
    for (int o = 16; o; o >>= 1) s += __shfl_xor_sync(0xffffffffu, s, o);
    if (!lane) g_k2[row] = s;
}

// keys -> bf16 hi/lo split, staged layout [h][fc][seg][k][8f]
__global__ void __launch_bounds__(256) prep_keys(const float* __restrict__ keys)
{
    int gid = blockIdx.x * 256 + threadIdx.x;   // < 131072
    int k   = gid & 511;
    int seg = (gid >> 9) & 1;
    int fc  = (gid >> 10) & 15;
    int h   = gid >> 14;
    const float* src = keys + ((size_t)(h*NK + k))*NF + fc*16 + seg*8;
    __nv_bfloat16* dhi = g_khi + (size_t)gid*8;
    __nv_bfloat16* dlo = g_klo + (size_t)gid*8;
    #pragma unroll
    for (int j = 0; j < 8; j++) {
        float x = src[j];
        __nv_bfloat16 hi = __float2bfloat16_rn(x);
        __nv_bfloat16 lo =
            __float2bfloat16_rn(__fsub_rn(x, __bfloat162float(hi)));
        dhi[j] = hi; dlo[j] = lo;
    }
}

// Q -> Q^T bf16 hi/lo [b][f][n] via smem transpose
__global__ void __launch_bounds__(256) prep_q(const float* __restrict__ Q)
{
    __shared__ float t[64][65];
    const int b = blockIdx.z, n0 = blockIdx.x*64, f0 = blockIdx.y*64;
    const int tid = threadIdx.x;
    const float4* src = (const float4*)(Q + ((size_t)(b*NN + n0))*NF + f0);
    #pragma unroll
    for (int i = tid; i < 64*16; i += 256) {
        int rr = i >> 4, cc = i & 15;
        float4 v = src[(size_t)rr*64 + cc];
        t[rr][cc*4+0]=v.x; t[rr][cc*4+1]=v.y;
        t[rr][cc*4+2]=v.z; t[rr][cc*4+3]=v.w;
    }
    __syncthreads();
    #pragma unroll
    for (int u = tid; u < 512; u += 256) {
        int fl = u >> 3, no = u & 7;
        unsigned ph[4], pl[4];
        #pragma unroll
        for (int j = 0; j < 8; j += 2) {
            float x0 = t[no*8 + j][fl], x1 = t[no*8 + j + 1][fl];
            __nv_bfloat16 h0 = __float2bfloat16_rn(x0);
            __nv_bfloat16 h1 = __float2bfloat16_rn(x1);
            __nv_bfloat16 l0 = __float2bfloat16_rn(__fsub_rn(x0, __bfloat162float(h0)));
            __nv_bfloat16 l1 = __float2bfloat16_rn(__fsub_rn(x1, __bfloat162float(h1)));
            ph[j>>1] = ((unsigned)__bfloat16_as_ushort(h1) << 16)
                     | __bfloat16_as_ushort(h0);
            pl[j>>1] = ((unsigned)__bfloat16_as_ushort(l1) << 16)
                     | __bfloat16_as_ushort(l0);
        }
        size_t base = ((size_t)(b*NF + f0 + fl))*NN + n0 + no*8;
        *(uint4*)(g_qthi + base) = make_uint4(ph[0], ph[1], ph[2], ph[3]);
        *(uint4*)(g_qtlo + base) = make_uint4(pl[0], pl[1], pl[2], pl[3]);
    }
}

// ------------------------------------------------------------------
// cp.async one chunk of THIS WARP's private key slice (hi+lo) into stage
__device__ __forceinline__ void issue_slice(
    float* kbuf, int h, int chunk, int w, int lane)
{
    const int st = chunk % 3;
    char* dstbase = (char*)kbuf + (size_t)((st*16 + w)*2)*1024;
    #pragma unroll
    for (int i = 0; i < 4; i++) {
        int t = i >> 1, seg = i & 1;
        const __nv_bfloat16* src = (t ? g_klo : g_khi)
            + ((size_t)(((h*16 + chunk)*2 + seg)*512) + 32*w + lane)*8;
        char* dst = dstbase + t*1024 + seg*512 + lane*16;
        unsigned d = (unsigned)__cvta_generic_to_shared(dst);
        asm volatile("cp.async.ca.shared.global [%0], [%1], 16;"
                     :: "r"(d), "l"(src));
    }
    asm volatile("cp.async.commit_group;");
}

// ------------------------------------------------------------------
// Fused scores kernel: tensor-core qk (bf16 2-product: hiQ*hiK + hiQ*loK;
// dropped loQ*hiK term is softmax-annihilated), ldmatrix frags, register
// logits, frozen epilogue; emits exact fp32 C, Ct bf16 hi/lo, cn partials.
__global__ void __launch_bounds__(512, 1) scores_kernel(
    const float* __restrict__ Q, const float* __restrict__ conv_w,
    const int* __restrict__ mask)
{
    extern __shared__ float sm[];
    float* QsU  = sm;                      // fp32 Q then Qhi (bf16)
    float* Sacc = sm + 8704;               // 32*SP (after head loop only)
    float* kbuf = Sacc + 32*SP;            // 96KB, 3 stages
    float* redw = kbuf + 24576;            // 16*32 rowsum partials
    float* rowv = redw + 512;              // 32
    float* q2s  = rowv + 32;               // 32
    float* mxs  = q2s + 32;                // 32
    float* msk  = mxs + 32;                // 32

    const int tid  = threadIdx.x;
    const int lane = tid & 31, warp = tid >> 5;
    const int g = lane >> 2, c = lane & 3;
    const int b  = blockIdx.y;
    const int n0 = blockIdx.x * 32;
    const int k  = tid;

    // --- load Q tile (fp32) + mask ---
    float* Qs = QsU;
    const float4* Qg = (const float4*)(Q + ((size_t)b*NN + n0)*NF);
    float4* Qs4 = (float4*)Qs;
    #pragma unroll
    for (int i = tid; i < 32*64; i += 512) Qs4[i] = Qg[i];
    if (tid < 32) msk[tid] = (float)mask[b*NN + n0 + tid];
    __syncthreads();

    // --- q2 per row ---
    #pragma unroll
    for (int r = 0; r < 2; r++) {
        int n = warp*2 + r;
        float s = 0.f;
        #pragma unroll
        for (int j = 0; j < 8; j++) {
            float v = Qs[n*256 + lane + 32*j];
            s = __fadd_rn(s, __fmul_rn(v, v));
        }
        #pragma unroll
        for (int o = 16; o; o >>= 1)
            s = __fadd_rn(s, __shfl_xor_sync(0xffffffffu, s, o));
        if (!lane) q2s[n] = s;
    }

    // --- convert Q fp32 -> bf16 hi in place (lo no longer needed) ---
    float vals[16];
    #pragma unroll
    for (int j = 0; j < 16; j++) vals[j] = Qs[tid + 512*j];
    __syncthreads();
    {
        __nv_bfloat16* Qhb = (__nv_bfloat16*)QsU;
        #pragma unroll
        for (int j = 0; j < 16; j++) {
            int idx = tid + 512*j;
            int n = idx >> 8, f = idx & 255;
            Qhb[n*264 + f] = __float2bfloat16_rn(vals[j]);
        }
    }
    __syncthreads();

    // --- ldmatrix base addresses ---
    const unsigned smQ = (unsigned)__cvta_generic_to_shared(QsU);
    const unsigned smK = (unsigned)__cvta_generic_to_shared(kbuf);
    const unsigned aoff = (unsigned)((lane & 15)*528 + (lane >> 4)*16);
    const unsigned aHi0 = smQ + aoff;
    const unsigned aHi1 = aHi0 + 16*528;
    const unsigned boff = (unsigned)((((lane >> 3) & 1)*512)
                        + (((lane & 7) + 8*(lane >> 4))*16));
    const unsigned bwarp = smK + (unsigned)(warp*2048) + boff;

    issue_slice(kbuf, 0, 0, warp, lane);
    issue_slice(kbuf, 0, 1, warp, lane);

    float lg[2][4][4];
    #pragma unroll
    for (int mt = 0; mt < 2; mt++)
        #pragma unroll
        for (int kt = 0; kt < 4; kt++)
            #pragma unroll
            for (int e = 0; e < 4; e++) lg[mt][kt][e] = 0.f;

    for (int h = 0; h < NH; h++) {
        float d[2][4][4];
        #pragma unroll
        for (int mt = 0; mt < 2; mt++)
            #pragma unroll
            for (int kt = 0; kt < 4; kt++)
                #pragma unroll
                for (int e = 0; e < 4; e++) d[mt][kt][e] = 0.f;

        #pragma unroll 1
        for (int chunk = 0; chunk < 16; chunk++) {
            if (chunk + 1 < 16)
                asm volatile("cp.async.wait_group 1;");
            else
                asm volatile("cp.async.wait_group 0;");
            __syncwarp();
            if (chunk + 2 < 16)
                issue_slice(kbuf, h, chunk + 2, warp, lane);

            unsigned ah[2][4];
            {
                unsigned cb = (unsigned)(chunk*32);
                ldsm_x4(ah[0][0], ah[0][1], ah[0][2], ah[0][3], aHi0 + cb);
                ldsm_x4(ah[1][0], ah[1][1], ah[1][2], ah[1][3], aHi1 + cb);
            }
            unsigned bh[4][2], bl[4][2];
            {
                unsigned bb = bwarp + (unsigned)((chunk % 3)*32768);
                ldsm_x4(bh[0][0], bh[0][1], bh[1][0], bh[1][1], bb);
                ldsm_x4(bh[2][0], bh[2][1], bh[3][0], bh[3][1], bb + 256);
                ldsm_x4(bl[0][0], bl[0][1], bl[1][0], bl[1][1], bb + 1024);
                ldsm_x4(bl[2][0], bl[2][1], bl[3][0], bl[3][1], bb + 1280);
            }

            #pragma unroll
            for (int kt = 0; kt < 4; kt++) {
                #pragma unroll
                for (int mt = 0; mt < 2; mt++) {
                    mma_bf16(d[mt][kt][0], d[mt][kt][1],
                             d[mt][kt][2], d[mt][kt][3],
                             ah[mt][0], ah[mt][1], ah[mt][2], ah[mt][3],
                             bh[kt][0], bh[kt][1]);
                    mma_bf16(d[mt][kt][0], d[mt][kt][1],
                             d[mt][kt][2], d[mt][kt][3],
                             ah[mt][0], ah[mt][1], ah[mt][2], ah[mt][3],
                             bl[kt][0], bl[kt][1]);
                }
            }
        }

        if (h + 1 < NH) {
            issue_slice(kbuf, h + 1, 0, warp, lane);
            issue_slice(kbuf, h + 1, 1, warp, lane);
        }

        // d2 = (q2+k2) - 2*qk; cv = 1/(1 + sqrt(max(d2,0))^2)
        float k2r[4][2];
        {
            const float* k2p = g_k2 + h*NK + 32*warp + 2*c;
            #pragma unroll
            for (int kt = 0; kt < 4; kt++) {
                k2r[kt][0] = __ldg(k2p + kt*8);
                k2r[kt][1] = __ldg(k2p + kt*8 + 1);
            }
        }
        #pragma unroll
        for (int mt = 0; mt < 2; mt++)
            #pragma unroll
            for (int kt = 0; kt < 4; kt++)
                #pragma unroll
                for (int e = 0; e < 4; e++) {
                    int n  = mt*16 + g + ((e & 2) ? 8 : 0);
                    float qk = d[mt][kt][e];
                    float d2 = __fsub_rn(__fadd_rn(q2s[n], k2r[kt][e & 1]),
                                         __fmul_rn(2.0f, qk));
                    float t  = sqrtf(fmaxf(d2, 0.0f));
                    d[mt][kt][e] = __fdiv_rn(1.0f,
                                     __fadd_rn(1.0f, __fmul_rn(t, t)));
                }

        // warp-partial rowsum
        #pragma unroll
        for (int mt = 0; mt < 2; mt++)
            #pragma unroll
            for (int e2 = 0; e2 < 2; e2++) {
                float s = 0.f;
                #pragma unroll
                for (int kt = 0; kt < 4; kt++) {
                    s = __fadd_rn(s, d[mt][kt][2*e2]);
                    s = __fadd_rn(s, d[mt][kt][2*e2 + 1]);
                }
                s = __fadd_rn(s, __shfl_xor_sync(0xffffffffu, s, 1));
                s = __fadd_rn(s, __shfl_xor_sync(0xffffffffu, s, 2));
                if (c == 0)
                    redw[warp*32 + mt*16 + 8*e2 + g] = s;
            }
        __syncthreads();
        if (tid < 32) {
            float s = 0.f;
            #pragma unroll
            for (int w = 0; w < 16; w++)
                s = __fadd_rn(s, redw[w*32 + tid]);
            rowv[tid] = s;
        }
        __syncthreads();

        const float cw = conv_w[h];
        #pragma unroll
        for (int mt = 0; mt < 2; mt++)
            #pragma unroll
            for (int kt = 0; kt < 4; kt++)
                #pragma unroll
                for (int e = 0; e < 4; e++) {
                    int n = mt*16 + g + ((e & 2) ? 8 : 0);
                    float cdiv = __fdiv_rn(d[mt][kt][e], rowv[n]);
                    float term = __fmul_rn(cw, __fmul_rn(cdiv, msk[n]));
                    lg[mt][kt][e] = __fadd_rn(lg[mt][kt][e], term);
                }
    }

    // write logits to Sacc once
    #pragma unroll
    for (int mt = 0; mt < 2; mt++)
        #pragma unroll
        for (int kt = 0; kt < 4; kt++)
            #pragma unroll
            for (int e = 0; e < 4; e++) {
                int n  = mt*16 + g + ((e & 2) ? 8 : 0);
                int kx = 32*warp + kt*8 + 2*c + (e & 1);
                Sacc[n*SP + kx] = lg[mt][kt][e];
            }
    __syncthreads();

    // softmax: row max
    #pragma unroll
    for (int r = 0; r < 2; r++) {
        int n = warp*2 + r;
        float mx = -3.402823466e38f;
        #pragma unroll
        for (int j = 0; j < 16; j++)
            mx = fmaxf(mx, Sacc[n*SP + lane + 32*j]);
        #pragma unroll
        for (int o = 16; o; o >>= 1)
            mx = fmaxf(mx, __shfl_xor_sync(0xffffffffu, mx, o));
        if (!lane) mxs[n] = mx;
    }
    __syncthreads();
    #pragma unroll
    for (int n = 0; n < 32; n++) {
        float x = __fsub_rn(Sacc[n*SP + k], mxs[n]);
        Sacc[n*SP + k] = exp_small(x);
    }
    __syncthreads();
    // denominator: strict sequential ascending fp32 (FROZEN order)
    if (tid < 32) {
        const float* row = &Sacc[tid*SP];
        float s = 0.f;
        #pragma unroll 8
        for (int j = 0; j < NK; j++)
            s = __fadd_rn(s, row[j]);
        rowv[tid] = s;
    }
    __syncthreads();

    // C = (e/s)*msk; write fp32 C, bf16 hi/lo C^T, colsum partial
    float* Cout = g_C + ((size_t)b*NN + n0)*NK + k;
    float cs = 0.f;
    unsigned ph[16], pl[16];
    #pragma unroll
    for (int n = 0; n < 32; n++) {
        float cvv = __fmul_rn(__fdiv_rn(Sacc[n*SP + k], rowv[n]), msk[n]);
        Cout[(size_t)n*NK] = cvv;
        cs = __fadd_rn(cs, cvv);
        __nv_bfloat16 bh16 = __float2bfloat16_rn(cvv);
        __nv_bfloat16 bl16 = __float2bfloat16_rn(
            __fsub_rn(cvv, __bfloat162float(bh16)));
        unsigned uh = __bfloat16_as_ushort(bh16);
        unsigned ul = __bfloat16_as_ushort(bl16);
        if (n & 1) { ph[n>>1] |= uh << 16; pl[n>>1] |= ul << 16; }
        else       { ph[n>>1] = uh;        pl[n>>1] = ul; }
    }
    g_cnp[((size_t)b*32 + blockIdx.x)*NK + k] = cs;
    size_t cb = ((size_t)(b*NK + k))*NN + n0;
    uint4* dh = (uint4*)(g_cthi + cb);
    uint4* dl = (uint4*)(g_ctlo + cb);
    #pragma unroll
    for (int i = 0; i < 4; i++) {
        dh[i] = make_uint4(ph[4*i], ph[4*i+1], ph[4*i+2], ph[4*i+3]);
        dl[i] = make_uint4(pl[4*i], pl[4*i+1], pl[4*i+2], pl[4*i+3]);
    }
}

// ------------------------------------------------------------------
// cn[b][k] = sum of 32 block partials, ascending block order
__global__ void __launch_bounds__(256) cn_kernel()
{
    int id = blockIdx.x * blockDim.x + threadIdx.x;
    int b = id >> 9, kk = id & 511;
    const float* p = g_cnp + ((size_t)b*32)*NK + kk;
    float s = 0.f;
    #pragma unroll
    for (int j = 0; j < 32; j++)
        s = __fadd_rn(s, p[(size_t)j*NK]);
    g_cnf[id] = s;
}

// ------------------------------------------------------------------
// KL: warp per (b,n) row. Sequential fp32 pn (FROZEN); float-float logs.
__global__ void __launch_bounds__(256) kl_kernel()
{
    __shared__ float cbuf[8][SP];
    __shared__ float pbuf[8][SP];
    const int warp = threadIdx.x >> 5, lane = threadIdx.x & 31;
    const int row = blockIdx.x * 8 + warp;
    const int b = row >> 10;
    const float* crow = g_C + (size_t)row * NK;
    const float* cnb = g_cnf + b*NK;

    #pragma unroll
    for (int j = 0; j < 16; j++) {
        int kk = lane + 32*j;
        float c = crow[kk];
        float cnf = __fadd_rn(cnb[kk], EPSF);
        float p = __fdiv_rn(__fmul_rn(c, c), cnf);
        cbuf[warp][kk] = c;
        pbuf[warp][kk] = p;
    }
    __syncwarp();
    if (!lane) {
        float pn = 0.f;
        const float* prow = pbuf[warp];
        #pragma unroll 8
        for (int j = 0; j < NK; j++)
            pn = __fadd_rn(pn, prow[j]);
        pbuf[warp][512] = __fadd_rn(pn, EPSF);
    }
    __syncwarp();
    const float pnf = pbuf[warp][512];

    double t = 0.0;
    #pragma unroll
    for (int j = 0; j < 16; j++) {
        int kk = lane + 32*j;
        float pv = pbuf[warp][kk];
        if (pv != 0.f) {
            float P  = __fdiv_rn(pv, pnf);
            float la = log_near(__fadd_rn(P, EPSF));
            float lb = log_near(__fadd_rn(cbuf[warp][kk], EPSF));
            t += (double)__fmul_rn(P, __fsub_rn(la, lb));
        }
    }
    #pragma unroll
    for (int o = 16; o; o >>= 1) t += __shfl_xor_sync(0xffffffffu, t, o);
    if (!lane) atomicAdd(&g_kl, t);
}

// ------------------------------------------------------------------
// Tensor-core V: V[b][k][f] = sum_n Ct[k][n]*Qt[f][n], bf16 3-product.
// Block 256 thr: tile 64k x 64f; warp: kt = w&3 (16 k), fh = w>>2 (32 f).
__global__ void __launch_bounds__(256) v_kernel()
{
    __shared__ __align__(16) char vb[3*4*2*64*16];   // 24576 B
    const int tid = threadIdx.x, lane = tid & 31, warp = tid >> 5;
    const int g = lane >> 2, c = lane & 3;
    const int b = blockIdx.z;
    const int k0 = blockIdx.x*64, f0 = blockIdx.y*64;
    const int kt = warp & 3, fh = warp >> 2;

    // cp.async role: mat = tid>>6 (0 Ahi,1 Alo,2 Bhi,3 Blo), row r = tid&63
    const int mat = tid >> 6, r = tid & 63;
    const __nv_bfloat16* srcb;
    if      (mat == 0) srcb = g_cthi + ((size_t)(b*NK + k0 + r))*NN;
    else if (mat == 1) srcb = g_ctlo + ((size_t)(b*NK + k0 + r))*NN;
    else if (mat == 2) srcb = g_qthi + ((size_t)(b*NF + f0 + r))*NN;
    else               srcb = g_qtlo + ((size_t)(b*NF + f0 + r))*NN;
    const unsigned dbase = (unsigned)__cvta_generic_to_shared(
        vb + (size_t)(mat*2*64 + r)*16);

    // ldmatrix bases
    const unsigned smv = (unsigned)__cvta_generic_to_shared(vb);
    const unsigned arow = (unsigned)(kt*16 + (lane & 7) + 8*((lane >> 3) & 1));
    const unsigned aseg = (unsigned)(lane >> 4);
    const unsigned aHi = smv + ((0*2 + aseg)*64 + arow)*16;
    const unsigned aLo = smv + ((1*2 + aseg)*64 + arow)*16;
    const unsigned brow = (unsigned)(fh*32 + (lane & 7) + 8*(lane >> 4));
    const unsigned bseg = (unsigned)((lane >> 3) & 1);
    const unsigned bHi = smv + ((2*2 + bseg)*64 + brow)*16;
    const unsigned bLo = smv + ((3*2 + bseg)*64 + brow)*16;

    float acc[4][4];
    #pragma unroll
    for (int ft = 0; ft < 4; ft++)
        #pragma unroll
        for (int e = 0; e < 4; e++) acc[ft][e] = 0.f;

    // issue chunk: 2 cp.async (seg 0/1) + commit
    #define V_ISSUE(ch) do { \
        int st_ = (ch) % 3; \
        const __nv_bfloat16* s_ = srcb + (ch)*16; \
        unsigned d_ = dbase + (unsigned)(st_*8192); \
        asm volatile("cp.async.ca.shared.global [%0], [%1], 16;" \
                     :: "r"(d_), "l"(s_)); \
        asm volatile("cp.async.ca.shared.global [%0], [%1], 16;" \
                     :: "r"(d_ + 1024), "l"(s_ + 8)); \
        asm volatile("cp.async.commit_group;"); } while (0)

    V_ISSUE(0);
    V_ISSUE(1);

    #pragma unroll 1
    for (int chunk = 0; chunk < 64; chunk++) {
        if (chunk + 1 < 64)
            asm volatile("cp.async.wait_group 1;");
        else
            asm volatile("cp.async.wait_group 0;");
        __syncthreads();
        if (chunk + 2 < 64) V_ISSUE(chunk + 2);

        unsigned off = (unsigned)((chunk % 3)*8192);
        unsigned ah[4], al[4], bh[4][2], bl[4][2];
        ldsm_x4(ah[0], ah[1], ah[2], ah[3], aHi + off);
        ldsm_x4(al[0], al[1], al[2], al[3], aLo + off);
        ldsm_x4(bh[0][0], bh[0][1], bh[1][0], bh[1][1], bHi + off);
        ldsm_x4(bh[2][0], bh[2][1], bh[3][0], bh[3][1], bHi + off + 256);
        ldsm_x4(bl[0][0], bl[0][1], bl[1][0], bl[1][1], bLo + off);
        ldsm_x4(bl[2][0], bl[2][1], bl[3][0], bl[3][1], bLo + off + 256);

        #pragma unroll
        for (int ft = 0; ft < 4; ft++) {
            mma_bf16(acc[ft][0], acc[ft][1], acc[ft][2], acc[ft][3],
                     ah[0], ah[1], ah[2], ah[3], bh[ft][0], bh[ft][1]);
            mma_bf16(acc[ft][0], acc[ft][1], acc[ft][2], acc[ft][3],
                     ah[0], ah[1], ah[2], ah[3], bl[ft][0], bl[ft][1]);
            mma_bf16(acc[ft][0], acc[ft][1], acc[ft][2], acc[ft][3],
                     al[0], al[1], al[2], al[3], bh[ft][0], bh[ft][1]);
        }
        __syncthreads();
    }
    #undef V_ISSUE

    const int krow = k0 + kt*16 + g;
    const int fcb  = f0 + fh*32 + 2*c;
    #pragma unroll
    for (int ft = 0; ft < 4; ft++) {
        *(float2*)(g_V + ((size_t)(b*NK + krow))*NF + fcb + ft*8) =
            make_float2(acc[ft][0], acc[ft][1]);
        *(float2*)(g_V + ((size_t)(b*NK + krow + 8))*NF + fcb + ft*8) =
            make_float2(acc[ft][2], acc[ft][3]);
    }
}

// ------------------------------------------------------------------
// out[m][o] = lrelu( sum_f V[m][f]*W[o][f] + bias[o] )
__global__ void __launch_bounds__(256) out_kernel(
    const float* __restrict__ W, const float* __restrict__ bias,
    float* __restrict__ out)
{
    const int m0 = blockIdx.x * 64, o0 = blockIdx.y * 64;
    __shared__ float As[64][33];
    __shared__ float Ws[64][33];
    const int tid = threadIdx.x;
    const int tx = tid & 15, ty = tid >> 4;
    const int lr = tid >> 5, lc = tid & 31;

    float acc[4][4];
    #pragma unroll
    for (int i = 0; i < 4; i++)
        #pragma unroll
        for (int j = 0; j < 4; j++) acc[i][j] = 0.f;

    for (int fc = 0; fc < NF; fc += 32) {
        #pragma unroll
        for (int r = 0; r < 8; r++) {
            int mm = lr + r*8;
            As[mm][lc] = g_V[(size_t)(m0 + mm)*NF + fc + lc];
            Ws[mm][lc] = W[(size_t)(o0 + mm)*NF + fc + lc];
        }
        __syncthreads();
        #pragma unroll
        for (int ff = 0; ff < 32; ff++) {
            float a[4], w[4];
            #pragma unroll
            for (int i = 0; i < 4; i++) a[i] = As[tx*4 + i][ff];
            #pragma unroll
            for (int j = 0; j < 4; j++) w[j] = Ws[ty*4 + j][ff];
            #pragma unroll
            for (int i = 0; i < 4; i++)
                #pragma unroll
                for (int j = 0; j < 4; j++)
                    acc[i][j] = fmaf(a[i], w[j], acc[i][j]);
        }
        __syncthreads();
    }
    #pragma unroll
    for (int j = 0; j < 4; j++) {
        float bj = bias[o0 + ty*4 + j];
        #pragma unroll
        for (int i = 0; i < 4; i++) {
            float v = acc[i][j] + bj;
            v = (v >= 0.f) ? v : 0.01f * v;
            out[(size_t)(m0 + tx*4 + i)*NDOUT + o0 + ty*4 + j] = v;
        }
    }
}

// write kl scalar(s) after the out tensor
__global__ void finalize_kernel(float* __restrict__ out, int out_size)
{
    int i = OUT_ELEMS + blockIdx.x * blockDim.x + threadIdx.x;
    if (i < out_size) out[i] = __fmul_rn(100.0f, (float)g_kl);
}

// ------------------------------------------------------------------
extern "C" void kernel_launch(void* const* d_in, const int* in_sizes, int n_in,
                              void* d_out, int out_size)
{
    const float* Q      = (const float*)d_in[0];
    const float* keys   = (const float*)d_in[1];
    const float* conv_w = (const float*)d_in[2];
    const float* lin_w  = (const float*)d_in[3];
    const float* lin_b  = (const float*)d_in[4];
    const int*   mask   = (const int*)d_in[5];
    float* out = (float*)d_out;

    const int smem = (8704 + 32*SP + 24576 + 512 + 4*32) * (int)sizeof(float);
    cudaFuncSetAttribute(scores_kernel, cudaFuncAttributeMaxDynamicSharedMemorySize, smem);

    init_kernel<<<1, 32>>>();                      // my #0
    k2_kernel<<<(NH*NK)/8, 256>>>(keys);           // my #1
    prep_keys<<<512, 256>>>(keys);                 // my #2
    scores_kernel<<<dim3(NN/32, NB), 512, smem>>>(Q, conv_w, mask); // my #3 = ncu slot 5
    prep_q<<<dim3(NN/64, NF/64, NB), 256>>>(Q);
    cn_kernel<<<(NB*NK)/256, 256>>>();
    kl_kernel<<<(NB*NN)/8, 256>>>();
    v_kernel<<<dim3(NK/64, NF/64, NB), 256>>>();
    out_kernel<<<dim3((NB*NK)/64, NDOUT/64), 256>>>(lin_w, lin_b, out);

    int extra = out_size - OUT_ELEMS;
    if (extra > 0)
        finalize_kernel<<<(extra + 255)/256, 256>>>(out, out_size);
}